// round 8
// baseline (speedup 1.0000x reference)
#include <cuda_runtime.h>
#include <math_constants.h>
#include <cstdint>
#include <cstddef>

// ---------------- problem constants ----------------
#define NB    128
#define NV    1024
#define NFEAT 10
#define NBK   11
#define NF    32
#define NP    20
#define NA    4
#define NC    24
#define DFE   352   // NBK*NF
#define HALF_V 512

// h ring: slot 0 = h0, slot l+1 = output of block l. layout g_h[b][s*32+k][v]
__device__ float g_h[(size_t)NB * 384 * NV];     // 201 MB
__device__ float g_w[(size_t)NB * NA * NV];      // per-block edge weights
__device__ float g_pmax[2][NB * 96 * 2];         // double-buffered partial max
__device__ float g_psum[2][NB * 96 * 2];         // double-buffered partial sum
__device__ float g_cbias[NB * NF];               // per-event folded input bias

// ---------------- f32x2 packed-math helpers ----------------
typedef unsigned long long ull;
__device__ __forceinline__ ull pk2(float a, float b) {
    ull r; asm("mov.b64 %0, {%1, %2};" : "=l"(r) : "f"(a), "f"(b)); return r;
}
__device__ __forceinline__ ull dup2(float a) { return pk2(a, a); }
__device__ __forceinline__ void fma2(ull& d, ull a, ull b) {
    asm("fma.rn.f32x2 %0, %1, %2, %0;" : "+l"(d) : "l"(a), "l"(b));
}
__device__ __forceinline__ ull mul2(ull a, ull b) {
    ull r; asm("mul.rn.f32x2 %0, %1, %2;" : "=l"(r) : "l"(a), "l"(b)); return r;
}
__device__ __forceinline__ ull add2(ull a, ull b) {
    ull r; asm("add.rn.f32x2 %0, %1, %2;" : "=l"(r) : "l"(a), "l"(b)); return r;
}
__device__ __forceinline__ float2 up2(ull v) {
    float2 r; asm("mov.b64 {%0, %1}, %2;" : "=f"(r.x), "=f"(r.y) : "l"(v)); return r;
}
union F4U { float4 f; ull u[2]; };

__device__ __forceinline__ float tanh_fast(float x) {
    float r; asm("tanh.approx.f32 %0, %1;" : "=f"(r) : "f"(x)); return r;
}

// ---------------- 2-vertex shared helpers ----------------
template<bool BN>
__device__ __forceinline__ void stream_epi_fw2(
    ull acc0[16], ull acc1[16],
    const float* __restrict__ sscale, const float* __restrict__ sshift,
    const float (*__restrict__ sWfw)[NC], const float* __restrict__ sbfw,
    float* __restrict__ ob, ull facc0[12], ull facc1[12])
{
    #pragma unroll
    for (int j = 0; j < 12; j++) {
        float2 bb = *(const float2*)&sbfw[2 * j];
        ull p = pk2(bb.x, bb.y);
        facc0[j] = p; facc1[j] = p;
    }
    #pragma unroll
    for (int j2 = 0; j2 < 16; j2++) {
        float2 z0 = up2(acc0[j2]), z1 = up2(acc1[j2]);
        float a00 = tanh_fast(z0.x), a01 = tanh_fast(z0.y);
        float a10 = tanh_fast(z1.x), a11 = tanh_fast(z1.y);
        if (BN) {
            float sc0 = sscale[2 * j2], sh0 = sshift[2 * j2];
            float sc1 = sscale[2 * j2 + 1], sh1 = sshift[2 * j2 + 1];
            a00 = a00 * sc0 + sh0; a10 = a10 * sc0 + sh0;
            a01 = a01 * sc1 + sh1; a11 = a11 * sc1 + sh1;
        }
        *(float2*)(ob + (size_t)(2 * j2) * NV)     = make_float2(a00, a10);
        *(float2*)(ob + (size_t)(2 * j2 + 1) * NV) = make_float2(a01, a11);
        ull d00 = dup2(a00), d01 = dup2(a01), d10 = dup2(a10), d11 = dup2(a11);
        #pragma unroll
        for (int g6 = 0; g6 < 6; g6++) {
            F4U w0; w0.f = *(const float4*)&sWfw[2 * j2][g6 * 4];
            F4U w1; w1.f = *(const float4*)&sWfw[2 * j2 + 1][g6 * 4];
            fma2(facc0[2 * g6],     d00, w0.u[0]); fma2(facc0[2 * g6 + 1], d00, w0.u[1]);
            fma2(facc0[2 * g6],     d01, w1.u[0]); fma2(facc0[2 * g6 + 1], d01, w1.u[1]);
            fma2(facc1[2 * g6],     d10, w0.u[0]); fma2(facc1[2 * g6 + 1], d10, w0.u[1]);
            fma2(facc1[2 * g6],     d11, w1.u[0]); fma2(facc1[2 * g6 + 1], d11, w1.u[1]);
        }
    }
}

__device__ __forceinline__ void fw_finish2(
    ull facc0[12], ull facc1[12], float (*__restrict__ sbuf)[HALF_V], int tid,
    float* __restrict__ gw)
{
    #pragma unroll
    for (int j = 0; j < 10; j++) {
        float2 f0 = up2(facc0[j]), f1 = up2(facc1[j]);
        *(float2*)&sbuf[2 * j][2 * tid]     = make_float2(f0.x, f1.x);
        *(float2*)&sbuf[2 * j + 1][2 * tid] = make_float2(f0.y, f1.y);
    }
    float2 p0 = up2(facc0[10]), q0 = up2(facc0[11]);
    float2 p1 = up2(facc1[10]), q1 = up2(facc1[11]);
    float w0a = __expf(-fabsf(p0.x)), w0b = __expf(-fabsf(p0.y));
    float w0c = __expf(-fabsf(q0.x)), w0d = __expf(-fabsf(q0.y));
    float w1a = __expf(-fabsf(p1.x)), w1b = __expf(-fabsf(p1.y));
    float w1c = __expf(-fabsf(q1.x)), w1d = __expf(-fabsf(q1.y));
    *(float2*)&sbuf[20][2 * tid] = make_float2(w0a, w1a);
    *(float2*)&sbuf[21][2 * tid] = make_float2(w0b, w1b);
    *(float2*)&sbuf[22][2 * tid] = make_float2(w0c, w1c);
    *(float2*)&sbuf[23][2 * tid] = make_float2(w0d, w1d);
    *(float2*)(gw)                    = make_float2(w0a, w1a);
    *(float2*)(gw + (size_t)NV)       = make_float2(w0b, w1b);
    *(float2*)(gw + (size_t)2 * NV)   = make_float2(w0c, w1c);
    *(float2*)(gw + (size_t)3 * NV)   = make_float2(w0d, w1d);
}

// 96 max/sum tasks over 512 vertices; warp w -> aa = w>>1, c = (w&1)*12..+12
__device__ __forceinline__ void reduce96_2(
    const float (*__restrict__ sbuf)[HALF_V], int b, int half, int warp, int lane,
    int pb)
{
    const int aa = warp >> 1, cbase = (warp & 1) * 12;
    ull s2[12]; float m0[12], m1[12];
    #pragma unroll
    for (int c = 0; c < 12; c++) { s2[c] = 0ull; m0[c] = -CUDART_INF_F; m1[c] = -CUDART_INF_F; }
    #pragma unroll
    for (int i = 0; i < 8; i++) {
        const int vv = (lane + i * 32) * 2;
        ull w2 = *(const ull*)&sbuf[NP + aa][vv];
        #pragma unroll
        for (int c = 0; c < 12; c++) {
            ull f2 = *(const ull*)&sbuf[cbase + c][vv];
            ull p = mul2(w2, f2);
            s2[c] = add2(s2[c], p);
            float2 pv = up2(p);
            m0[c] = fmaxf(m0[c], pv.x);
            m1[c] = fmaxf(m1[c], pv.y);
        }
    }
    #pragma unroll
    for (int c = 0; c < 12; c++) {
        float m = fmaxf(m0[c], m1[c]);
        float2 sv = up2(s2[c]);
        float s = sv.x + sv.y;
        #pragma unroll
        for (int o = 16; o > 0; o >>= 1) {
            m = fmaxf(m, __shfl_xor_sync(~0u, m, o));
            s += __shfl_xor_sync(~0u, s, o);
        }
        if (lane == 0) {
            const int t = aa * 24 + cbase + c;
            g_pmax[pb][(b * 96 + t) * 2 + half] = m;
            g_psum[pb][(b * 96 + t) * 2 + half] = s;
        }
    }
}

// =====================================================================
// kA: per-event vertex mean + folded constant bias
// =====================================================================
__global__ __launch_bounds__(256)
void kA(const float* __restrict__ x,
        const float* __restrict__ bn0_gamma, const float* __restrict__ bn0_beta,
        const float* __restrict__ bn0_mean,  const float* __restrict__ bn0_var,
        const float* __restrict__ W_in,      const float* __restrict__ b_in)
{
    __shared__ float sp[8][NFEAT];
    __shared__ float smean[NFEAT];
    __shared__ float ss0[20], st0[20];
    const int tid = threadIdx.x, b = blockIdx.x;
    const int lane = tid & 31, warp = tid >> 5;

    float s[NFEAT];
    #pragma unroll
    for (int c = 0; c < NFEAT; c++) s[c] = 0.0f;
    #pragma unroll
    for (int i = 0; i < 4; i++) {
        const float* xv = x + ((size_t)b * NV + tid + i * 256) * NFEAT;
        #pragma unroll
        for (int c = 0; c < NFEAT; c++) s[c] += xv[c];
    }
    #pragma unroll
    for (int o = 16; o > 0; o >>= 1)
        #pragma unroll
        for (int c = 0; c < NFEAT; c++) s[c] += __shfl_xor_sync(~0u, s[c], o);
    if (lane == 0)
        #pragma unroll
        for (int c = 0; c < NFEAT; c++) sp[warp][c] = s[c];
    if (tid < 20) {
        float sc = bn0_gamma[tid] * rsqrtf(bn0_var[tid] + 1e-3f);
        ss0[tid] = sc;
        st0[tid] = bn0_beta[tid] - bn0_mean[tid] * sc;
    }
    __syncthreads();
    if (tid < NFEAT) {
        float a = 0.0f;
        #pragma unroll
        for (int w = 0; w < 8; w++) a += sp[w][tid];
        smean[tid] = a * (1.0f / 1024.0f);
    }
    __syncthreads();
    if (tid < NF) {
        float a = b_in[tid];
        #pragma unroll
        for (int c = 10; c < 20; c++) {
            float g = smean[c - 10] * ss0[c] + st0[c];
            a += g * W_in[c * NF + tid];
        }
        g_cbias[b * NF + tid] = a;
    }
}

// =====================================================================
// kB_fw: h0 = tanh(bn0(x)@W_in + cbias) -> slot 0, fused fw(block 0)
// =====================================================================
struct __align__(16) SmemB {
    float sbuf[NC][HALF_V];
    float sW[NFEAT][NF];
    float sWfw[NF][NC];
    float scb[NF];
    float ss0[NFEAT], st0[NFEAT];
    float sbfw[NC];
};

__global__ __launch_bounds__(256, 2)
void kB_fw(const float* __restrict__ x,
           const float* __restrict__ bn0_gamma, const float* __restrict__ bn0_var,
           const float* __restrict__ bn0_beta,  const float* __restrict__ bn0_mean,
           const float* __restrict__ W_in,
           const float* __restrict__ W_flr, const float* __restrict__ b_flr,
           const float* __restrict__ W_s,   const float* __restrict__ b_s)
{
    extern __shared__ char smraw[];
    SmemB& S = *reinterpret_cast<SmemB*>(smraw);
    const int tid = threadIdx.x;
    const int b = blockIdx.x >> 1, half = blockIdx.x & 1;
    const int v0 = half * HALF_V + tid * 2;
    const int warp = tid >> 5, lane = tid & 31;

    const float* xv0 = x + ((size_t)b * NV + v0) * NFEAT;
    float xr0[NFEAT], xr1[NFEAT];
    #pragma unroll
    for (int c = 0; c < NFEAT; c++) { xr0[c] = xv0[c]; xr1[c] = xv0[NFEAT + c]; }

    for (int i = tid; i < NFEAT * NF; i += 256) S.sW[i / NF][i % NF] = W_in[i];
    for (int i = tid; i < NF * NC; i += 256) {
        int k = i / NC, c = i % NC;
        S.sWfw[k][c] = (c < NP) ? W_flr[(size_t)k * NP + c] : W_s[(size_t)k * NA + (c - NP)];
    }
    if (tid < NF) S.scb[tid] = g_cbias[b * NF + tid];
    if (tid >= 32 && tid < 32 + NFEAT) {
        int c = tid - 32;
        float sc = bn0_gamma[c] * rsqrtf(bn0_var[c] + 1e-3f);
        S.ss0[c] = sc;
        S.st0[c] = bn0_beta[c] - bn0_mean[c] * sc;
    }
    if (tid >= 64 && tid < 64 + NC)
        S.sbfw[tid - 64] = (tid - 64 < NP) ? b_flr[tid - 64] : b_s[tid - 64 - NP];
    __syncthreads();

    ull acc0[16], acc1[16];
    #pragma unroll
    for (int j = 0; j < 16; j++) {
        float2 bb = *(const float2*)&S.scb[2 * j];
        ull p = pk2(bb.x, bb.y);
        acc0[j] = p; acc1[j] = p;
    }
    #pragma unroll
    for (int c = 0; c < NFEAT; c++) {
        float sc = S.ss0[c], sh = S.st0[c];
        ull g0 = dup2(xr0[c] * sc + sh);
        ull g1 = dup2(xr1[c] * sc + sh);
        #pragma unroll
        for (int g8 = 0; g8 < 8; g8++) {
            F4U w; w.f = *(const float4*)&S.sW[c][g8 * 4];
            fma2(acc0[g8 * 2],     g0, w.u[0]); fma2(acc0[g8 * 2 + 1], g0, w.u[1]);
            fma2(acc1[g8 * 2],     g1, w.u[0]); fma2(acc1[g8 * 2 + 1], g1, w.u[1]);
        }
    }
    float* ob = g_h + (size_t)b * 384 * NV + v0;
    ull facc0[12], facc1[12];
    stream_epi_fw2<false>(acc0, acc1, nullptr, nullptr, S.sWfw, S.sbfw, ob, facc0, facc1);
    fw_finish2(facc0, facc1, S.sbuf, tid, g_w + ((size_t)b * NA) * NV + v0);
    __syncthreads();
    reduce96_2(S.sbuf, b, half, warp, lane, 0);
}

// =====================================================================
// F: fused block: Gp(l) -> out(l) -> h_{l+1} -> fw(l+1) -> partials
// =====================================================================
struct __align__(16) SmemF {
    float sbuf[NC][HALF_V];
    float sWo32[NF][NF];
    float sWfw[NF][NC];
    float sGp[NA][NF];
    float sam[96], sas[96];
    float sbfw[NC];
    float sbo[NF], sscale[NF], sshift[NF];
};

__global__ __launch_bounds__(256, 2)
void F_block(int l,
             const float* __restrict__ W_out,    const float* __restrict__ b_out,
             const float* __restrict__ bn_gamma, const float* __restrict__ bn_beta,
             const float* __restrict__ bn_mean,  const float* __restrict__ bn_var,
             const float* __restrict__ W_flr,    const float* __restrict__ b_flr,
             const float* __restrict__ W_s,      const float* __restrict__ b_s)
{
    extern __shared__ char smraw[];
    SmemF& S = *reinterpret_cast<SmemF*>(smraw);
    const int tid = threadIdx.x;
    const int b = blockIdx.x >> 1, half = blockIdx.x & 1;
    const int v0 = half * HALF_V + tid * 2;
    const int warp = tid >> 5, lane = tid & 31;
    const int pb = l & 1, lf = l + 1;

    const float* hb = g_h + ((size_t)b * 384 + (size_t)l * NF) * NV + v0;
    float2 wv[NA];
    #pragma unroll
    for (int a = 0; a < NA; a++)
        wv[a] = *(const float2*)(g_w + ((size_t)b * NA + a) * NV + v0);

    const float* WoG = W_out + (size_t)l * 228 * NF;
    ((float4*)&S.sWo32[0][0])[tid] = ((const float4*)WoG)[tid];   // 256 float4 = 32x32
    for (int i = tid; i < NF * NC; i += 256) {
        int k = i / NC, c = i % NC;
        S.sWfw[k][c] = (c < NP) ? W_flr[((size_t)lf * NF + k) * NP + c]
                                : W_s[((size_t)lf * NF + k) * NA + (c - NP)];
    }
    if (tid < 96) {
        float2 pm = *(const float2*)&g_pmax[pb][(b * 96 + tid) * 2];
        float2 ps = *(const float2*)&g_psum[pb][(b * 96 + tid) * 2];
        S.sam[tid] = fmaxf(pm.x, pm.y);
        S.sas[tid] = (ps.x + ps.y) * (1.0f / 1024.0f);
    }
    if (tid >= 128 && tid < 160) {
        int j = tid - 128;
        S.sbo[j] = b_out[l * NF + j];
        float sc = bn_gamma[l * NF + j] * rsqrtf(bn_var[l * NF + j] + 1e-3f);
        S.sscale[j] = sc;
        S.sshift[j] = bn_beta[l * NF + j] - bn_mean[l * NF + j] * sc;
    }
    if (tid >= 160 && tid < 160 + NC)
        S.sbfw[tid - 160] = (tid - 160 < NP) ? b_flr[lf * NP + tid - 160]
                                             : b_s[lf * NA + tid - 160 - NP];
    __syncthreads();

    if (tid < 128) {
        const int aa = warp, j = lane;
        float g = WoG[(224 + aa) * NF + j];
        #pragma unroll
        for (int c = 0; c < NC; c++)
            g += S.sam[aa * NC + c] * WoG[(32 + aa * 48 + c) * NF + j];
        #pragma unroll
        for (int c = 0; c < NC; c++)
            g += S.sas[aa * NC + c] * WoG[(32 + aa * 48 + NC + c) * NF + j];
        S.sGp[aa][j] = g;
    }
    __syncthreads();

    ull acc0[16], acc1[16];
    #pragma unroll
    for (int j = 0; j < 16; j++) {
        float2 bb = *(const float2*)&S.sbo[2 * j];
        ull p = pk2(bb.x, bb.y);
        acc0[j] = p; acc1[j] = p;
    }
    #pragma unroll
    for (int kc = 0; kc < 4; kc++) {
        float2 h2[8];
        #pragma unroll
        for (int k = 0; k < 8; k++)
            h2[k] = *(const float2*)(hb + (size_t)(kc * 8 + k) * NV);
        #pragma unroll
        for (int k = 0; k < 8; k++) {
            ull hk0 = dup2(h2[k].x), hk1 = dup2(h2[k].y);
            #pragma unroll
            for (int g8 = 0; g8 < 8; g8++) {
                F4U w; w.f = *(const float4*)&S.sWo32[kc * 8 + k][g8 * 4];
                fma2(acc0[g8 * 2],     hk0, w.u[0]); fma2(acc0[g8 * 2 + 1], hk0, w.u[1]);
                fma2(acc1[g8 * 2],     hk1, w.u[0]); fma2(acc1[g8 * 2 + 1], hk1, w.u[1]);
            }
        }
    }
    #pragma unroll
    for (int a = 0; a < NA; a++) {
        ull wa0 = dup2(wv[a].x), wa1 = dup2(wv[a].y);
        #pragma unroll
        for (int g8 = 0; g8 < 8; g8++) {
            F4U gg; gg.f = *(const float4*)&S.sGp[a][g8 * 4];
            fma2(acc0[g8 * 2],     wa0, gg.u[0]); fma2(acc0[g8 * 2 + 1], wa0, gg.u[1]);
            fma2(acc1[g8 * 2],     wa1, gg.u[0]); fma2(acc1[g8 * 2 + 1], wa1, gg.u[1]);
        }
    }

    float* ob = g_h + ((size_t)b * 384 + (size_t)lf * NF) * NV + v0;
    ull facc0[12], facc1[12];
    stream_epi_fw2<true>(acc0, acc1, S.sscale, S.sshift, S.sWfw, S.sbfw, ob, facc0, facc1);
    fw_finish2(facc0, facc1, S.sbuf, tid, g_w + ((size_t)b * NA) * NV + v0);
    __syncthreads();
    reduce96_2(S.sbuf, b, half, warp, lane, pb ^ 1);
}

// =====================================================================
// G: final block (l=10): out only. writes slot 11
// =====================================================================
__global__ __launch_bounds__(256, 2)
void G_block(const float* __restrict__ W_out,    const float* __restrict__ b_out,
             const float* __restrict__ bn_gamma, const float* __restrict__ bn_beta,
             const float* __restrict__ bn_mean,  const float* __restrict__ bn_var)
{
    __shared__ float sWo32[NF][NF];
    __shared__ float sGp[NA][NF];
    __shared__ float sam[96], sas[96];
    __shared__ float sbo[NF], sscale[NF], sshift[NF];
    const int tid = threadIdx.x;
    const int b = blockIdx.x >> 1, half = blockIdx.x & 1;
    const int v0 = half * HALF_V + tid * 2;
    const int warp = tid >> 5, lane = tid & 31;
    const int l = 10, pb = 0;

    const float* hb = g_h + ((size_t)b * 384 + (size_t)l * NF) * NV + v0;
    float2 wv[NA];
    #pragma unroll
    for (int a = 0; a < NA; a++)
        wv[a] = *(const float2*)(g_w + ((size_t)b * NA + a) * NV + v0);

    const float* WoG = W_out + (size_t)l * 228 * NF;
    ((float4*)&sWo32[0][0])[tid] = ((const float4*)WoG)[tid];
    if (tid < 96) {
        float2 pm = *(const float2*)&g_pmax[pb][(b * 96 + tid) * 2];
        float2 ps = *(const float2*)&g_psum[pb][(b * 96 + tid) * 2];
        sam[tid] = fmaxf(pm.x, pm.y);
        sas[tid] = (ps.x + ps.y) * (1.0f / 1024.0f);
    }
    if (tid >= 128 && tid < 160) {
        int j = tid - 128;
        sbo[j] = b_out[l * NF + j];
        float sc = bn_gamma[l * NF + j] * rsqrtf(bn_var[l * NF + j] + 1e-3f);
        sscale[j] = sc;
        sshift[j] = bn_beta[l * NF + j] - bn_mean[l * NF + j] * sc;
    }
    __syncthreads();
    if (tid < 128) {
        const int aa = warp, j = lane;
        float g = WoG[(224 + aa) * NF + j];
        #pragma unroll
        for (int c = 0; c < NC; c++)
            g += sam[aa * NC + c] * WoG[(32 + aa * 48 + c) * NF + j];
        #pragma unroll
        for (int c = 0; c < NC; c++)
            g += sas[aa * NC + c] * WoG[(32 + aa * 48 + NC + c) * NF + j];
        sGp[aa][j] = g;
    }
    __syncthreads();

    ull acc0[16], acc1[16];
    #pragma unroll
    for (int j = 0; j < 16; j++) {
        float2 bb = *(const float2*)&sbo[2 * j];
        ull p = pk2(bb.x, bb.y);
        acc0[j] = p; acc1[j] = p;
    }
    #pragma unroll
    for (int kc = 0; kc < 4; kc++) {
        float2 h2[8];
        #pragma unroll
        for (int k = 0; k < 8; k++)
            h2[k] = *(const float2*)(hb + (size_t)(kc * 8 + k) * NV);
        #pragma unroll
        for (int k = 0; k < 8; k++) {
            ull hk0 = dup2(h2[k].x), hk1 = dup2(h2[k].y);
            #pragma unroll
            for (int g8 = 0; g8 < 8; g8++) {
                F4U w; w.f = *(const float4*)&sWo32[kc * 8 + k][g8 * 4];
                fma2(acc0[g8 * 2],     hk0, w.u[0]); fma2(acc0[g8 * 2 + 1], hk0, w.u[1]);
                fma2(acc1[g8 * 2],     hk1, w.u[0]); fma2(acc1[g8 * 2 + 1], hk1, w.u[1]);
            }
        }
    }
    #pragma unroll
    for (int a = 0; a < NA; a++) {
        ull wa0 = dup2(wv[a].x), wa1 = dup2(wv[a].y);
        #pragma unroll
        for (int g8 = 0; g8 < 8; g8++) {
            F4U gg; gg.f = *(const float4*)&sGp[a][g8 * 4];
            fma2(acc0[g8 * 2],     wa0, gg.u[0]); fma2(acc0[g8 * 2 + 1], wa0, gg.u[1]);
            fma2(acc1[g8 * 2],     wa1, gg.u[0]); fma2(acc1[g8 * 2 + 1], wa1, gg.u[1]);
        }
    }
    float* ob = g_h + ((size_t)b * 384 + (size_t)11 * NF) * NV + v0;
    #pragma unroll
    for (int j2 = 0; j2 < 16; j2++) {
        float2 z0 = up2(acc0[j2]), z1 = up2(acc1[j2]);
        float sc0 = sscale[2 * j2], sh0 = sshift[2 * j2];
        float sc1 = sscale[2 * j2 + 1], sh1 = sshift[2 * j2 + 1];
        *(float2*)(ob + (size_t)(2 * j2) * NV) =
            make_float2(tanh_fast(z0.x) * sc0 + sh0, tanh_fast(z1.x) * sc0 + sh0);
        *(float2*)(ob + (size_t)(2 * j2 + 1) * NV) =
            make_float2(tanh_fast(z0.y) * sc1 + sh1, tanh_fast(z1.y) * sc1 + sh1);
    }
}

// =====================================================================
// k2: out = relu(relu(feats @ W_o0 + b_o0) @ W_o1 + b_o1); feats = slots 1..11
// grid 512 (b=blk>>2, qv=blk&3): CTA = 256 vertices.
// 256 threads = 4 output-quarters x 64 vertex-groups; 4 vertices/thread,
// 12 outputs/thread. Weight LDS shared across 4 vertices (FMA:LDS = 8:1).
// =====================================================================
struct __align__(16) SmemK2 {
    float Ws[DFE * 48];        // 67.6 KB
    float part[256][12];       // [vg*4+vi][qtr*3+c] partial 2nd-layer sums, 12 KB
    float sW1[144];
    float sb0[48];
    float sb1[4];
};

__global__ __launch_bounds__(256, 2)
void k2_mlp(const float* __restrict__ W_o0, const float* __restrict__ b_o0,
            const float* __restrict__ W_o1, const float* __restrict__ b_o1,
            float* __restrict__ out)
{
    extern __shared__ char smraw[];
    SmemK2& S = *reinterpret_cast<SmemK2*>(smraw);
    const int tid = threadIdx.x;
    {
        const float4* src = (const float4*)W_o0;
        float4* dst = (float4*)S.Ws;
        for (int i = tid; i < DFE * 48 / 4; i += 256) dst[i] = src[i];
    }
    if (tid < 144) S.sW1[tid] = W_o1[tid];
    if (tid >= 160 && tid < 208) S.sb0[tid - 160] = b_o0[tid - 160];
    if (tid >= 208 && tid < 211) S.sb1[tid - 208] = b_o1[tid - 208];
    __syncthreads();

    const int b = blockIdx.x >> 2, qv = blockIdx.x & 3;
    const int qtr = tid >> 6;            // output quarter: j0 = qtr*12
    const int vg  = tid & 63;            // vertex group
    const int j0  = qtr * 12;
    const int vbase = qv * 256 + vg * 4; // 4 consecutive vertices

    // acc[vi][jj]: 4 vertices x 6 f32x2 (12 outputs)
    ull acc[4][6];
    #pragma unroll
    for (int jj = 0; jj < 6; jj++) {
        float2 bb = *(const float2*)&S.sb0[j0 + 2 * jj];
        ull p = pk2(bb.x, bb.y);
        #pragma unroll
        for (int vi = 0; vi < 4; vi++) acc[vi][jj] = p;
    }
    const float* fb = g_h + ((size_t)b * 384 + NF) * NV + vbase;
    #pragma unroll 2
    for (int k = 0; k < DFE; k++) {
        float4 f = *(const float4*)(fb + (size_t)k * NV);
        F4U w0, w1, w2;
        const float* wr = &S.Ws[k * 48 + j0];
        w0.f = *(const float4*)(wr);
        w1.f = *(const float4*)(wr + 4);
        w2.f = *(const float4*)(wr + 8);
        ull d0 = dup2(f.x), d1 = dup2(f.y), d2 = dup2(f.z), d3 = dup2(f.w);
        fma2(acc[0][0], d0, w0.u[0]); fma2(acc[0][1], d0, w0.u[1]);
        fma2(acc[0][2], d0, w1.u[0]); fma2(acc[0][3], d0, w1.u[1]);
        fma2(acc[0][4], d0, w2.u[0]); fma2(acc[0][5], d0, w2.u[1]);
        fma2(acc[1][0], d1, w0.u[0]); fma2(acc[1][1], d1, w0.u[1]);
        fma2(acc[1][2], d1, w1.u[0]); fma2(acc[1][3], d1, w1.u[1]);
        fma2(acc[1][4], d1, w2.u[0]); fma2(acc[1][5], d1, w2.u[1]);
        fma2(acc[2][0], d2, w0.u[0]); fma2(acc[2][1], d2, w0.u[1]);
        fma2(acc[2][2], d2, w1.u[0]); fma2(acc[2][3], d2, w1.u[1]);
        fma2(acc[2][4], d2, w2.u[0]); fma2(acc[2][5], d2, w2.u[1]);
        fma2(acc[3][0], d3, w0.u[0]); fma2(acc[3][1], d3, w0.u[1]);
        fma2(acc[3][2], d3, w1.u[0]); fma2(acc[3][3], d3, w1.u[1]);
        fma2(acc[3][4], d3, w2.u[0]); fma2(acc[3][5], d3, w2.u[1]);
    }

    // 2nd-layer partials: this thread's 12 hid values -> 3 dots per vertex
    #pragma unroll
    for (int vi = 0; vi < 4; vi++) {
        float o0 = 0.0f, o1 = 0.0f, o2 = 0.0f;
        #pragma unroll
        for (int jj = 0; jj < 6; jj++) {
            float2 hv = up2(acc[vi][jj]);
            float a = fmaxf(hv.x, 0.0f), c = fmaxf(hv.y, 0.0f);
            const float* w1a = &S.sW1[(j0 + 2 * jj) * 3];
            o0 += a * w1a[0] + c * w1a[3];
            o1 += a * w1a[1] + c * w1a[4];
            o2 += a * w1a[2] + c * w1a[5];
        }
        S.part[vg * 4 + vi][qtr * 3 + 0] = o0;
        S.part[vg * 4 + vi][qtr * 3 + 1] = o1;
        S.part[vg * 4 + vi][qtr * 3 + 2] = o2;
    }
    __syncthreads();

    // combine quarters: thread t handles vertex t (of this CTA's 256)
    {
        const float* p = S.part[tid];
        float o0 = S.sb1[0] + p[0] + p[3] + p[6] + p[9];
        float o1 = S.sb1[1] + p[1] + p[4] + p[7] + p[10];
        float o2 = S.sb1[2] + p[2] + p[5] + p[8] + p[11];
        float* op = out + ((size_t)b * NV + qv * 256 + tid) * 3;
        op[0] = fmaxf(o0, 0.0f);
        op[1] = fmaxf(o1, 0.0f);
        op[2] = fmaxf(o2, 0.0f);
    }
}

// =====================================================================
extern "C" void kernel_launch(void* const* d_in, const int* in_sizes, int n_in,
                              void* d_out, int out_size)
{
    const float* x         = (const float*)d_in[0];
    const float* bn0_gamma = (const float*)d_in[1];
    const float* bn0_beta  = (const float*)d_in[2];
    const float* bn0_mean  = (const float*)d_in[3];
    const float* bn0_var   = (const float*)d_in[4];
    const float* W_in      = (const float*)d_in[5];
    const float* b_in      = (const float*)d_in[6];
    const float* W_flr     = (const float*)d_in[7];
    const float* b_flr     = (const float*)d_in[8];
    const float* W_s       = (const float*)d_in[9];
    const float* b_s       = (const float*)d_in[10];
    const float* W_out     = (const float*)d_in[11];
    const float* b_out     = (const float*)d_in[12];
    const float* bn_gamma  = (const float*)d_in[13];
    const float* bn_beta   = (const float*)d_in[14];
    const float* bn_mean   = (const float*)d_in[15];
    const float* bn_var    = (const float*)d_in[16];
    const float* W_o0      = (const float*)d_in[17];
    const float* b_o0      = (const float*)d_in[18];
    const float* W_o1      = (const float*)d_in[19];
    const float* b_o1      = (const float*)d_in[20];

    cudaFuncSetAttribute(kB_fw, cudaFuncAttributeMaxDynamicSharedMemorySize,
                         (int)sizeof(SmemB));
    cudaFuncSetAttribute(F_block, cudaFuncAttributeMaxDynamicSharedMemorySize,
                         (int)sizeof(SmemF));
    cudaFuncSetAttribute(k2_mlp, cudaFuncAttributeMaxDynamicSharedMemorySize,
                         (int)sizeof(SmemK2));

    kA<<<NB, 256>>>(x, bn0_gamma, bn0_beta, bn0_mean, bn0_var, W_in, b_in);
    kB_fw<<<NB * 2, 256, sizeof(SmemB)>>>(x, bn0_gamma, bn0_var, bn0_beta, bn0_mean,
                                          W_in, W_flr, b_flr, W_s, b_s);

    for (int l = 0; l < NBK - 1; l++) {
        F_block<<<NB * 2, 256, sizeof(SmemF)>>>(l, W_out, b_out, bn_gamma, bn_beta,
                                                bn_mean, bn_var, W_flr, b_flr, W_s, b_s);
    }
    G_block<<<NB * 2, 256>>>(W_out, b_out, bn_gamma, bn_beta, bn_mean, bn_var);

    k2_mlp<<<NB * 4, 256, sizeof(SmemK2)>>>(
        W_o0, b_o0, W_o1, b_o1, (float*)d_out);
}

// round 9
// speedup vs baseline: 1.0028x; 1.0028x over previous
#include <cuda_runtime.h>
#include <math_constants.h>
#include <cstdint>
#include <cstddef>

// ---------------- problem constants ----------------
#define NB    128
#define NV    1024
#define NFEAT 10
#define NBK   11
#define NF    32
#define NP    20
#define NA    4
#define NC    24
#define DFE   352   // NBK*NF
#define HALF_V 512

// h ring: slot 0 = h0, slot l+1 = output of block l. layout g_h[b][s*32+k][v]
__device__ float g_h[(size_t)NB * 384 * NV];     // 201 MB
__device__ float g_w[(size_t)NB * NA * NV];      // per-block edge weights
__device__ float g_pmax[2][NB * 96 * 2];         // double-buffered partial max
__device__ float g_psum[2][NB * 96 * 2];         // double-buffered partial sum
__device__ float g_cbias[NB * NF];               // per-event folded input bias

// ---------------- f32x2 packed-math helpers ----------------
typedef unsigned long long ull;
__device__ __forceinline__ ull pk2(float a, float b) {
    ull r; asm("mov.b64 %0, {%1, %2};" : "=l"(r) : "f"(a), "f"(b)); return r;
}
__device__ __forceinline__ ull dup2(float a) { return pk2(a, a); }
__device__ __forceinline__ void fma2(ull& d, ull a, ull b) {
    asm("fma.rn.f32x2 %0, %1, %2, %0;" : "+l"(d) : "l"(a), "l"(b));
}
__device__ __forceinline__ ull mul2(ull a, ull b) {
    ull r; asm("mul.rn.f32x2 %0, %1, %2;" : "=l"(r) : "l"(a), "l"(b)); return r;
}
__device__ __forceinline__ ull add2(ull a, ull b) {
    ull r; asm("add.rn.f32x2 %0, %1, %2;" : "=l"(r) : "l"(a), "l"(b)); return r;
}
__device__ __forceinline__ float2 up2(ull v) {
    float2 r; asm("mov.b64 {%0, %1}, %2;" : "=f"(r.x), "=f"(r.y) : "l"(v)); return r;
}
union F4U { float4 f; ull u[2]; };

__device__ __forceinline__ float tanh_fast(float x) {
    float r; asm("tanh.approx.f32 %0, %1;" : "=f"(r) : "f"(x)); return r;
}

// ---------------- 2-vertex shared helpers ----------------
template<bool BN>
__device__ __forceinline__ void stream_epi_fw2(
    ull acc0[16], ull acc1[16],
    const float* __restrict__ sscale, const float* __restrict__ sshift,
    const float (*__restrict__ sWfw)[NC], const float* __restrict__ sbfw,
    float* __restrict__ ob, ull facc0[12], ull facc1[12])
{
    #pragma unroll
    for (int j = 0; j < 12; j++) {
        float2 bb = *(const float2*)&sbfw[2 * j];
        ull p = pk2(bb.x, bb.y);
        facc0[j] = p; facc1[j] = p;
    }
    #pragma unroll
    for (int j2 = 0; j2 < 16; j2++) {
        float2 z0 = up2(acc0[j2]), z1 = up2(acc1[j2]);
        float a00 = tanh_fast(z0.x), a01 = tanh_fast(z0.y);
        float a10 = tanh_fast(z1.x), a11 = tanh_fast(z1.y);
        if (BN) {
            float sc0 = sscale[2 * j2], sh0 = sshift[2 * j2];
            float sc1 = sscale[2 * j2 + 1], sh1 = sshift[2 * j2 + 1];
            a00 = a00 * sc0 + sh0; a10 = a10 * sc0 + sh0;
            a01 = a01 * sc1 + sh1; a11 = a11 * sc1 + sh1;
        }
        *(float2*)(ob + (size_t)(2 * j2) * NV)     = make_float2(a00, a10);
        *(float2*)(ob + (size_t)(2 * j2 + 1) * NV) = make_float2(a01, a11);
        ull d00 = dup2(a00), d01 = dup2(a01), d10 = dup2(a10), d11 = dup2(a11);
        #pragma unroll
        for (int g6 = 0; g6 < 6; g6++) {
            F4U w0; w0.f = *(const float4*)&sWfw[2 * j2][g6 * 4];
            F4U w1; w1.f = *(const float4*)&sWfw[2 * j2 + 1][g6 * 4];
            fma2(facc0[2 * g6],     d00, w0.u[0]); fma2(facc0[2 * g6 + 1], d00, w0.u[1]);
            fma2(facc0[2 * g6],     d01, w1.u[0]); fma2(facc0[2 * g6 + 1], d01, w1.u[1]);
            fma2(facc1[2 * g6],     d10, w0.u[0]); fma2(facc1[2 * g6 + 1], d10, w0.u[1]);
            fma2(facc1[2 * g6],     d11, w1.u[0]); fma2(facc1[2 * g6 + 1], d11, w1.u[1]);
        }
    }
}

__device__ __forceinline__ void fw_finish2(
    ull facc0[12], ull facc1[12], float (*__restrict__ sbuf)[HALF_V], int tid,
    float* __restrict__ gw)
{
    #pragma unroll
    for (int j = 0; j < 10; j++) {
        float2 f0 = up2(facc0[j]), f1 = up2(facc1[j]);
        *(float2*)&sbuf[2 * j][2 * tid]     = make_float2(f0.x, f1.x);
        *(float2*)&sbuf[2 * j + 1][2 * tid] = make_float2(f0.y, f1.y);
    }
    float2 p0 = up2(facc0[10]), q0 = up2(facc0[11]);
    float2 p1 = up2(facc1[10]), q1 = up2(facc1[11]);
    float w0a = __expf(-fabsf(p0.x)), w0b = __expf(-fabsf(p0.y));
    float w0c = __expf(-fabsf(q0.x)), w0d = __expf(-fabsf(q0.y));
    float w1a = __expf(-fabsf(p1.x)), w1b = __expf(-fabsf(p1.y));
    float w1c = __expf(-fabsf(q1.x)), w1d = __expf(-fabsf(q1.y));
    *(float2*)&sbuf[20][2 * tid] = make_float2(w0a, w1a);
    *(float2*)&sbuf[21][2 * tid] = make_float2(w0b, w1b);
    *(float2*)&sbuf[22][2 * tid] = make_float2(w0c, w1c);
    *(float2*)&sbuf[23][2 * tid] = make_float2(w0d, w1d);
    *(float2*)(gw)                    = make_float2(w0a, w1a);
    *(float2*)(gw + (size_t)NV)       = make_float2(w0b, w1b);
    *(float2*)(gw + (size_t)2 * NV)   = make_float2(w0c, w1c);
    *(float2*)(gw + (size_t)3 * NV)   = make_float2(w0d, w1d);
}

// 96 max/sum tasks over 512 vertices; warp w -> aa = w>>1, c = (w&1)*12..+12
__device__ __forceinline__ void reduce96_2(
    const float (*__restrict__ sbuf)[HALF_V], int b, int half, int warp, int lane,
    int pb)
{
    const int aa = warp >> 1, cbase = (warp & 1) * 12;
    ull s2[12]; float m0[12], m1[12];
    #pragma unroll
    for (int c = 0; c < 12; c++) { s2[c] = 0ull; m0[c] = -CUDART_INF_F; m1[c] = -CUDART_INF_F; }
    #pragma unroll
    for (int i = 0; i < 8; i++) {
        const int vv = (lane + i * 32) * 2;
        ull w2 = *(const ull*)&sbuf[NP + aa][vv];
        #pragma unroll
        for (int c = 0; c < 12; c++) {
            ull f2 = *(const ull*)&sbuf[cbase + c][vv];
            ull p = mul2(w2, f2);
            s2[c] = add2(s2[c], p);
            float2 pv = up2(p);
            m0[c] = fmaxf(m0[c], pv.x);
            m1[c] = fmaxf(m1[c], pv.y);
        }
    }
    #pragma unroll
    for (int c = 0; c < 12; c++) {
        float m = fmaxf(m0[c], m1[c]);
        float2 sv = up2(s2[c]);
        float s = sv.x + sv.y;
        #pragma unroll
        for (int o = 16; o > 0; o >>= 1) {
            m = fmaxf(m, __shfl_xor_sync(~0u, m, o));
            s += __shfl_xor_sync(~0u, s, o);
        }
        if (lane == 0) {
            const int t = aa * 24 + cbase + c;
            g_pmax[pb][(b * 96 + t) * 2 + half] = m;
            g_psum[pb][(b * 96 + t) * 2 + half] = s;
        }
    }
}

// =====================================================================
// kA: per-event vertex mean + folded constant bias
// =====================================================================
__global__ __launch_bounds__(256)
void kA(const float* __restrict__ x,
        const float* __restrict__ bn0_gamma, const float* __restrict__ bn0_beta,
        const float* __restrict__ bn0_mean,  const float* __restrict__ bn0_var,
        const float* __restrict__ W_in,      const float* __restrict__ b_in)
{
    __shared__ float sp[8][NFEAT];
    __shared__ float smean[NFEAT];
    __shared__ float ss0[20], st0[20];
    const int tid = threadIdx.x, b = blockIdx.x;
    const int lane = tid & 31, warp = tid >> 5;

    float s[NFEAT];
    #pragma unroll
    for (int c = 0; c < NFEAT; c++) s[c] = 0.0f;
    #pragma unroll
    for (int i = 0; i < 4; i++) {
        const float* xv = x + ((size_t)b * NV + tid + i * 256) * NFEAT;
        #pragma unroll
        for (int c = 0; c < NFEAT; c++) s[c] += xv[c];
    }
    #pragma unroll
    for (int o = 16; o > 0; o >>= 1)
        #pragma unroll
        for (int c = 0; c < NFEAT; c++) s[c] += __shfl_xor_sync(~0u, s[c], o);
    if (lane == 0)
        #pragma unroll
        for (int c = 0; c < NFEAT; c++) sp[warp][c] = s[c];
    if (tid < 20) {
        float sc = bn0_gamma[tid] * rsqrtf(bn0_var[tid] + 1e-3f);
        ss0[tid] = sc;
        st0[tid] = bn0_beta[tid] - bn0_mean[tid] * sc;
    }
    __syncthreads();
    if (tid < NFEAT) {
        float a = 0.0f;
        #pragma unroll
        for (int w = 0; w < 8; w++) a += sp[w][tid];
        smean[tid] = a * (1.0f / 1024.0f);
    }
    __syncthreads();
    if (tid < NF) {
        float a = b_in[tid];
        #pragma unroll
        for (int c = 10; c < 20; c++) {
            float g = smean[c - 10] * ss0[c] + st0[c];
            a += g * W_in[c * NF + tid];
        }
        g_cbias[b * NF + tid] = a;
    }
}

// =====================================================================
// kB_fw: h0 = tanh(bn0(x)@W_in + cbias) -> slot 0, fused fw(block 0)
// =====================================================================
struct __align__(16) SmemB {
    float sbuf[NC][HALF_V];
    float sW[NFEAT][NF];
    float sWfw[NF][NC];
    float scb[NF];
    float ss0[NFEAT], st0[NFEAT];
    float sbfw[NC];
};

__global__ __launch_bounds__(256, 2)
void kB_fw(const float* __restrict__ x,
           const float* __restrict__ bn0_gamma, const float* __restrict__ bn0_var,
           const float* __restrict__ bn0_beta,  const float* __restrict__ bn0_mean,
           const float* __restrict__ W_in,
           const float* __restrict__ W_flr, const float* __restrict__ b_flr,
           const float* __restrict__ W_s,   const float* __restrict__ b_s)
{
    extern __shared__ char smraw[];
    SmemB& S = *reinterpret_cast<SmemB*>(smraw);
    const int tid = threadIdx.x;
    const int b = blockIdx.x >> 1, half = blockIdx.x & 1;
    const int v0 = half * HALF_V + tid * 2;
    const int warp = tid >> 5, lane = tid & 31;

    const float* xv0 = x + ((size_t)b * NV + v0) * NFEAT;
    float xr0[NFEAT], xr1[NFEAT];
    #pragma unroll
    for (int c = 0; c < NFEAT; c++) { xr0[c] = xv0[c]; xr1[c] = xv0[NFEAT + c]; }

    for (int i = tid; i < NFEAT * NF; i += 256) S.sW[i / NF][i % NF] = W_in[i];
    for (int i = tid; i < NF * NC; i += 256) {
        int k = i / NC, c = i % NC;
        S.sWfw[k][c] = (c < NP) ? W_flr[(size_t)k * NP + c] : W_s[(size_t)k * NA + (c - NP)];
    }
    if (tid < NF) S.scb[tid] = g_cbias[b * NF + tid];
    if (tid >= 32 && tid < 32 + NFEAT) {
        int c = tid - 32;
        float sc = bn0_gamma[c] * rsqrtf(bn0_var[c] + 1e-3f);
        S.ss0[c] = sc;
        S.st0[c] = bn0_beta[c] - bn0_mean[c] * sc;
    }
    if (tid >= 64 && tid < 64 + NC)
        S.sbfw[tid - 64] = (tid - 64 < NP) ? b_flr[tid - 64] : b_s[tid - 64 - NP];
    __syncthreads();

    ull acc0[16], acc1[16];
    #pragma unroll
    for (int j = 0; j < 16; j++) {
        float2 bb = *(const float2*)&S.scb[2 * j];
        ull p = pk2(bb.x, bb.y);
        acc0[j] = p; acc1[j] = p;
    }
    #pragma unroll
    for (int c = 0; c < NFEAT; c++) {
        float sc = S.ss0[c], sh = S.st0[c];
        ull g0 = dup2(xr0[c] * sc + sh);
        ull g1 = dup2(xr1[c] * sc + sh);
        #pragma unroll
        for (int g8 = 0; g8 < 8; g8++) {
            F4U w; w.f = *(const float4*)&S.sW[c][g8 * 4];
            fma2(acc0[g8 * 2],     g0, w.u[0]); fma2(acc0[g8 * 2 + 1], g0, w.u[1]);
            fma2(acc1[g8 * 2],     g1, w.u[0]); fma2(acc1[g8 * 2 + 1], g1, w.u[1]);
        }
    }
    float* ob = g_h + (size_t)b * 384 * NV + v0;
    ull facc0[12], facc1[12];
    stream_epi_fw2<false>(acc0, acc1, nullptr, nullptr, S.sWfw, S.sbfw, ob, facc0, facc1);
    fw_finish2(facc0, facc1, S.sbuf, tid, g_w + ((size_t)b * NA) * NV + v0);
    __syncthreads();
    reduce96_2(S.sbuf, b, half, warp, lane, 0);
}

// =====================================================================
// F: fused block: Gp(l) -> out(l) -> h_{l+1} -> fw(l+1) -> partials
// =====================================================================
struct __align__(16) SmemF {
    float sbuf[NC][HALF_V];
    float sWo32[NF][NF];
    float sWfw[NF][NC];
    float sGp[NA][NF];
    float sam[96], sas[96];
    float sbfw[NC];
    float sbo[NF], sscale[NF], sshift[NF];
};

__global__ __launch_bounds__(256, 2)
void F_block(int l,
             const float* __restrict__ W_out,    const float* __restrict__ b_out,
             const float* __restrict__ bn_gamma, const float* __restrict__ bn_beta,
             const float* __restrict__ bn_mean,  const float* __restrict__ bn_var,
             const float* __restrict__ W_flr,    const float* __restrict__ b_flr,
             const float* __restrict__ W_s,      const float* __restrict__ b_s)
{
    extern __shared__ char smraw[];
    SmemF& S = *reinterpret_cast<SmemF*>(smraw);
    const int tid = threadIdx.x;
    const int b = blockIdx.x >> 1, half = blockIdx.x & 1;
    const int v0 = half * HALF_V + tid * 2;
    const int warp = tid >> 5, lane = tid & 31;
    const int pb = l & 1, lf = l + 1;

    const float* hb = g_h + ((size_t)b * 384 + (size_t)l * NF) * NV + v0;
    float2 wv[NA];
    #pragma unroll
    for (int a = 0; a < NA; a++)
        wv[a] = *(const float2*)(g_w + ((size_t)b * NA + a) * NV + v0);

    const float* WoG = W_out + (size_t)l * 228 * NF;
    ((float4*)&S.sWo32[0][0])[tid] = ((const float4*)WoG)[tid];   // 256 float4 = 32x32
    for (int i = tid; i < NF * NC; i += 256) {
        int k = i / NC, c = i % NC;
        S.sWfw[k][c] = (c < NP) ? W_flr[((size_t)lf * NF + k) * NP + c]
                                : W_s[((size_t)lf * NF + k) * NA + (c - NP)];
    }
    if (tid < 96) {
        float2 pm = *(const float2*)&g_pmax[pb][(b * 96 + tid) * 2];
        float2 ps = *(const float2*)&g_psum[pb][(b * 96 + tid) * 2];
        S.sam[tid] = fmaxf(pm.x, pm.y);
        S.sas[tid] = (ps.x + ps.y) * (1.0f / 1024.0f);
    }
    if (tid >= 128 && tid < 160) {
        int j = tid - 128;
        S.sbo[j] = b_out[l * NF + j];
        float sc = bn_gamma[l * NF + j] * rsqrtf(bn_var[l * NF + j] + 1e-3f);
        S.sscale[j] = sc;
        S.sshift[j] = bn_beta[l * NF + j] - bn_mean[l * NF + j] * sc;
    }
    if (tid >= 160 && tid < 160 + NC)
        S.sbfw[tid - 160] = (tid - 160 < NP) ? b_flr[lf * NP + tid - 160]
                                             : b_s[lf * NA + tid - 160 - NP];
    __syncthreads();

    if (tid < 128) {
        const int aa = warp, j = lane;
        float g = WoG[(224 + aa) * NF + j];
        #pragma unroll
        for (int c = 0; c < NC; c++)
            g += S.sam[aa * NC + c] * WoG[(32 + aa * 48 + c) * NF + j];
        #pragma unroll
        for (int c = 0; c < NC; c++)
            g += S.sas[aa * NC + c] * WoG[(32 + aa * 48 + NC + c) * NF + j];
        S.sGp[aa][j] = g;
    }
    __syncthreads();

    ull acc0[16], acc1[16];
    #pragma unroll
    for (int j = 0; j < 16; j++) {
        float2 bb = *(const float2*)&S.sbo[2 * j];
        ull p = pk2(bb.x, bb.y);
        acc0[j] = p; acc1[j] = p;
    }
    #pragma unroll
    for (int kc = 0; kc < 4; kc++) {
        float2 h2[8];
        #pragma unroll
        for (int k = 0; k < 8; k++)
            h2[k] = *(const float2*)(hb + (size_t)(kc * 8 + k) * NV);
        #pragma unroll
        for (int k = 0; k < 8; k++) {
            ull hk0 = dup2(h2[k].x), hk1 = dup2(h2[k].y);
            #pragma unroll
            for (int g8 = 0; g8 < 8; g8++) {
                F4U w; w.f = *(const float4*)&S.sWo32[kc * 8 + k][g8 * 4];
                fma2(acc0[g8 * 2],     hk0, w.u[0]); fma2(acc0[g8 * 2 + 1], hk0, w.u[1]);
                fma2(acc1[g8 * 2],     hk1, w.u[0]); fma2(acc1[g8 * 2 + 1], hk1, w.u[1]);
            }
        }
    }
    #pragma unroll
    for (int a = 0; a < NA; a++) {
        ull wa0 = dup2(wv[a].x), wa1 = dup2(wv[a].y);
        #pragma unroll
        for (int g8 = 0; g8 < 8; g8++) {
            F4U gg; gg.f = *(const float4*)&S.sGp[a][g8 * 4];
            fma2(acc0[g8 * 2],     wa0, gg.u[0]); fma2(acc0[g8 * 2 + 1], wa0, gg.u[1]);
            fma2(acc1[g8 * 2],     wa1, gg.u[0]); fma2(acc1[g8 * 2 + 1], wa1, gg.u[1]);
        }
    }

    float* ob = g_h + ((size_t)b * 384 + (size_t)lf * NF) * NV + v0;
    ull facc0[12], facc1[12];
    stream_epi_fw2<true>(acc0, acc1, S.sscale, S.sshift, S.sWfw, S.sbfw, ob, facc0, facc1);
    fw_finish2(facc0, facc1, S.sbuf, tid, g_w + ((size_t)b * NA) * NV + v0);
    __syncthreads();
    reduce96_2(S.sbuf, b, half, warp, lane, pb ^ 1);
}

// =====================================================================
// G: final block (l=10): out only. writes slot 11
// =====================================================================
__global__ __launch_bounds__(256, 2)
void G_block(const float* __restrict__ W_out,    const float* __restrict__ b_out,
             const float* __restrict__ bn_gamma, const float* __restrict__ bn_beta,
             const float* __restrict__ bn_mean,  const float* __restrict__ bn_var)
{
    __shared__ float sWo32[NF][NF];
    __shared__ float sGp[NA][NF];
    __shared__ float sam[96], sas[96];
    __shared__ float sbo[NF], sscale[NF], sshift[NF];
    const int tid = threadIdx.x;
    const int b = blockIdx.x >> 1, half = blockIdx.x & 1;
    const int v0 = half * HALF_V + tid * 2;
    const int warp = tid >> 5, lane = tid & 31;
    const int l = 10, pb = 0;

    const float* hb = g_h + ((size_t)b * 384 + (size_t)l * NF) * NV + v0;
    float2 wv[NA];
    #pragma unroll
    for (int a = 0; a < NA; a++)
        wv[a] = *(const float2*)(g_w + ((size_t)b * NA + a) * NV + v0);

    const float* WoG = W_out + (size_t)l * 228 * NF;
    ((float4*)&sWo32[0][0])[tid] = ((const float4*)WoG)[tid];
    if (tid < 96) {
        float2 pm = *(const float2*)&g_pmax[pb][(b * 96 + tid) * 2];
        float2 ps = *(const float2*)&g_psum[pb][(b * 96 + tid) * 2];
        sam[tid] = fmaxf(pm.x, pm.y);
        sas[tid] = (ps.x + ps.y) * (1.0f / 1024.0f);
    }
    if (tid >= 128 && tid < 160) {
        int j = tid - 128;
        sbo[j] = b_out[l * NF + j];
        float sc = bn_gamma[l * NF + j] * rsqrtf(bn_var[l * NF + j] + 1e-3f);
        sscale[j] = sc;
        sshift[j] = bn_beta[l * NF + j] - bn_mean[l * NF + j] * sc;
    }
    __syncthreads();
    if (tid < 128) {
        const int aa = warp, j = lane;
        float g = WoG[(224 + aa) * NF + j];
        #pragma unroll
        for (int c = 0; c < NC; c++)
            g += sam[aa * NC + c] * WoG[(32 + aa * 48 + c) * NF + j];
        #pragma unroll
        for (int c = 0; c < NC; c++)
            g += sas[aa * NC + c] * WoG[(32 + aa * 48 + NC + c) * NF + j];
        sGp[aa][j] = g;
    }
    __syncthreads();

    ull acc0[16], acc1[16];
    #pragma unroll
    for (int j = 0; j < 16; j++) {
        float2 bb = *(const float2*)&sbo[2 * j];
        ull p = pk2(bb.x, bb.y);
        acc0[j] = p; acc1[j] = p;
    }
    #pragma unroll
    for (int kc = 0; kc < 4; kc++) {
        float2 h2[8];
        #pragma unroll
        for (int k = 0; k < 8; k++)
            h2[k] = *(const float2*)(hb + (size_t)(kc * 8 + k) * NV);
        #pragma unroll
        for (int k = 0; k < 8; k++) {
            ull hk0 = dup2(h2[k].x), hk1 = dup2(h2[k].y);
            #pragma unroll
            for (int g8 = 0; g8 < 8; g8++) {
                F4U w; w.f = *(const float4*)&sWo32[kc * 8 + k][g8 * 4];
                fma2(acc0[g8 * 2],     hk0, w.u[0]); fma2(acc0[g8 * 2 + 1], hk0, w.u[1]);
                fma2(acc1[g8 * 2],     hk1, w.u[0]); fma2(acc1[g8 * 2 + 1], hk1, w.u[1]);
            }
        }
    }
    #pragma unroll
    for (int a = 0; a < NA; a++) {
        ull wa0 = dup2(wv[a].x), wa1 = dup2(wv[a].y);
        #pragma unroll
        for (int g8 = 0; g8 < 8; g8++) {
            F4U gg; gg.f = *(const float4*)&sGp[a][g8 * 4];
            fma2(acc0[g8 * 2],     wa0, gg.u[0]); fma2(acc0[g8 * 2 + 1], wa0, gg.u[1]);
            fma2(acc1[g8 * 2],     wa1, gg.u[0]); fma2(acc1[g8 * 2 + 1], wa1, gg.u[1]);
        }
    }
    float* ob = g_h + ((size_t)b * 384 + (size_t)11 * NF) * NV + v0;
    #pragma unroll
    for (int j2 = 0; j2 < 16; j2++) {
        float2 z0 = up2(acc0[j2]), z1 = up2(acc1[j2]);
        float sc0 = sscale[2 * j2], sh0 = sshift[2 * j2];
        float sc1 = sscale[2 * j2 + 1], sh1 = sshift[2 * j2 + 1];
        *(float2*)(ob + (size_t)(2 * j2) * NV) =
            make_float2(tanh_fast(z0.x) * sc0 + sh0, tanh_fast(z1.x) * sc0 + sh0);
        *(float2*)(ob + (size_t)(2 * j2 + 1) * NV) =
            make_float2(tanh_fast(z0.y) * sc1 + sh1, tanh_fast(z1.y) * sc1 + sh1);
    }
}

// =====================================================================
// k2: out = relu(relu(feats @ W_o0 + b_o0) @ W_o1 + b_o1); feats = slots 1..11
// grid 512 (b=blk>>2, qv=blk&3): CTA = 256 vertices.
// 256 threads = 8 j-groups (6 outputs each) x 32 vertex-groups.
// 8 vertices/thread as two coalesced float4 quads (v, v+128).
// acc = 24 ull (48 regs) -> no spill. Weights via LDS.64 broadcast.
// =====================================================================
struct __align__(16) SmemK2 {
    float Ws[DFE * 48];        // 67.6 KB
    float part[24][260];       // transposed partials, padded; 25 KB
    float sW1[144];
    float sb0[48];
    float sb1[4];
};

__global__ __launch_bounds__(256, 2)
void k2_mlp(const float* __restrict__ W_o0, const float* __restrict__ b_o0,
            const float* __restrict__ W_o1, const float* __restrict__ b_o1,
            float* __restrict__ out)
{
    extern __shared__ char smraw[];
    SmemK2& S = *reinterpret_cast<SmemK2*>(smraw);
    const int tid = threadIdx.x;
    {
        const float4* src = (const float4*)W_o0;
        float4* dst = (float4*)S.Ws;
        for (int i = tid; i < DFE * 48 / 4; i += 256) dst[i] = src[i];
    }
    if (tid < 144) S.sW1[tid] = W_o1[tid];
    if (tid >= 160 && tid < 208) S.sb0[tid - 160] = b_o0[tid - 160];
    if (tid >= 208 && tid < 211) S.sb1[tid - 208] = b_o1[tid - 208];
    __syncthreads();

    const int b = blockIdx.x >> 2, qv = blockIdx.x & 3;
    const int jg = tid >> 5;             // j-group: outputs j0..j0+5
    const int vg = tid & 31;             // vertex group: 4 verts at vg*4 and 128+vg*4
    const int j0 = jg * 6;

    ull acc[8][3];
    {
        ull b01 = *(const ull*)&S.sb0[j0];
        ull b23 = *(const ull*)&S.sb0[j0 + 2];
        ull b45 = *(const ull*)&S.sb0[j0 + 4];
        #pragma unroll
        for (int vi = 0; vi < 8; vi++) {
            acc[vi][0] = b01; acc[vi][1] = b23; acc[vi][2] = b45;
        }
    }
    const float* fb = g_h + ((size_t)b * 384 + NF) * NV + qv * 256 + vg * 4;
    #pragma unroll 2
    for (int k = 0; k < DFE; k++) {
        float4 fA = *(const float4*)(fb + (size_t)k * NV);
        float4 fB = *(const float4*)(fb + (size_t)k * NV + 128);
        const float* wr = &S.Ws[k * 48 + j0];
        ull w01 = *(const ull*)(wr);
        ull w23 = *(const ull*)(wr + 2);
        ull w45 = *(const ull*)(wr + 4);
        ull d;
        d = dup2(fA.x); fma2(acc[0][0], d, w01); fma2(acc[0][1], d, w23); fma2(acc[0][2], d, w45);
        d = dup2(fA.y); fma2(acc[1][0], d, w01); fma2(acc[1][1], d, w23); fma2(acc[1][2], d, w45);
        d = dup2(fA.z); fma2(acc[2][0], d, w01); fma2(acc[2][1], d, w23); fma2(acc[2][2], d, w45);
        d = dup2(fA.w); fma2(acc[3][0], d, w01); fma2(acc[3][1], d, w23); fma2(acc[3][2], d, w45);
        d = dup2(fB.x); fma2(acc[4][0], d, w01); fma2(acc[4][1], d, w23); fma2(acc[4][2], d, w45);
        d = dup2(fB.y); fma2(acc[5][0], d, w01); fma2(acc[5][1], d, w23); fma2(acc[5][2], d, w45);
        d = dup2(fB.z); fma2(acc[6][0], d, w01); fma2(acc[6][1], d, w23); fma2(acc[6][2], d, w45);
        d = dup2(fB.w); fma2(acc[7][0], d, w01); fma2(acc[7][1], d, w23); fma2(acc[7][2], d, w45);
    }

    // second layer partials: this thread's 6 hid values -> 3 dots per vertex
    #pragma unroll
    for (int vi = 0; vi < 8; vi++) {
        float o0 = 0.0f, o1 = 0.0f, o2 = 0.0f;
        #pragma unroll
        for (int jj = 0; jj < 3; jj++) {
            float2 hv = up2(acc[vi][jj]);
            float a = fmaxf(hv.x, 0.0f), c = fmaxf(hv.y, 0.0f);
            const float* w1a = &S.sW1[(j0 + 2 * jj) * 3];
            o0 += a * w1a[0] + c * w1a[3];
            o1 += a * w1a[1] + c * w1a[4];
            o2 += a * w1a[2] + c * w1a[5];
        }
        const int v = (vi >> 2) * 128 + vg * 4 + (vi & 3);
        S.part[jg * 3 + 0][v] = o0;
        S.part[jg * 3 + 1][v] = o1;
        S.part[jg * 3 + 2][v] = o2;
    }
    __syncthreads();

    // combine: thread t handles vertex t of this CTA's 256 (conflict-free reads)
    {
        float o0 = S.sb1[0], o1 = S.sb1[1], o2 = S.sb1[2];
        #pragma unroll
        for (int g = 0; g < 8; g++) {
            o0 += S.part[g * 3 + 0][tid];
            o1 += S.part[g * 3 + 1][tid];
            o2 += S.part[g * 3 + 2][tid];
        }
        float* op = out + ((size_t)b * NV + qv * 256 + tid) * 3;
        op[0] = fmaxf(o0, 0.0f);
        op[1] = fmaxf(o1, 0.0f);
        op[2] = fmaxf(o2, 0.0f);
    }
}

// =====================================================================
extern "C" void kernel_launch(void* const* d_in, const int* in_sizes, int n_in,
                              void* d_out, int out_size)
{
    const float* x         = (const float*)d_in[0];
    const float* bn0_gamma = (const float*)d_in[1];
    const float* bn0_beta  = (const float*)d_in[2];
    const float* bn0_mean  = (const float*)d_in[3];
    const float* bn0_var   = (const float*)d_in[4];
    const float* W_in      = (const float*)d_in[5];
    const float* b_in      = (const float*)d_in[6];
    const float* W_flr     = (const float*)d_in[7];
    const float* b_flr     = (const float*)d_in[8];
    const float* W_s       = (const float*)d_in[9];
    const float* b_s       = (const float*)d_in[10];
    const float* W_out     = (const float*)d_in[11];
    const float* b_out     = (const float*)d_in[12];
    const float* bn_gamma  = (const float*)d_in[13];
    const float* bn_beta   = (const float*)d_in[14];
    const float* bn_mean   = (const float*)d_in[15];
    const float* bn_var    = (const float*)d_in[16];
    const float* W_o0      = (const float*)d_in[17];
    const float* b_o0      = (const float*)d_in[18];
    const float* W_o1      = (const float*)d_in[19];
    const float* b_o1      = (const float*)d_in[20];

    cudaFuncSetAttribute(kB_fw, cudaFuncAttributeMaxDynamicSharedMemorySize,
                         (int)sizeof(SmemB));
    cudaFuncSetAttribute(F_block, cudaFuncAttributeMaxDynamicSharedMemorySize,
                         (int)sizeof(SmemF));
    cudaFuncSetAttribute(k2_mlp, cudaFuncAttributeMaxDynamicSharedMemorySize,
                         (int)sizeof(SmemK2));

    kA<<<NB, 256>>>(x, bn0_gamma, bn0_beta, bn0_mean, bn0_var, W_in, b_in);
    kB_fw<<<NB * 2, 256, sizeof(SmemB)>>>(x, bn0_gamma, bn0_var, bn0_beta, bn0_mean,
                                          W_in, W_flr, b_flr, W_s, b_s);

    for (int l = 0; l < NBK - 1; l++) {
        F_block<<<NB * 2, 256, sizeof(SmemF)>>>(l, W_out, b_out, bn_gamma, bn_beta,
                                                bn_mean, bn_var, W_flr, b_flr, W_s, b_s);
    }
    G_block<<<NB * 2, 256>>>(W_out, b_out, bn_gamma, bn_beta, bn_mean, bn_var);

    k2_mlp<<<NB * 4, 256, sizeof(SmemK2)>>>(
        W_o0, b_o0, W_o1, b_o1, (float*)d_out);
}

// round 10
// speedup vs baseline: 1.1550x; 1.1517x over previous
#include <cuda_runtime.h>
#include <math_constants.h>
#include <cstdint>
#include <cstddef>

// ---------------- problem constants ----------------
#define NB    128
#define NV    1024
#define NFEAT 10
#define NBK   11
#define NF    32
#define NP    20
#define NA    4
#define NC    24
#define DFE   352   // NBK*NF
#define HALF_V 512

// h ring: slot 0 = h0, slot l+1 = output of block l. layout g_h[b][s*32+k][v]
__device__ float g_h[(size_t)NB * 384 * NV];     // 201 MB
__device__ float g_w[(size_t)NB * NA * NV];      // per-block edge weights
__device__ float g_pmax[2][NB * 96 * 2];         // double-buffered partial max
__device__ float g_psum[2][NB * 96 * 2];         // double-buffered partial sum

// ---------------- f32x2 packed-math helpers ----------------
typedef unsigned long long ull;
__device__ __forceinline__ ull pk2(float a, float b) {
    ull r; asm("mov.b64 %0, {%1, %2};" : "=l"(r) : "f"(a), "f"(b)); return r;
}
__device__ __forceinline__ ull dup2(float a) { return pk2(a, a); }
__device__ __forceinline__ void fma2(ull& d, ull a, ull b) {
    asm("fma.rn.f32x2 %0, %1, %2, %0;" : "+l"(d) : "l"(a), "l"(b));
}
__device__ __forceinline__ ull mul2(ull a, ull b) {
    ull r; asm("mul.rn.f32x2 %0, %1, %2;" : "=l"(r) : "l"(a), "l"(b)); return r;
}
__device__ __forceinline__ ull add2(ull a, ull b) {
    ull r; asm("add.rn.f32x2 %0, %1, %2;" : "=l"(r) : "l"(a), "l"(b)); return r;
}
__device__ __forceinline__ float2 up2(ull v) {
    float2 r; asm("mov.b64 {%0, %1}, %2;" : "=f"(r.x), "=f"(r.y) : "l"(v)); return r;
}
union F4U { float4 f; ull u[2]; };

__device__ __forceinline__ float tanh_fast(float x) {
    float r; asm("tanh.approx.f32 %0, %1;" : "=f"(r) : "f"(x)); return r;
}

// ---------------- 2-vertex shared helpers ----------------
template<bool BN>
__device__ __forceinline__ void stream_epi_fw2(
    ull acc0[16], ull acc1[16],
    const float* __restrict__ sscale, const float* __restrict__ sshift,
    const float (*__restrict__ sWfw)[NC], const float* __restrict__ sbfw,
    float* __restrict__ ob, ull facc0[12], ull facc1[12])
{
    #pragma unroll
    for (int j = 0; j < 12; j++) {
        float2 bb = *(const float2*)&sbfw[2 * j];
        ull p = pk2(bb.x, bb.y);
        facc0[j] = p; facc1[j] = p;
    }
    #pragma unroll
    for (int j2 = 0; j2 < 16; j2++) {
        float2 z0 = up2(acc0[j2]), z1 = up2(acc1[j2]);
        float a00 = tanh_fast(z0.x), a01 = tanh_fast(z0.y);
        float a10 = tanh_fast(z1.x), a11 = tanh_fast(z1.y);
        if (BN) {
            float sc0 = sscale[2 * j2], sh0 = sshift[2 * j2];
            float sc1 = sscale[2 * j2 + 1], sh1 = sshift[2 * j2 + 1];
            a00 = a00 * sc0 + sh0; a10 = a10 * sc0 + sh0;
            a01 = a01 * sc1 + sh1; a11 = a11 * sc1 + sh1;
        }
        *(float2*)(ob + (size_t)(2 * j2) * NV)     = make_float2(a00, a10);
        *(float2*)(ob + (size_t)(2 * j2 + 1) * NV) = make_float2(a01, a11);
        ull d00 = dup2(a00), d01 = dup2(a01), d10 = dup2(a10), d11 = dup2(a11);
        #pragma unroll
        for (int g6 = 0; g6 < 6; g6++) {
            F4U w0; w0.f = *(const float4*)&sWfw[2 * j2][g6 * 4];
            F4U w1; w1.f = *(const float4*)&sWfw[2 * j2 + 1][g6 * 4];
            fma2(facc0[2 * g6],     d00, w0.u[0]); fma2(facc0[2 * g6 + 1], d00, w0.u[1]);
            fma2(facc0[2 * g6],     d01, w1.u[0]); fma2(facc0[2 * g6 + 1], d01, w1.u[1]);
            fma2(facc1[2 * g6],     d10, w0.u[0]); fma2(facc1[2 * g6 + 1], d10, w0.u[1]);
            fma2(facc1[2 * g6],     d11, w1.u[0]); fma2(facc1[2 * g6 + 1], d11, w1.u[1]);
        }
    }
}

__device__ __forceinline__ void fw_finish2(
    ull facc0[12], ull facc1[12], float (*__restrict__ sbuf)[HALF_V], int tid,
    float* __restrict__ gw)
{
    #pragma unroll
    for (int j = 0; j < 10; j++) {
        float2 f0 = up2(facc0[j]), f1 = up2(facc1[j]);
        *(float2*)&sbuf[2 * j][2 * tid]     = make_float2(f0.x, f1.x);
        *(float2*)&sbuf[2 * j + 1][2 * tid] = make_float2(f0.y, f1.y);
    }
    float2 p0 = up2(facc0[10]), q0 = up2(facc0[11]);
    float2 p1 = up2(facc1[10]), q1 = up2(facc1[11]);
    float w0a = __expf(-fabsf(p0.x)), w0b = __expf(-fabsf(p0.y));
    float w0c = __expf(-fabsf(q0.x)), w0d = __expf(-fabsf(q0.y));
    float w1a = __expf(-fabsf(p1.x)), w1b = __expf(-fabsf(p1.y));
    float w1c = __expf(-fabsf(q1.x)), w1d = __expf(-fabsf(q1.y));
    *(float2*)&sbuf[20][2 * tid] = make_float2(w0a, w1a);
    *(float2*)&sbuf[21][2 * tid] = make_float2(w0b, w1b);
    *(float2*)&sbuf[22][2 * tid] = make_float2(w0c, w1c);
    *(float2*)&sbuf[23][2 * tid] = make_float2(w0d, w1d);
    *(float2*)(gw)                    = make_float2(w0a, w1a);
    *(float2*)(gw + (size_t)NV)       = make_float2(w0b, w1b);
    *(float2*)(gw + (size_t)2 * NV)   = make_float2(w0c, w1c);
    *(float2*)(gw + (size_t)3 * NV)   = make_float2(w0d, w1d);
}

// 96 max/sum tasks over 512 vertices; warp w -> aa = w>>1, c = (w&1)*12..+12
__device__ __forceinline__ void reduce96_2(
    const float (*__restrict__ sbuf)[HALF_V], int b, int half, int warp, int lane,
    int pb)
{
    const int aa = warp >> 1, cbase = (warp & 1) * 12;
    ull s2[12]; float m0[12], m1[12];
    #pragma unroll
    for (int c = 0; c < 12; c++) { s2[c] = 0ull; m0[c] = -CUDART_INF_F; m1[c] = -CUDART_INF_F; }
    #pragma unroll
    for (int i = 0; i < 8; i++) {
        const int vv = (lane + i * 32) * 2;
        ull w2 = *(const ull*)&sbuf[NP + aa][vv];
        #pragma unroll
        for (int c = 0; c < 12; c++) {
            ull f2 = *(const ull*)&sbuf[cbase + c][vv];
            ull p = mul2(w2, f2);
            s2[c] = add2(s2[c], p);
            float2 pv = up2(p);
            m0[c] = fmaxf(m0[c], pv.x);
            m1[c] = fmaxf(m1[c], pv.y);
        }
    }
    #pragma unroll
    for (int c = 0; c < 12; c++) {
        float m = fmaxf(m0[c], m1[c]);
        float2 sv = up2(s2[c]);
        float s = sv.x + sv.y;
        #pragma unroll
        for (int o = 16; o > 0; o >>= 1) {
            m = fmaxf(m, __shfl_xor_sync(~0u, m, o));
            s += __shfl_xor_sync(~0u, s, o);
        }
        if (lane == 0) {
            const int t = aa * 24 + cbase + c;
            g_pmax[pb][(b * 96 + t) * 2 + half] = m;
            g_psum[pb][(b * 96 + t) * 2 + half] = s;
        }
    }
}

// =====================================================================
// kB_fw: event mean (computed in-CTA) + h0 = tanh(bn0(x)@W_in + cbias)
// -> slot 0, fused fw(block 0). grid 256 (b=blk>>1, half=blk&1), 256 thr
// =====================================================================
struct __align__(16) SmemB {
    float sbuf[NC][HALF_V];
    float sW[NFEAT][NF];
    float sWfw[NF][NC];
    float scb[NF];
    float ss0[20], st0[20];
    float sbfw[NC];
    float sp[8][12];
    float smean[12];
};

__global__ __launch_bounds__(256, 2)
void kB_fw(const float* __restrict__ x,
           const float* __restrict__ bn0_gamma, const float* __restrict__ bn0_var,
           const float* __restrict__ bn0_beta,  const float* __restrict__ bn0_mean,
           const float* __restrict__ W_in,      const float* __restrict__ b_in,
           const float* __restrict__ W_flr, const float* __restrict__ b_flr,
           const float* __restrict__ W_s,   const float* __restrict__ b_s)
{
    extern __shared__ char smraw[];
    SmemB& S = *reinterpret_cast<SmemB*>(smraw);
    const int tid = threadIdx.x;
    const int b = blockIdx.x >> 1, half = blockIdx.x & 1;
    const int v0 = half * HALF_V + tid * 2;
    const int warp = tid >> 5, lane = tid & 31;

    // per-event vertex mean (each CTA computes it for its event; cheap)
    {
        float s[NFEAT];
        #pragma unroll
        for (int c = 0; c < NFEAT; c++) s[c] = 0.0f;
        #pragma unroll
        for (int i = 0; i < 4; i++) {
            const float* xv = x + ((size_t)b * NV + tid + i * 256) * NFEAT;
            #pragma unroll
            for (int c = 0; c < NFEAT; c++) s[c] += xv[c];
        }
        #pragma unroll
        for (int o = 16; o > 0; o >>= 1)
            #pragma unroll
            for (int c = 0; c < NFEAT; c++) s[c] += __shfl_xor_sync(~0u, s[c], o);
        if (lane == 0)
            #pragma unroll
            for (int c = 0; c < NFEAT; c++) S.sp[warp][c] = s[c];
    }

    const float* xv0 = x + ((size_t)b * NV + v0) * NFEAT;
    float xr0[NFEAT], xr1[NFEAT];
    #pragma unroll
    for (int c = 0; c < NFEAT; c++) { xr0[c] = xv0[c]; xr1[c] = xv0[NFEAT + c]; }

    for (int i = tid; i < NFEAT * NF; i += 256) S.sW[i / NF][i % NF] = W_in[i];
    for (int i = tid; i < NF * NC; i += 256) {
        int k = i / NC, c = i % NC;
        S.sWfw[k][c] = (c < NP) ? W_flr[(size_t)k * NP + c] : W_s[(size_t)k * NA + (c - NP)];
    }
    if (tid >= 32 && tid < 52) {
        int c = tid - 32;
        float sc = bn0_gamma[c] * rsqrtf(bn0_var[c] + 1e-3f);
        S.ss0[c] = sc;
        S.st0[c] = bn0_beta[c] - bn0_mean[c] * sc;
    }
    if (tid >= 64 && tid < 64 + NC)
        S.sbfw[tid - 64] = (tid - 64 < NP) ? b_flr[tid - 64] : b_s[tid - 64 - NP];
    __syncthreads();
    if (tid < NFEAT) {
        float a = 0.0f;
        #pragma unroll
        for (int w = 0; w < 8; w++) a += S.sp[w][tid];
        S.smean[tid] = a * (1.0f / 1024.0f);
    }
    __syncthreads();
    if (tid < NF) {   // fold mean-half of gex + b_in into per-event constant bias
        float a = b_in[tid];
        #pragma unroll
        for (int c = 10; c < 20; c++) {
            float g = S.smean[c - 10] * S.ss0[c] + S.st0[c];
            a += g * W_in[c * NF + tid];
        }
        S.scb[tid] = a;
    }
    __syncthreads();

    ull acc0[16], acc1[16];
    #pragma unroll
    for (int j = 0; j < 16; j++) {
        float2 bb = *(const float2*)&S.scb[2 * j];
        ull p = pk2(bb.x, bb.y);
        acc0[j] = p; acc1[j] = p;
    }
    #pragma unroll
    for (int c = 0; c < NFEAT; c++) {
        float sc = S.ss0[c], sh = S.st0[c];
        ull g0 = dup2(xr0[c] * sc + sh);
        ull g1 = dup2(xr1[c] * sc + sh);
        #pragma unroll
        for (int g8 = 0; g8 < 8; g8++) {
            F4U w; w.f = *(const float4*)&S.sW[c][g8 * 4];
            fma2(acc0[g8 * 2],     g0, w.u[0]); fma2(acc0[g8 * 2 + 1], g0, w.u[1]);
            fma2(acc1[g8 * 2],     g1, w.u[0]); fma2(acc1[g8 * 2 + 1], g1, w.u[1]);
        }
    }
    float* ob = g_h + (size_t)b * 384 * NV + v0;
    ull facc0[12], facc1[12];
    stream_epi_fw2<false>(acc0, acc1, nullptr, nullptr, S.sWfw, S.sbfw, ob, facc0, facc1);
    fw_finish2(facc0, facc1, S.sbuf, tid, g_w + ((size_t)b * NA) * NV + v0);
    __syncthreads();
    reduce96_2(S.sbuf, b, half, warp, lane, 0);
}

// =====================================================================
// F: fused block: Gp(l) -> out(l) -> h_{l+1} -> fw(l+1) -> partials
// =====================================================================
struct __align__(16) SmemF {
    float sbuf[NC][HALF_V];
    float sWo32[NF][NF];
    float sWfw[NF][NC];
    float sGp[NA][NF];
    float sam[96], sas[96];
    float sbfw[NC];
    float sbo[NF], sscale[NF], sshift[NF];
};

__global__ __launch_bounds__(256, 2)
void F_block(int l,
             const float* __restrict__ W_out,    const float* __restrict__ b_out,
             const float* __restrict__ bn_gamma, const float* __restrict__ bn_beta,
             const float* __restrict__ bn_mean,  const float* __restrict__ bn_var,
             const float* __restrict__ W_flr,    const float* __restrict__ b_flr,
             const float* __restrict__ W_s,      const float* __restrict__ b_s)
{
    extern __shared__ char smraw[];
    SmemF& S = *reinterpret_cast<SmemF*>(smraw);
    const int tid = threadIdx.x;
    const int b = blockIdx.x >> 1, half = blockIdx.x & 1;
    const int v0 = half * HALF_V + tid * 2;
    const int warp = tid >> 5, lane = tid & 31;
    const int pb = l & 1, lf = l + 1;

    const float* hb = g_h + ((size_t)b * 384 + (size_t)l * NF) * NV + v0;
    float2 wv[NA];
    #pragma unroll
    for (int a = 0; a < NA; a++)
        wv[a] = *(const float2*)(g_w + ((size_t)b * NA + a) * NV + v0);

    const float* WoG = W_out + (size_t)l * 228 * NF;
    ((float4*)&S.sWo32[0][0])[tid] = ((const float4*)WoG)[tid];   // 256 float4 = 32x32
    for (int i = tid; i < NF * NC; i += 256) {
        int k = i / NC, c = i % NC;
        S.sWfw[k][c] = (c < NP) ? W_flr[((size_t)lf * NF + k) * NP + c]
                                : W_s[((size_t)lf * NF + k) * NA + (c - NP)];
    }
    if (tid < 96) {
        float2 pm = *(const float2*)&g_pmax[pb][(b * 96 + tid) * 2];
        float2 ps = *(const float2*)&g_psum[pb][(b * 96 + tid) * 2];
        S.sam[tid] = fmaxf(pm.x, pm.y);
        S.sas[tid] = (ps.x + ps.y) * (1.0f / 1024.0f);
    }
    if (tid >= 128 && tid < 160) {
        int j = tid - 128;
        S.sbo[j] = b_out[l * NF + j];
        float sc = bn_gamma[l * NF + j] * rsqrtf(bn_var[l * NF + j] + 1e-3f);
        S.sscale[j] = sc;
        S.sshift[j] = bn_beta[l * NF + j] - bn_mean[l * NF + j] * sc;
    }
    if (tid >= 160 && tid < 160 + NC)
        S.sbfw[tid - 160] = (tid - 160 < NP) ? b_flr[lf * NP + tid - 160]
                                             : b_s[lf * NA + tid - 160 - NP];
    __syncthreads();

    if (tid < 128) {
        const int aa = warp, j = lane;
        float g = WoG[(224 + aa) * NF + j];
        #pragma unroll
        for (int c = 0; c < NC; c++)
            g += S.sam[aa * NC + c] * WoG[(32 + aa * 48 + c) * NF + j];
        #pragma unroll
        for (int c = 0; c < NC; c++)
            g += S.sas[aa * NC + c] * WoG[(32 + aa * 48 + NC + c) * NF + j];
        S.sGp[aa][j] = g;
    }
    __syncthreads();

    ull acc0[16], acc1[16];
    #pragma unroll
    for (int j = 0; j < 16; j++) {
        float2 bb = *(const float2*)&S.sbo[2 * j];
        ull p = pk2(bb.x, bb.y);
        acc0[j] = p; acc1[j] = p;
    }
    #pragma unroll
    for (int kc = 0; kc < 4; kc++) {
        float2 h2[8];
        #pragma unroll
        for (int k = 0; k < 8; k++)
            h2[k] = *(const float2*)(hb + (size_t)(kc * 8 + k) * NV);
        #pragma unroll
        for (int k = 0; k < 8; k++) {
            ull hk0 = dup2(h2[k].x), hk1 = dup2(h2[k].y);
            #pragma unroll
            for (int g8 = 0; g8 < 8; g8++) {
                F4U w; w.f = *(const float4*)&S.sWo32[kc * 8 + k][g8 * 4];
                fma2(acc0[g8 * 2],     hk0, w.u[0]); fma2(acc0[g8 * 2 + 1], hk0, w.u[1]);
                fma2(acc1[g8 * 2],     hk1, w.u[0]); fma2(acc1[g8 * 2 + 1], hk1, w.u[1]);
            }
        }
    }
    #pragma unroll
    for (int a = 0; a < NA; a++) {
        ull wa0 = dup2(wv[a].x), wa1 = dup2(wv[a].y);
        #pragma unroll
        for (int g8 = 0; g8 < 8; g8++) {
            F4U gg; gg.f = *(const float4*)&S.sGp[a][g8 * 4];
            fma2(acc0[g8 * 2],     wa0, gg.u[0]); fma2(acc0[g8 * 2 + 1], wa0, gg.u[1]);
            fma2(acc1[g8 * 2],     wa1, gg.u[0]); fma2(acc1[g8 * 2 + 1], wa1, gg.u[1]);
        }
    }

    float* ob = g_h + ((size_t)b * 384 + (size_t)lf * NF) * NV + v0;
    ull facc0[12], facc1[12];
    stream_epi_fw2<true>(acc0, acc1, S.sscale, S.sshift, S.sWfw, S.sbfw, ob, facc0, facc1);
    fw_finish2(facc0, facc1, S.sbuf, tid, g_w + ((size_t)b * NA) * NV + v0);
    __syncthreads();
    reduce96_2(S.sbuf, b, half, warp, lane, pb ^ 1);
}

// =====================================================================
// G: final block (l=10): out only. writes slot 11
// =====================================================================
__global__ __launch_bounds__(256, 2)
void G_block(const float* __restrict__ W_out,    const float* __restrict__ b_out,
             const float* __restrict__ bn_gamma, const float* __restrict__ bn_beta,
             const float* __restrict__ bn_mean,  const float* __restrict__ bn_var)
{
    __shared__ float sWo32[NF][NF];
    __shared__ float sGp[NA][NF];
    __shared__ float sam[96], sas[96];
    __shared__ float sbo[NF], sscale[NF], sshift[NF];
    const int tid = threadIdx.x;
    const int b = blockIdx.x >> 1, half = blockIdx.x & 1;
    const int v0 = half * HALF_V + tid * 2;
    const int warp = tid >> 5, lane = tid & 31;
    const int l = 10, pb = 0;

    const float* hb = g_h + ((size_t)b * 384 + (size_t)l * NF) * NV + v0;
    float2 wv[NA];
    #pragma unroll
    for (int a = 0; a < NA; a++)
        wv[a] = *(const float2*)(g_w + ((size_t)b * NA + a) * NV + v0);

    const float* WoG = W_out + (size_t)l * 228 * NF;
    ((float4*)&sWo32[0][0])[tid] = ((const float4*)WoG)[tid];
    if (tid < 96) {
        float2 pm = *(const float2*)&g_pmax[pb][(b * 96 + tid) * 2];
        float2 ps = *(const float2*)&g_psum[pb][(b * 96 + tid) * 2];
        sam[tid] = fmaxf(pm.x, pm.y);
        sas[tid] = (ps.x + ps.y) * (1.0f / 1024.0f);
    }
    if (tid >= 128 && tid < 160) {
        int j = tid - 128;
        sbo[j] = b_out[l * NF + j];
        float sc = bn_gamma[l * NF + j] * rsqrtf(bn_var[l * NF + j] + 1e-3f);
        sscale[j] = sc;
        sshift[j] = bn_beta[l * NF + j] - bn_mean[l * NF + j] * sc;
    }
    __syncthreads();
    if (tid < 128) {
        const int aa = warp, j = lane;
        float g = WoG[(224 + aa) * NF + j];
        #pragma unroll
        for (int c = 0; c < NC; c++)
            g += sam[aa * NC + c] * WoG[(32 + aa * 48 + c) * NF + j];
        #pragma unroll
        for (int c = 0; c < NC; c++)
            g += sas[aa * NC + c] * WoG[(32 + aa * 48 + NC + c) * NF + j];
        sGp[aa][j] = g;
    }
    __syncthreads();

    ull acc0[16], acc1[16];
    #pragma unroll
    for (int j = 0; j < 16; j++) {
        float2 bb = *(const float2*)&sbo[2 * j];
        ull p = pk2(bb.x, bb.y);
        acc0[j] = p; acc1[j] = p;
    }
    #pragma unroll
    for (int kc = 0; kc < 4; kc++) {
        float2 h2[8];
        #pragma unroll
        for (int k = 0; k < 8; k++)
            h2[k] = *(const float2*)(hb + (size_t)(kc * 8 + k) * NV);
        #pragma unroll
        for (int k = 0; k < 8; k++) {
            ull hk0 = dup2(h2[k].x), hk1 = dup2(h2[k].y);
            #pragma unroll
            for (int g8 = 0; g8 < 8; g8++) {
                F4U w; w.f = *(const float4*)&sWo32[kc * 8 + k][g8 * 4];
                fma2(acc0[g8 * 2],     hk0, w.u[0]); fma2(acc0[g8 * 2 + 1], hk0, w.u[1]);
                fma2(acc1[g8 * 2],     hk1, w.u[0]); fma2(acc1[g8 * 2 + 1], hk1, w.u[1]);
            }
        }
    }
    #pragma unroll
    for (int a = 0; a < NA; a++) {
        ull wa0 = dup2(wv[a].x), wa1 = dup2(wv[a].y);
        #pragma unroll
        for (int g8 = 0; g8 < 8; g8++) {
            F4U gg; gg.f = *(const float4*)&sGp[a][g8 * 4];
            fma2(acc0[g8 * 2],     wa0, gg.u[0]); fma2(acc0[g8 * 2 + 1], wa0, gg.u[1]);
            fma2(acc1[g8 * 2],     wa1, gg.u[1 - 1]); fma2(acc1[g8 * 2 + 1], wa1, gg.u[1]);
        }
    }
    float* ob = g_h + ((size_t)b * 384 + (size_t)11 * NF) * NV + v0;
    #pragma unroll
    for (int j2 = 0; j2 < 16; j2++) {
        float2 z0 = up2(acc0[j2]), z1 = up2(acc1[j2]);
        float sc0 = sscale[2 * j2], sh0 = sshift[2 * j2];
        float sc1 = sscale[2 * j2 + 1], sh1 = sshift[2 * j2 + 1];
        *(float2*)(ob + (size_t)(2 * j2) * NV) =
            make_float2(tanh_fast(z0.x) * sc0 + sh0, tanh_fast(z1.x) * sc0 + sh0);
        *(float2*)(ob + (size_t)(2 * j2 + 1) * NV) =
            make_float2(tanh_fast(z0.y) * sc1 + sh1, tanh_fast(z1.y) * sc1 + sh1);
    }
}

// =====================================================================
// k2: out = relu(relu(feats @ W_o0 + b_o0) @ W_o1 + b_o1); feats = slots 1..11
// grid 128 (1 CTA = 1 event = 1 SM), 512 threads, 2 adjacent verts/thread.
// R7-proven inner loop; weight staging once per SM.
// =====================================================================
#define K2_SMEMF (DFE * 48 + 144 + 48 + 4)

__global__ __launch_bounds__(512, 1)
void k2_mlp(const float* __restrict__ W_o0, const float* __restrict__ b_o0,
            const float* __restrict__ W_o1, const float* __restrict__ b_o1,
            float* __restrict__ out)
{
    extern __shared__ float s2[];
    float* Ws  = s2;
    float* sW1 = s2 + DFE * 48;
    float* sb0 = sW1 + 144;
    float* sb1 = sb0 + 48;
    const int tid = threadIdx.x;
    {
        const float4* src = (const float4*)W_o0;
        float4* dst = (float4*)Ws;
        for (int i = tid; i < DFE * 48 / 4; i += 512) dst[i] = src[i];
    }
    if (tid < 144) sW1[tid] = W_o1[tid];
    if (tid >= 160 && tid < 208) sb0[tid - 160] = b_o0[tid - 160];
    if (tid >= 208 && tid < 211) sb1[tid - 208] = b_o1[tid - 208];
    __syncthreads();

    const int b = blockIdx.x;
    const int v0 = tid * 2;

    ull acc0[24], acc1[24];
    #pragma unroll
    for (int j = 0; j < 24; j++) {
        float2 bb = *(const float2*)&sb0[2 * j];
        ull p = pk2(bb.x, bb.y);
        acc0[j] = p; acc1[j] = p;
    }
    const float* fb = g_h + ((size_t)b * 384 + NF) * NV + v0;
    #pragma unroll 4
    for (int k = 0; k < DFE; k++) {
        float2 f = *(const float2*)(fb + (size_t)k * NV);
        ull f0 = dup2(f.x), f1 = dup2(f.y);
        #pragma unroll
        for (int g12 = 0; g12 < 12; g12++) {
            F4U w; w.f = *(const float4*)&Ws[k * 48 + g12 * 4];
            fma2(acc0[g12 * 2],     f0, w.u[0]);
            fma2(acc0[g12 * 2 + 1], f0, w.u[1]);
            fma2(acc1[g12 * 2],     f1, w.u[0]);
            fma2(acc1[g12 * 2 + 1], f1, w.u[1]);
        }
    }
    #pragma unroll
    for (int m = 0; m < 2; m++) {
        const ull* acc = m ? acc1 : acc0;
        float o0 = sb1[0], o1 = sb1[1], o2 = sb1[2];
        #pragma unroll
        for (int j2 = 0; j2 < 24; j2++) {
            float2 hv = up2(acc[j2]);
            float a = fmaxf(hv.x, 0.0f), c = fmaxf(hv.y, 0.0f);
            o0 += a * sW1[(2 * j2) * 3 + 0] + c * sW1[(2 * j2 + 1) * 3 + 0];
            o1 += a * sW1[(2 * j2) * 3 + 1] + c * sW1[(2 * j2 + 1) * 3 + 1];
            o2 += a * sW1[(2 * j2) * 3 + 2] + c * sW1[(2 * j2 + 1) * 3 + 2];
        }
        float* op = out + ((size_t)b * NV + v0 + m) * 3;
        op[0] = fmaxf(o0, 0.0f);
        op[1] = fmaxf(o1, 0.0f);
        op[2] = fmaxf(o2, 0.0f);
    }
}

// =====================================================================
extern "C" void kernel_launch(void* const* d_in, const int* in_sizes, int n_in,
                              void* d_out, int out_size)
{
    const float* x         = (const float*)d_in[0];
    const float* bn0_gamma = (const float*)d_in[1];
    const float* bn0_beta  = (const float*)d_in[2];
    const float* bn0_mean  = (const float*)d_in[3];
    const float* bn0_var   = (const float*)d_in[4];
    const float* W_in      = (const float*)d_in[5];
    const float* b_in      = (const float*)d_in[6];
    const float* W_flr     = (const float*)d_in[7];
    const float* b_flr     = (const float*)d_in[8];
    const float* W_s       = (const float*)d_in[9];
    const float* b_s       = (const float*)d_in[10];
    const float* W_out     = (const float*)d_in[11];
    const float* b_out     = (const float*)d_in[12];
    const float* bn_gamma  = (const float*)d_in[13];
    const float* bn_beta   = (const float*)d_in[14];
    const float* bn_mean   = (const float*)d_in[15];
    const float* bn_var    = (const float*)d_in[16];
    const float* W_o0      = (const float*)d_in[17];
    const float* b_o0      = (const float*)d_in[18];
    const float* W_o1      = (const float*)d_in[19];
    const float* b_o1      = (const float*)d_in[20];

    cudaFuncSetAttribute(kB_fw, cudaFuncAttributeMaxDynamicSharedMemorySize,
                         (int)sizeof(SmemB));
    cudaFuncSetAttribute(F_block, cudaFuncAttributeMaxDynamicSharedMemorySize,
                         (int)sizeof(SmemF));
    cudaFuncSetAttribute(k2_mlp, cudaFuncAttributeMaxDynamicSharedMemorySize,
                         (int)(K2_SMEMF * sizeof(float)));

    kB_fw<<<NB * 2, 256, sizeof(SmemB)>>>(x, bn0_gamma, bn0_var, bn0_beta, bn0_mean,
                                          W_in, b_in, W_flr, b_flr, W_s, b_s);

    for (int l = 0; l < NBK - 1; l++) {
        F_block<<<NB * 2, 256, sizeof(SmemF)>>>(l, W_out, b_out, bn_gamma, bn_beta,
                                                bn_mean, bn_var, W_flr, b_flr, W_s, b_s);
    }
    G_block<<<NB * 2, 256>>>(W_out, b_out, bn_gamma, bn_beta, bn_mean, bn_var);

    k2_mlp<<<NB, 512, K2_SMEMF * sizeof(float)>>>(
        W_o0, b_o0, W_o1, b_o1, (float*)d_out);
}

// round 12
// speedup vs baseline: 1.2650x; 1.0952x over previous
#include <cuda_runtime.h>
#include <math_constants.h>
#include <cstdint>
#include <cstddef>

// ---------------- problem constants ----------------
#define NB    128
#define NV    1024
#define NFEAT 10
#define NBK   11
#define NF    32
#define NP    20
#define NA    4
#define NC    24
#define DFE   352   // NBK*NF
#define HALF_V 512

// h ring: slot 0 = h0, slot l+1 = output of block l. layout g_h[b][s*32+k][v]
__device__ float g_h[(size_t)NB * 384 * NV];     // 201 MB
__device__ float g_w[(size_t)NB * NA * NV];      // per-block edge weights
__device__ float g_pmax[2][NB * 96 * 2];         // double-buffered partial max
__device__ float g_psum[2][NB * 96 * 2];         // double-buffered partial sum

// ---------------- f32x2 packed-math helpers ----------------
typedef unsigned long long ull;
__device__ __forceinline__ ull pk2(float a, float b) {
    ull r; asm("mov.b64 %0, {%1, %2};" : "=l"(r) : "f"(a), "f"(b)); return r;
}
__device__ __forceinline__ ull dup2(float a) { return pk2(a, a); }
__device__ __forceinline__ void fma2(ull& d, ull a, ull b) {
    asm("fma.rn.f32x2 %0, %1, %2, %0;" : "+l"(d) : "l"(a), "l"(b));
}
__device__ __forceinline__ ull mul2(ull a, ull b) {
    ull r; asm("mul.rn.f32x2 %0, %1, %2;" : "=l"(r) : "l"(a), "l"(b)); return r;
}
__device__ __forceinline__ ull add2(ull a, ull b) {
    ull r; asm("add.rn.f32x2 %0, %1, %2;" : "=l"(r) : "l"(a), "l"(b)); return r;
}
__device__ __forceinline__ float2 up2(ull v) {
    float2 r; asm("mov.b64 {%0, %1}, %2;" : "=f"(r.x), "=f"(r.y) : "l"(v)); return r;
}
union F4U { float4 f; ull u[2]; };

__device__ __forceinline__ float tanh_fast(float x) {
    float r; asm("tanh.approx.f32 %0, %1;" : "=f"(r) : "f"(x)); return r;
}
__device__ __forceinline__ unsigned to_tf32(float x) {
    unsigned r; asm("cvt.rna.tf32.f32 %0, %1;" : "=r"(r) : "f"(x)); return r;
}
__device__ __forceinline__ void split_tf32(float x, unsigned& hi, unsigned& lo) {
    hi = to_tf32(x);
    lo = to_tf32(x - __uint_as_float(hi));
}
__device__ __forceinline__ void mma_tf32(
    float& d0, float& d1, float& d2, float& d3,
    unsigned a0, unsigned a1, unsigned a2, unsigned a3,
    unsigned b0, unsigned b1)
{
    asm("mma.sync.aligned.m16n8k8.row.col.f32.tf32.tf32.f32 "
        "{%0,%1,%2,%3}, {%4,%5,%6,%7}, {%8,%9}, {%0,%1,%2,%3};"
        : "+f"(d0), "+f"(d1), "+f"(d2), "+f"(d3)
        : "r"(a0), "r"(a1), "r"(a2), "r"(a3), "r"(b0), "r"(b1));
}

// ---------------- 2-vertex shared helpers ----------------
template<bool BN>
__device__ __forceinline__ void stream_epi_fw2(
    ull acc0[16], ull acc1[16],
    const float* __restrict__ sscale, const float* __restrict__ sshift,
    const float (*__restrict__ sWfw)[NC], const float* __restrict__ sbfw,
    float* __restrict__ ob, ull facc0[12], ull facc1[12])
{
    #pragma unroll
    for (int j = 0; j < 12; j++) {
        float2 bb = *(const float2*)&sbfw[2 * j];
        ull p = pk2(bb.x, bb.y);
        facc0[j] = p; facc1[j] = p;
    }
    #pragma unroll
    for (int j2 = 0; j2 < 16; j2++) {
        float2 z0 = up2(acc0[j2]), z1 = up2(acc1[j2]);
        float a00 = tanh_fast(z0.x), a01 = tanh_fast(z0.y);
        float a10 = tanh_fast(z1.x), a11 = tanh_fast(z1.y);
        if (BN) {
            float sc0 = sscale[2 * j2], sh0 = sshift[2 * j2];
            float sc1 = sscale[2 * j2 + 1], sh1 = sshift[2 * j2 + 1];
            a00 = a00 * sc0 + sh0; a10 = a10 * sc0 + sh0;
            a01 = a01 * sc1 + sh1; a11 = a11 * sc1 + sh1;
        }
        *(float2*)(ob + (size_t)(2 * j2) * NV)     = make_float2(a00, a10);
        *(float2*)(ob + (size_t)(2 * j2 + 1) * NV) = make_float2(a01, a11);
        ull d00 = dup2(a00), d01 = dup2(a01), d10 = dup2(a10), d11 = dup2(a11);
        #pragma unroll
        for (int g6 = 0; g6 < 6; g6++) {
            F4U w0; w0.f = *(const float4*)&sWfw[2 * j2][g6 * 4];
            F4U w1; w1.f = *(const float4*)&sWfw[2 * j2 + 1][g6 * 4];
            fma2(facc0[2 * g6],     d00, w0.u[0]); fma2(facc0[2 * g6 + 1], d00, w0.u[1]);
            fma2(facc0[2 * g6],     d01, w1.u[0]); fma2(facc0[2 * g6 + 1], d01, w1.u[1]);
            fma2(facc1[2 * g6],     d10, w0.u[0]); fma2(facc1[2 * g6 + 1], d10, w0.u[1]);
            fma2(facc1[2 * g6],     d11, w1.u[0]); fma2(facc1[2 * g6 + 1], d11, w1.u[1]);
        }
    }
}

__device__ __forceinline__ void fw_finish2(
    ull facc0[12], ull facc1[12], float (*__restrict__ sbuf)[HALF_V], int tid,
    float* __restrict__ gw)
{
    #pragma unroll
    for (int j = 0; j < 10; j++) {
        float2 f0 = up2(facc0[j]), f1 = up2(facc1[j]);
        *(float2*)&sbuf[2 * j][2 * tid]     = make_float2(f0.x, f1.x);
        *(float2*)&sbuf[2 * j + 1][2 * tid] = make_float2(f0.y, f1.y);
    }
    float2 p0 = up2(facc0[10]), q0 = up2(facc0[11]);
    float2 p1 = up2(facc1[10]), q1 = up2(facc1[11]);
    float w0a = __expf(-fabsf(p0.x)), w0b = __expf(-fabsf(p0.y));
    float w0c = __expf(-fabsf(q0.x)), w0d = __expf(-fabsf(q0.y));
    float w1a = __expf(-fabsf(p1.x)), w1b = __expf(-fabsf(p1.y));
    float w1c = __expf(-fabsf(q1.x)), w1d = __expf(-fabsf(q1.y));
    *(float2*)&sbuf[20][2 * tid] = make_float2(w0a, w1a);
    *(float2*)&sbuf[21][2 * tid] = make_float2(w0b, w1b);
    *(float2*)&sbuf[22][2 * tid] = make_float2(w0c, w1c);
    *(float2*)&sbuf[23][2 * tid] = make_float2(w0d, w1d);
    *(float2*)(gw)                    = make_float2(w0a, w1a);
    *(float2*)(gw + (size_t)NV)       = make_float2(w0b, w1b);
    *(float2*)(gw + (size_t)2 * NV)   = make_float2(w0c, w1c);
    *(float2*)(gw + (size_t)3 * NV)   = make_float2(w0d, w1d);
}

// 96 max/sum tasks over 512 vertices; warp w -> aa = w>>1, c = (w&1)*12..+12
__device__ __forceinline__ void reduce96_2(
    const float (*__restrict__ sbuf)[HALF_V], int b, int half, int warp, int lane,
    int pb)
{
    const int aa = warp >> 1, cbase = (warp & 1) * 12;
    ull s2[12]; float m0[12], m1[12];
    #pragma unroll
    for (int c = 0; c < 12; c++) { s2[c] = 0ull; m0[c] = -CUDART_INF_F; m1[c] = -CUDART_INF_F; }
    #pragma unroll
    for (int i = 0; i < 8; i++) {
        const int vv = (lane + i * 32) * 2;
        ull w2 = *(const ull*)&sbuf[NP + aa][vv];
        #pragma unroll
        for (int c = 0; c < 12; c++) {
            ull f2 = *(const ull*)&sbuf[cbase + c][vv];
            ull p = mul2(w2, f2);
            s2[c] = add2(s2[c], p);
            float2 pv = up2(p);
            m0[c] = fmaxf(m0[c], pv.x);
            m1[c] = fmaxf(m1[c], pv.y);
        }
    }
    #pragma unroll
    for (int c = 0; c < 12; c++) {
        float m = fmaxf(m0[c], m1[c]);
        float2 sv = up2(s2[c]);
        float s = sv.x + sv.y;
        #pragma unroll
        for (int o = 16; o > 0; o >>= 1) {
            m = fmaxf(m, __shfl_xor_sync(~0u, m, o));
            s += __shfl_xor_sync(~0u, s, o);
        }
        if (lane == 0) {
            const int t = aa * 24 + cbase + c;
            g_pmax[pb][(b * 96 + t) * 2 + half] = m;
            g_psum[pb][(b * 96 + t) * 2 + half] = s;
        }
    }
}

// =====================================================================
// kB_fw: event mean (computed in-CTA) + h0 = tanh(bn0(x)@W_in + cbias)
// -> slot 0, fused fw(block 0). grid 256 (b=blk>>1, half=blk&1), 256 thr
// =====================================================================
struct __align__(16) SmemB {
    float sbuf[NC][HALF_V];
    float sW[NFEAT][NF];
    float sWfw[NF][NC];
    float scb[NF];
    float ss0[20], st0[20];
    float sbfw[NC];
    float sp[8][12];
    float smean[12];
};

__global__ __launch_bounds__(256, 2)
void kB_fw(const float* __restrict__ x,
           const float* __restrict__ bn0_gamma, const float* __restrict__ bn0_var,
           const float* __restrict__ bn0_beta,  const float* __restrict__ bn0_mean,
           const float* __restrict__ W_in,      const float* __restrict__ b_in,
           const float* __restrict__ W_flr, const float* __restrict__ b_flr,
           const float* __restrict__ W_s,   const float* __restrict__ b_s)
{
    extern __shared__ char smraw[];
    SmemB& S = *reinterpret_cast<SmemB*>(smraw);
    const int tid = threadIdx.x;
    const int b = blockIdx.x >> 1, half = blockIdx.x & 1;
    const int v0 = half * HALF_V + tid * 2;
    const int warp = tid >> 5, lane = tid & 31;

    // per-event vertex mean (each CTA computes it for its event; cheap)
    {
        float s[NFEAT];
        #pragma unroll
        for (int c = 0; c < NFEAT; c++) s[c] = 0.0f;
        #pragma unroll
        for (int i = 0; i < 4; i++) {
            const float* xv = x + ((size_t)b * NV + tid + i * 256) * NFEAT;
            #pragma unroll
            for (int c = 0; c < NFEAT; c++) s[c] += xv[c];
        }
        #pragma unroll
        for (int o = 16; o > 0; o >>= 1)
            #pragma unroll
            for (int c = 0; c < NFEAT; c++) s[c] += __shfl_xor_sync(~0u, s[c], o);
        if (lane == 0)
            #pragma unroll
            for (int c = 0; c < NFEAT; c++) S.sp[warp][c] = s[c];
    }

    const float* xv0 = x + ((size_t)b * NV + v0) * NFEAT;
    float xr0[NFEAT], xr1[NFEAT];
    #pragma unroll
    for (int c = 0; c < NFEAT; c++) { xr0[c] = xv0[c]; xr1[c] = xv0[NFEAT + c]; }

    for (int i = tid; i < NFEAT * NF; i += 256) S.sW[i / NF][i % NF] = W_in[i];
    for (int i = tid; i < NF * NC; i += 256) {
        int k = i / NC, c = i % NC;
        S.sWfw[k][c] = (c < NP) ? W_flr[(size_t)k * NP + c] : W_s[(size_t)k * NA + (c - NP)];
    }
    if (tid >= 32 && tid < 52) {
        int c = tid - 32;
        float sc = bn0_gamma[c] * rsqrtf(bn0_var[c] + 1e-3f);
        S.ss0[c] = sc;
        S.st0[c] = bn0_beta[c] - bn0_mean[c] * sc;
    }
    if (tid >= 64 && tid < 64 + NC)
        S.sbfw[tid - 64] = (tid - 64 < NP) ? b_flr[tid - 64] : b_s[tid - 64 - NP];
    __syncthreads();
    if (tid < NFEAT) {
        float a = 0.0f;
        #pragma unroll
        for (int w = 0; w < 8; w++) a += S.sp[w][tid];
        S.smean[tid] = a * (1.0f / 1024.0f);
    }
    __syncthreads();
    if (tid < NF) {   // fold mean-half of gex + b_in into per-event constant bias
        float a = b_in[tid];
        #pragma unroll
        for (int c = 10; c < 20; c++) {
            float g = S.smean[c - 10] * S.ss0[c] + S.st0[c];
            a += g * W_in[c * NF + tid];
        }
        S.scb[tid] = a;
    }
    __syncthreads();

    ull acc0[16], acc1[16];
    #pragma unroll
    for (int j = 0; j < 16; j++) {
        float2 bb = *(const float2*)&S.scb[2 * j];
        ull p = pk2(bb.x, bb.y);
        acc0[j] = p; acc1[j] = p;
    }
    #pragma unroll
    for (int c = 0; c < NFEAT; c++) {
        float sc = S.ss0[c], sh = S.st0[c];
        ull g0 = dup2(xr0[c] * sc + sh);
        ull g1 = dup2(xr1[c] * sc + sh);
        #pragma unroll
        for (int g8 = 0; g8 < 8; g8++) {
            F4U w; w.f = *(const float4*)&S.sW[c][g8 * 4];
            fma2(acc0[g8 * 2],     g0, w.u[0]); fma2(acc0[g8 * 2 + 1], g0, w.u[1]);
            fma2(acc1[g8 * 2],     g1, w.u[0]); fma2(acc1[g8 * 2 + 1], g1, w.u[1]);
        }
    }
    float* ob = g_h + (size_t)b * 384 * NV + v0;
    ull facc0[12], facc1[12];
    stream_epi_fw2<false>(acc0, acc1, nullptr, nullptr, S.sWfw, S.sbfw, ob, facc0, facc1);
    fw_finish2(facc0, facc1, S.sbuf, tid, g_w + ((size_t)b * NA) * NV + v0);
    __syncthreads();
    reduce96_2(S.sbuf, b, half, warp, lane, 0);
}

// =====================================================================
// F: fused block: Gp(l) -> out(l) -> h_{l+1} -> fw(l+1) -> partials
// =====================================================================
struct __align__(16) SmemF {
    float sbuf[NC][HALF_V];
    float sWo32[NF][NF];
    float sWfw[NF][NC];
    float sGp[NA][NF];
    float sam[96], sas[96];
    float sbfw[NC];
    float sbo[NF], sscale[NF], sshift[NF];
};

__global__ __launch_bounds__(256, 2)
void F_block(int l,
             const float* __restrict__ W_out,    const float* __restrict__ b_out,
             const float* __restrict__ bn_gamma, const float* __restrict__ bn_beta,
             const float* __restrict__ bn_mean,  const float* __restrict__ bn_var,
             const float* __restrict__ W_flr,    const float* __restrict__ b_flr,
             const float* __restrict__ W_s,      const float* __restrict__ b_s)
{
    extern __shared__ char smraw[];
    SmemF& S = *reinterpret_cast<SmemF*>(smraw);
    const int tid = threadIdx.x;
    const int b = blockIdx.x >> 1, half = blockIdx.x & 1;
    const int v0 = half * HALF_V + tid * 2;
    const int warp = tid >> 5, lane = tid & 31;
    const int pb = l & 1, lf = l + 1;

    const float* hb = g_h + ((size_t)b * 384 + (size_t)l * NF) * NV + v0;
    float2 wv[NA];
    #pragma unroll
    for (int a = 0; a < NA; a++)
        wv[a] = *(const float2*)(g_w + ((size_t)b * NA + a) * NV + v0);

    const float* WoG = W_out + (size_t)l * 228 * NF;
    ((float4*)&S.sWo32[0][0])[tid] = ((const float4*)WoG)[tid];   // 256 float4 = 32x32
    for (int i = tid; i < NF * NC; i += 256) {
        int k = i / NC, c = i % NC;
        S.sWfw[k][c] = (c < NP) ? W_flr[((size_t)lf * NF + k) * NP + c]
                                : W_s[((size_t)lf * NF + k) * NA + (c - NP)];
    }
    if (tid < 96) {
        float2 pm = *(const float2*)&g_pmax[pb][(b * 96 + tid) * 2];
        float2 ps = *(const float2*)&g_psum[pb][(b * 96 + tid) * 2];
        S.sam[tid] = fmaxf(pm.x, pm.y);
        S.sas[tid] = (ps.x + ps.y) * (1.0f / 1024.0f);
    }
    if (tid >= 128 && tid < 160) {
        int j = tid - 128;
        S.sbo[j] = b_out[l * NF + j];
        float sc = bn_gamma[l * NF + j] * rsqrtf(bn_var[l * NF + j] + 1e-3f);
        S.sscale[j] = sc;
        S.sshift[j] = bn_beta[l * NF + j] - bn_mean[l * NF + j] * sc;
    }
    if (tid >= 160 && tid < 160 + NC)
        S.sbfw[tid - 160] = (tid - 160 < NP) ? b_flr[lf * NP + tid - 160]
                                             : b_s[lf * NA + tid - 160 - NP];
    __syncthreads();

    if (tid < 128) {
        const int aa = warp, j = lane;
        float g = WoG[(224 + aa) * NF + j];
        #pragma unroll
        for (int c = 0; c < NC; c++)
            g += S.sam[aa * NC + c] * WoG[(32 + aa * 48 + c) * NF + j];
        #pragma unroll
        for (int c = 0; c < NC; c++)
            g += S.sas[aa * NC + c] * WoG[(32 + aa * 48 + NC + c) * NF + j];
        S.sGp[aa][j] = g;
    }
    __syncthreads();

    ull acc0[16], acc1[16];
    #pragma unroll
    for (int j = 0; j < 16; j++) {
        float2 bb = *(const float2*)&S.sbo[2 * j];
        ull p = pk2(bb.x, bb.y);
        acc0[j] = p; acc1[j] = p;
    }
    #pragma unroll
    for (int kc = 0; kc < 4; kc++) {
        float2 h2[8];
        #pragma unroll
        for (int k = 0; k < 8; k++)
            h2[k] = *(const float2*)(hb + (size_t)(kc * 8 + k) * NV);
        #pragma unroll
        for (int k = 0; k < 8; k++) {
            ull hk0 = dup2(h2[k].x), hk1 = dup2(h2[k].y);
            #pragma unroll
            for (int g8 = 0; g8 < 8; g8++) {
                F4U w; w.f = *(const float4*)&S.sWo32[kc * 8 + k][g8 * 4];
                fma2(acc0[g8 * 2],     hk0, w.u[0]); fma2(acc0[g8 * 2 + 1], hk0, w.u[1]);
                fma2(acc1[g8 * 2],     hk1, w.u[0]); fma2(acc1[g8 * 2 + 1], hk1, w.u[1]);
            }
        }
    }
    #pragma unroll
    for (int a = 0; a < NA; a++) {
        ull wa0 = dup2(wv[a].x), wa1 = dup2(wv[a].y);
        #pragma unroll
        for (int g8 = 0; g8 < 8; g8++) {
            F4U gg; gg.f = *(const float4*)&S.sGp[a][g8 * 4];
            fma2(acc0[g8 * 2],     wa0, gg.u[0]); fma2(acc0[g8 * 2 + 1], wa0, gg.u[1]);
            fma2(acc1[g8 * 2],     wa1, gg.u[0]); fma2(acc1[g8 * 2 + 1], wa1, gg.u[1]);
        }
    }

    float* ob = g_h + ((size_t)b * 384 + (size_t)lf * NF) * NV + v0;
    ull facc0[12], facc1[12];
    stream_epi_fw2<true>(acc0, acc1, S.sscale, S.sshift, S.sWfw, S.sbfw, ob, facc0, facc1);
    fw_finish2(facc0, facc1, S.sbuf, tid, g_w + ((size_t)b * NA) * NV + v0);
    __syncthreads();
    reduce96_2(S.sbuf, b, half, warp, lane, pb ^ 1);
}

// =====================================================================
// G: final block (l=10): out only. writes slot 11
// =====================================================================
__global__ __launch_bounds__(256, 2)
void G_block(const float* __restrict__ W_out,    const float* __restrict__ b_out,
             const float* __restrict__ bn_gamma, const float* __restrict__ bn_beta,
             const float* __restrict__ bn_mean,  const float* __restrict__ bn_var)
{
    __shared__ float sWo32[NF][NF];
    __shared__ float sGp[NA][NF];
    __shared__ float sam[96], sas[96];
    __shared__ float sbo[NF], sscale[NF], sshift[NF];
    const int tid = threadIdx.x;
    const int b = blockIdx.x >> 1, half = blockIdx.x & 1;
    const int v0 = half * HALF_V + tid * 2;
    const int warp = tid >> 5, lane = tid & 31;
    const int l = 10, pb = 0;

    const float* hb = g_h + ((size_t)b * 384 + (size_t)l * NF) * NV + v0;
    float2 wv[NA];
    #pragma unroll
    for (int a = 0; a < NA; a++)
        wv[a] = *(const float2*)(g_w + ((size_t)b * NA + a) * NV + v0);

    const float* WoG = W_out + (size_t)l * 228 * NF;
    ((float4*)&sWo32[0][0])[tid] = ((const float4*)WoG)[tid];
    if (tid < 96) {
        float2 pm = *(const float2*)&g_pmax[pb][(b * 96 + tid) * 2];
        float2 ps = *(const float2*)&g_psum[pb][(b * 96 + tid) * 2];
        sam[tid] = fmaxf(pm.x, pm.y);
        sas[tid] = (ps.x + ps.y) * (1.0f / 1024.0f);
    }
    if (tid >= 128 && tid < 160) {
        int j = tid - 128;
        sbo[j] = b_out[l * NF + j];
        float sc = bn_gamma[l * NF + j] * rsqrtf(bn_var[l * NF + j] + 1e-3f);
        sscale[j] = sc;
        sshift[j] = bn_beta[l * NF + j] - bn_mean[l * NF + j] * sc;
    }
    __syncthreads();
    if (tid < 128) {
        const int aa = warp, j = lane;
        float g = WoG[(224 + aa) * NF + j];
        #pragma unroll
        for (int c = 0; c < NC; c++)
            g += sam[aa * NC + c] * WoG[(32 + aa * 48 + c) * NF + j];
        #pragma unroll
        for (int c = 0; c < NC; c++)
            g += sas[aa * NC + c] * WoG[(32 + aa * 48 + NC + c) * NF + j];
        sGp[aa][j] = g;
    }
    __syncthreads();

    ull acc0[16], acc1[16];
    #pragma unroll
    for (int j = 0; j < 16; j++) {
        float2 bb = *(const float2*)&sbo[2 * j];
        ull p = pk2(bb.x, bb.y);
        acc0[j] = p; acc1[j] = p;
    }
    #pragma unroll
    for (int kc = 0; kc < 4; kc++) {
        float2 h2[8];
        #pragma unroll
        for (int k = 0; k < 8; k++)
            h2[k] = *(const float2*)(hb + (size_t)(kc * 8 + k) * NV);
        #pragma unroll
        for (int k = 0; k < 8; k++) {
            ull hk0 = dup2(h2[k].x), hk1 = dup2(h2[k].y);
            #pragma unroll
            for (int g8 = 0; g8 < 8; g8++) {
                F4U w; w.f = *(const float4*)&sWo32[kc * 8 + k][g8 * 4];
                fma2(acc0[g8 * 2],     hk0, w.u[0]); fma2(acc0[g8 * 2 + 1], hk0, w.u[1]);
                fma2(acc1[g8 * 2],     hk1, w.u[0]); fma2(acc1[g8 * 2 + 1], hk1, w.u[1]);
            }
        }
    }
    #pragma unroll
    for (int a = 0; a < NA; a++) {
        ull wa0 = dup2(wv[a].x), wa1 = dup2(wv[a].y);
        #pragma unroll
        for (int g8 = 0; g8 < 8; g8++) {
            F4U gg; gg.f = *(const float4*)&sGp[a][g8 * 4];
            fma2(acc0[g8 * 2],     wa0, gg.u[0]); fma2(acc0[g8 * 2 + 1], wa0, gg.u[1]);
            fma2(acc1[g8 * 2],     wa1, gg.u[0]); fma2(acc1[g8 * 2 + 1], wa1, gg.u[1]);
        }
    }
    float* ob = g_h + ((size_t)b * 384 + (size_t)11 * NF) * NV + v0;
    #pragma unroll
    for (int j2 = 0; j2 < 16; j2++) {
        float2 z0 = up2(acc0[j2]), z1 = up2(acc1[j2]);
        float sc0 = sscale[2 * j2], sh0 = sshift[2 * j2];
        float sc1 = sscale[2 * j2 + 1], sh1 = sshift[2 * j2 + 1];
        *(float2*)(ob + (size_t)(2 * j2) * NV) =
            make_float2(tanh_fast(z0.x) * sc0 + sh0, tanh_fast(z1.x) * sc0 + sh0);
        *(float2*)(ob + (size_t)(2 * j2 + 1) * NV) =
            make_float2(tanh_fast(z0.y) * sc1 + sh1, tanh_fast(z1.y) * sc1 + sh1);
    }
}

// =====================================================================
// k2_tc: out = relu(relu(F @ W_o0 + b0) @ W_o1 + b1) via 3xTF32 mma.sync
// (split-precision: A*B = Ahi*Bhi + Alo*Bhi + Ahi*Blo; tf32-error ~1e-6).
// F = g_h slots 1..11: logical A[v][k], stored [k][v] (v contiguous).
// grid 512 (b=blk>>2, chunk=blk&3): CTA = 256 vertices, 8 warps.
// Each warp: M=32 (two m16 tiles), N=48, K=352. B hi+lo frags in smem.
// =====================================================================
#define NKT 44              // 352 / 8
#define NNT 6               // 48 / 8
#define BPK (NNT * NKT * 32)  // 8448 frag pairs

struct __align__(16) SmemK2T {
    float bph[BPK * 2];     // packed tf32 B hi-frags
    float bpl[BPK * 2];     // packed tf32 B lo-frags
    float sW1[144];
    float sb0[48];
    float sb1[4];
};

__global__ __launch_bounds__(256, 1)
void k2_tc(const float* __restrict__ W_o0, const float* __restrict__ b_o0,
           const float* __restrict__ W_o1, const float* __restrict__ b_o1,
           float* __restrict__ out)
{
    extern __shared__ char smraw[];
    SmemK2T& S = *reinterpret_cast<SmemK2T*>(smraw);
    const int tid = threadIdx.x;
    const int lane = tid & 31, warp = tid >> 5;
    const int gr = lane >> 2, gc = lane & 3;   // frag row/col indices

    // stage packed B frags: hi + lo residual
    for (int i = tid; i < BPK; i += 256) {
        int ln = i & 31, rest = i >> 5;
        int kt = rest % NKT, nt = rest / NKT;
        int c = ln & 3, r = ln >> 2;
        int k0 = kt * 8, n0 = nt * 8;
        float w0 = W_o0[(k0 + c) * 48 + n0 + r];
        float w1 = W_o0[(k0 + c + 4) * 48 + n0 + r];
        unsigned h0, l0, h1, l1;
        split_tf32(w0, h0, l0);
        split_tf32(w1, h1, l1);
        *(uint2*)&S.bph[2 * i] = make_uint2(h0, h1);
        *(uint2*)&S.bpl[2 * i] = make_uint2(l0, l1);
    }
    if (tid < 144) S.sW1[tid] = W_o1[tid];
    if (tid >= 160 && tid < 208) S.sb0[tid - 160] = b_o0[tid - 160];
    if (tid >= 208 && tid < 211) S.sb1[tid - 208] = b_o1[tid - 208];
    __syncthreads();

    const int b = blockIdx.x >> 2, chunk = blockIdx.x & 3;
    const int vb = chunk * 256 + warp * 32;          // 32 vertices per warp
    const float* fb = g_h + ((size_t)b * 384 + NF) * NV;

    float d[2][NNT][4];
    #pragma unroll
    for (int t = 0; t < 2; t++)
        #pragma unroll
        for (int nt = 0; nt < NNT; nt++)
            #pragma unroll
            for (int q = 0; q < 4; q++) d[t][nt][q] = 0.0f;

    #pragma unroll 2
    for (int kt = 0; kt < NKT; kt++) {
        const int k0 = kt * 8;
        unsigned ah[2][4], al[2][4];
        #pragma unroll
        for (int t = 0; t < 2; t++) {
            const float* base = fb + (size_t)(k0 + gc) * NV + vb + t * 16 + gr;
            float f0 = base[0];
            float f1 = base[8];
            float f2 = base[(size_t)4 * NV];
            float f3 = base[(size_t)4 * NV + 8];
            split_tf32(f0, ah[t][0], al[t][0]);
            split_tf32(f1, ah[t][1], al[t][1]);
            split_tf32(f2, ah[t][2], al[t][2]);
            split_tf32(f3, ah[t][3], al[t][3]);
        }
        #pragma unroll
        for (int nt = 0; nt < NNT; nt++) {
            const int fi = 2 * ((nt * NKT + kt) * 32 + lane);
            uint2 bh = *(const uint2*)&S.bph[fi];
            uint2 bl = *(const uint2*)&S.bpl[fi];
            #pragma unroll
            for (int t = 0; t < 2; t++) {
                mma_tf32(d[t][nt][0], d[t][nt][1], d[t][nt][2], d[t][nt][3],
                         ah[t][0], ah[t][1], ah[t][2], ah[t][3], bh.x, bh.y);
                mma_tf32(d[t][nt][0], d[t][nt][1], d[t][nt][2], d[t][nt][3],
                         al[t][0], al[t][1], al[t][2], al[t][3], bh.x, bh.y);
                mma_tf32(d[t][nt][0], d[t][nt][1], d[t][nt][2], d[t][nt][3],
                         ah[t][0], ah[t][1], ah[t][2], ah[t][3], bl.x, bl.y);
            }
        }
    }

    // epilogue: bias + relu + second layer (48 -> 3) + quad reduce
    #pragma unroll
    for (int t = 0; t < 2; t++) {
        float o0a = 0.0f, o1a = 0.0f, o2a = 0.0f;   // row gr
        float o0b = 0.0f, o1b = 0.0f, o2b = 0.0f;   // row gr+8
        #pragma unroll
        for (int nt = 0; nt < NNT; nt++) {
            const int n = nt * 8 + 2 * gc;
            float2 bb = *(const float2*)&S.sb0[n];
            float h0 = fmaxf(d[t][nt][0] + bb.x, 0.0f);
            float h1 = fmaxf(d[t][nt][1] + bb.y, 0.0f);
            float h2 = fmaxf(d[t][nt][2] + bb.x, 0.0f);
            float h3 = fmaxf(d[t][nt][3] + bb.y, 0.0f);
            const float* w1a = &S.sW1[n * 3];       // W1[n][0..2], W1[n+1][0..2]
            o0a += h0 * w1a[0] + h1 * w1a[3];
            o1a += h0 * w1a[1] + h1 * w1a[4];
            o2a += h0 * w1a[2] + h1 * w1a[5];
            o0b += h2 * w1a[0] + h3 * w1a[3];
            o1b += h2 * w1a[1] + h3 * w1a[4];
            o2b += h2 * w1a[2] + h3 * w1a[5];
        }
        #pragma unroll
        for (int o = 1; o <= 2; o <<= 1) {
            o0a += __shfl_xor_sync(~0u, o0a, o); o1a += __shfl_xor_sync(~0u, o1a, o);
            o2a += __shfl_xor_sync(~0u, o2a, o); o0b += __shfl_xor_sync(~0u, o0b, o);
            o1b += __shfl_xor_sync(~0u, o1b, o); o2b += __shfl_xor_sync(~0u, o2b, o);
        }
        if (gc == 0) {
            const int va = b * NV + vb + t * 16 + gr;
            float* opa = out + (size_t)va * 3;
            opa[0] = fmaxf(o0a + S.sb1[0], 0.0f);
            opa[1] = fmaxf(o1a + S.sb1[1], 0.0f);
            opa[2] = fmaxf(o2a + S.sb1[2], 0.0f);
            float* opb = out + (size_t)(va + 8) * 3;
            opb[0] = fmaxf(o0b + S.sb1[0], 0.0f);
            opb[1] = fmaxf(o1b + S.sb1[1], 0.0f);
            opb[2] = fmaxf(o2b + S.sb1[2], 0.0f);
        }
    }
}

// =====================================================================
extern "C" void kernel_launch(void* const* d_in, const int* in_sizes, int n_in,
                              void* d_out, int out_size)
{
    const float* x         = (const float*)d_in[0];
    const float* bn0_gamma = (const float*)d_in[1];
    const float* bn0_beta  = (const float*)d_in[2];
    const float* bn0_mean  = (const float*)d_in[3];
    const float* bn0_var   = (const float*)d_in[4];
    const float* W_in      = (const float*)d_in[5];
    const float* b_in      = (const float*)d_in[6];
    const float* W_flr     = (const float*)d_in[7];
    const float* b_flr     = (const float*)d_in[8];
    const float* W_s       = (const float*)d_in[9];
    const float* b_s       = (const float*)d_in[10];
    const float* W_out     = (const float*)d_in[11];
    const float* b_out     = (const float*)d_in[12];
    const float* bn_gamma  = (const float*)d_in[13];
    const float* bn_beta   = (const float*)d_in[14];
    const float* bn_mean   = (const float*)d_in[15];
    const float* bn_var    = (const float*)d_in[16];
    const float* W_o0      = (const float*)d_in[17];
    const float* b_o0      = (const float*)d_in[18];
    const float* W_o1      = (const float*)d_in[19];
    const float* b_o1      = (const float*)d_in[20];

    cudaFuncSetAttribute(kB_fw, cudaFuncAttributeMaxDynamicSharedMemorySize,
                         (int)sizeof(SmemB));
    cudaFuncSetAttribute(F_block, cudaFuncAttributeMaxDynamicSharedMemorySize,
                         (int)sizeof(SmemF));
    cudaFuncSetAttribute(k2_tc, cudaFuncAttributeMaxDynamicSharedMemorySize,
                         (int)sizeof(SmemK2T));

    kB_fw<<<NB * 2, 256, sizeof(SmemB)>>>(x, bn0_gamma, bn0_var, bn0_beta, bn0_mean,
                                          W_in, b_in, W_flr, b_flr, W_s, b_s);

    for (int l = 0; l < NBK - 1; l++) {
        F_block<<<NB * 2, 256, sizeof(SmemF)>>>(l, W_out, b_out, bn_gamma, bn_beta,
                                                bn_mean, bn_var, W_flr, b_flr, W_s, b_s);
    }
    G_block<<<NB * 2, 256>>>(W_out, b_out, bn_gamma, bn_beta, bn_mean, bn_var);

    k2_tc<<<NB * 4, 256, sizeof(SmemK2T)>>>(
        W_o0, b_o0, W_o1, b_o1, (float*)d_out);
}

// round 13
// speedup vs baseline: 1.3665x; 1.0803x over previous
#include <cuda_runtime.h>
#include <math_constants.h>
#include <cstdint>
#include <cstddef>

// ---------------- problem constants ----------------
#define NB    128
#define NV    1024
#define NFEAT 10
#define NBK   11
#define NF    32
#define NP    20
#define NA    4
#define NC    24
#define DFE   352   // NBK*NF
#define HALF_V 512

// h ring: slot 0 = h0, slot l+1 = output of block l. layout g_h[b][s*32+k][v]
__device__ float g_h[(size_t)NB * 384 * NV];     // 201 MB
__device__ float g_w[(size_t)NB * NA * NV];      // per-block edge weights
__device__ float g_pmax[2][NB * 96 * 2];         // double-buffered partial max
__device__ float g_psum[2][NB * 96 * 2];         // double-buffered partial sum

// ---------------- PDL helpers ----------------
__device__ __forceinline__ void pdl_trigger() {
#if defined(__CUDA_ARCH__) && __CUDA_ARCH__ >= 900
    cudaTriggerProgrammaticLaunchCompletion();
#endif
}
__device__ __forceinline__ void pdl_wait() {
#if defined(__CUDA_ARCH__) && __CUDA_ARCH__ >= 900
    cudaGridDependencySynchronize();
#endif
}

// ---------------- f32x2 packed-math helpers ----------------
typedef unsigned long long ull;
__device__ __forceinline__ ull pk2(float a, float b) {
    ull r; asm("mov.b64 %0, {%1, %2};" : "=l"(r) : "f"(a), "f"(b)); return r;
}
__device__ __forceinline__ ull dup2(float a) { return pk2(a, a); }
__device__ __forceinline__ void fma2(ull& d, ull a, ull b) {
    asm("fma.rn.f32x2 %0, %1, %2, %0;" : "+l"(d) : "l"(a), "l"(b));
}
__device__ __forceinline__ ull mul2(ull a, ull b) {
    ull r; asm("mul.rn.f32x2 %0, %1, %2;" : "=l"(r) : "l"(a), "l"(b)); return r;
}
__device__ __forceinline__ ull add2(ull a, ull b) {
    ull r; asm("add.rn.f32x2 %0, %1, %2;" : "=l"(r) : "l"(a), "l"(b)); return r;
}
__device__ __forceinline__ float2 up2(ull v) {
    float2 r; asm("mov.b64 {%0, %1}, %2;" : "=f"(r.x), "=f"(r.y) : "l"(v)); return r;
}
union F4U { float4 f; ull u[2]; };

__device__ __forceinline__ float tanh_fast(float x) {
    float r; asm("tanh.approx.f32 %0, %1;" : "=f"(r) : "f"(x)); return r;
}
__device__ __forceinline__ unsigned to_tf32(float x) {
    unsigned r; asm("cvt.rna.tf32.f32 %0, %1;" : "=r"(r) : "f"(x)); return r;
}
__device__ __forceinline__ void split_tf32(float x, unsigned& hi, unsigned& lo) {
    hi = to_tf32(x);
    lo = to_tf32(x - __uint_as_float(hi));
}
__device__ __forceinline__ void mma_tf32(
    float& d0, float& d1, float& d2, float& d3,
    unsigned a0, unsigned a1, unsigned a2, unsigned a3,
    unsigned b0, unsigned b1)
{
    asm("mma.sync.aligned.m16n8k8.row.col.f32.tf32.tf32.f32 "
        "{%0,%1,%2,%3}, {%4,%5,%6,%7}, {%8,%9}, {%0,%1,%2,%3};"
        : "+f"(d0), "+f"(d1), "+f"(d2), "+f"(d3)
        : "r"(a0), "r"(a1), "r"(a2), "r"(a3), "r"(b0), "r"(b1));
}

// ---------------- 2-vertex shared helpers ----------------
template<bool BN>
__device__ __forceinline__ void stream_epi_fw2(
    ull acc0[16], ull acc1[16],
    const float* __restrict__ sscale, const float* __restrict__ sshift,
    const float (*__restrict__ sWfw)[NC], const float* __restrict__ sbfw,
    float* __restrict__ ob, ull facc0[12], ull facc1[12])
{
    #pragma unroll
    for (int j = 0; j < 12; j++) {
        float2 bb = *(const float2*)&sbfw[2 * j];
        ull p = pk2(bb.x, bb.y);
        facc0[j] = p; facc1[j] = p;
    }
    #pragma unroll
    for (int j2 = 0; j2 < 16; j2++) {
        float2 z0 = up2(acc0[j2]), z1 = up2(acc1[j2]);
        float a00 = tanh_fast(z0.x), a01 = tanh_fast(z0.y);
        float a10 = tanh_fast(z1.x), a11 = tanh_fast(z1.y);
        if (BN) {
            float sc0 = sscale[2 * j2], sh0 = sshift[2 * j2];
            float sc1 = sscale[2 * j2 + 1], sh1 = sshift[2 * j2 + 1];
            a00 = a00 * sc0 + sh0; a10 = a10 * sc0 + sh0;
            a01 = a01 * sc1 + sh1; a11 = a11 * sc1 + sh1;
        }
        *(float2*)(ob + (size_t)(2 * j2) * NV)     = make_float2(a00, a10);
        *(float2*)(ob + (size_t)(2 * j2 + 1) * NV) = make_float2(a01, a11);
        ull d00 = dup2(a00), d01 = dup2(a01), d10 = dup2(a10), d11 = dup2(a11);
        #pragma unroll
        for (int g6 = 0; g6 < 6; g6++) {
            F4U w0; w0.f = *(const float4*)&sWfw[2 * j2][g6 * 4];
            F4U w1; w1.f = *(const float4*)&sWfw[2 * j2 + 1][g6 * 4];
            fma2(facc0[2 * g6],     d00, w0.u[0]); fma2(facc0[2 * g6 + 1], d00, w0.u[1]);
            fma2(facc0[2 * g6],     d01, w1.u[0]); fma2(facc0[2 * g6 + 1], d01, w1.u[1]);
            fma2(facc1[2 * g6],     d10, w0.u[0]); fma2(facc1[2 * g6 + 1], d10, w0.u[1]);
            fma2(facc1[2 * g6],     d11, w1.u[0]); fma2(facc1[2 * g6 + 1], d11, w1.u[1]);
        }
    }
}

__device__ __forceinline__ void fw_finish2(
    ull facc0[12], ull facc1[12], float (*__restrict__ sbuf)[HALF_V], int tid,
    float* __restrict__ gw)
{
    #pragma unroll
    for (int j = 0; j < 10; j++) {
        float2 f0 = up2(facc0[j]), f1 = up2(facc1[j]);
        *(float2*)&sbuf[2 * j][2 * tid]     = make_float2(f0.x, f1.x);
        *(float2*)&sbuf[2 * j + 1][2 * tid] = make_float2(f0.y, f1.y);
    }
    float2 p0 = up2(facc0[10]), q0 = up2(facc0[11]);
    float2 p1 = up2(facc1[10]), q1 = up2(facc1[11]);
    float w0a = __expf(-fabsf(p0.x)), w0b = __expf(-fabsf(p0.y));
    float w0c = __expf(-fabsf(q0.x)), w0d = __expf(-fabsf(q0.y));
    float w1a = __expf(-fabsf(p1.x)), w1b = __expf(-fabsf(p1.y));
    float w1c = __expf(-fabsf(q1.x)), w1d = __expf(-fabsf(q1.y));
    *(float2*)&sbuf[20][2 * tid] = make_float2(w0a, w1a);
    *(float2*)&sbuf[21][2 * tid] = make_float2(w0b, w1b);
    *(float2*)&sbuf[22][2 * tid] = make_float2(w0c, w1c);
    *(float2*)&sbuf[23][2 * tid] = make_float2(w0d, w1d);
    *(float2*)(gw)                    = make_float2(w0a, w1a);
    *(float2*)(gw + (size_t)NV)       = make_float2(w0b, w1b);
    *(float2*)(gw + (size_t)2 * NV)   = make_float2(w0c, w1c);
    *(float2*)(gw + (size_t)3 * NV)   = make_float2(w0d, w1d);
}

// 96 max/sum tasks over 512 vertices; warp w -> aa = w>>1, c = (w&1)*12..+12
__device__ __forceinline__ void reduce96_2(
    const float (*__restrict__ sbuf)[HALF_V], int b, int half, int warp, int lane,
    int pb)
{
    const int aa = warp >> 1, cbase = (warp & 1) * 12;
    ull s2[12]; float m0[12], m1[12];
    #pragma unroll
    for (int c = 0; c < 12; c++) { s2[c] = 0ull; m0[c] = -CUDART_INF_F; m1[c] = -CUDART_INF_F; }
    #pragma unroll
    for (int i = 0; i < 8; i++) {
        const int vv = (lane + i * 32) * 2;
        ull w2 = *(const ull*)&sbuf[NP + aa][vv];
        #pragma unroll
        for (int c = 0; c < 12; c++) {
            ull f2 = *(const ull*)&sbuf[cbase + c][vv];
            ull p = mul2(w2, f2);
            s2[c] = add2(s2[c], p);
            float2 pv = up2(p);
            m0[c] = fmaxf(m0[c], pv.x);
            m1[c] = fmaxf(m1[c], pv.y);
        }
    }
    #pragma unroll
    for (int c = 0; c < 12; c++) {
        float m = fmaxf(m0[c], m1[c]);
        float2 sv = up2(s2[c]);
        float s = sv.x + sv.y;
        #pragma unroll
        for (int o = 16; o > 0; o >>= 1) {
            m = fmaxf(m, __shfl_xor_sync(~0u, m, o));
            s += __shfl_xor_sync(~0u, s, o);
        }
        if (lane == 0) {
            const int t = aa * 24 + cbase + c;
            g_pmax[pb][(b * 96 + t) * 2 + half] = m;
            g_psum[pb][(b * 96 + t) * 2 + half] = s;
        }
    }
}

// =====================================================================
// kB_fw: event mean (computed in-CTA) + h0 = tanh(bn0(x)@W_in + cbias)
// -> slot 0, fused fw(block 0). grid 256 (b=blk>>1, half=blk&1), 256 thr
// =====================================================================
struct __align__(16) SmemB {
    float sbuf[NC][HALF_V];
    float sW[NFEAT][NF];
    float sWfw[NF][NC];
    float scb[NF];
    float ss0[20], st0[20];
    float sbfw[NC];
    float sp[8][12];
    float smean[12];
};

__global__ __launch_bounds__(256, 2)
void kB_fw(const float* __restrict__ x,
           const float* __restrict__ bn0_gamma, const float* __restrict__ bn0_var,
           const float* __restrict__ bn0_beta,  const float* __restrict__ bn0_mean,
           const float* __restrict__ W_in,      const float* __restrict__ b_in,
           const float* __restrict__ W_flr, const float* __restrict__ b_flr,
           const float* __restrict__ W_s,   const float* __restrict__ b_s)
{
    extern __shared__ char smraw[];
    SmemB& S = *reinterpret_cast<SmemB*>(smraw);
    const int tid = threadIdx.x;
    const int b = blockIdx.x >> 1, half = blockIdx.x & 1;
    const int v0 = half * HALF_V + tid * 2;
    const int warp = tid >> 5, lane = tid & 31;

    pdl_trigger();   // allow F(0) to prelaunch and stage its weights

    // per-event vertex mean (each CTA computes it for its event; cheap)
    {
        float s[NFEAT];
        #pragma unroll
        for (int c = 0; c < NFEAT; c++) s[c] = 0.0f;
        #pragma unroll
        for (int i = 0; i < 4; i++) {
            const float* xv = x + ((size_t)b * NV + tid + i * 256) * NFEAT;
            #pragma unroll
            for (int c = 0; c < NFEAT; c++) s[c] += xv[c];
        }
        #pragma unroll
        for (int o = 16; o > 0; o >>= 1)
            #pragma unroll
            for (int c = 0; c < NFEAT; c++) s[c] += __shfl_xor_sync(~0u, s[c], o);
        if (lane == 0)
            #pragma unroll
            for (int c = 0; c < NFEAT; c++) S.sp[warp][c] = s[c];
    }

    const float* xv0 = x + ((size_t)b * NV + v0) * NFEAT;
    float xr0[NFEAT], xr1[NFEAT];
    #pragma unroll
    for (int c = 0; c < NFEAT; c++) { xr0[c] = xv0[c]; xr1[c] = xv0[NFEAT + c]; }

    for (int i = tid; i < NFEAT * NF; i += 256) S.sW[i / NF][i % NF] = W_in[i];
    for (int i = tid; i < NF * NC; i += 256) {
        int k = i / NC, c = i % NC;
        S.sWfw[k][c] = (c < NP) ? W_flr[(size_t)k * NP + c] : W_s[(size_t)k * NA + (c - NP)];
    }
    if (tid >= 32 && tid < 52) {
        int c = tid - 32;
        float sc = bn0_gamma[c] * rsqrtf(bn0_var[c] + 1e-3f);
        S.ss0[c] = sc;
        S.st0[c] = bn0_beta[c] - bn0_mean[c] * sc;
    }
    if (tid >= 64 && tid < 64 + NC)
        S.sbfw[tid - 64] = (tid - 64 < NP) ? b_flr[tid - 64] : b_s[tid - 64 - NP];
    __syncthreads();
    if (tid < NFEAT) {
        float a = 0.0f;
        #pragma unroll
        for (int w = 0; w < 8; w++) a += S.sp[w][tid];
        S.smean[tid] = a * (1.0f / 1024.0f);
    }
    __syncthreads();
    if (tid < NF) {   // fold mean-half of gex + b_in into per-event constant bias
        float a = b_in[tid];
        #pragma unroll
        for (int c = 10; c < 20; c++) {
            float g = S.smean[c - 10] * S.ss0[c] + S.st0[c];
            a += g * W_in[c * NF + tid];
        }
        S.scb[tid] = a;
    }
    __syncthreads();

    ull acc0[16], acc1[16];
    #pragma unroll
    for (int j = 0; j < 16; j++) {
        float2 bb = *(const float2*)&S.scb[2 * j];
        ull p = pk2(bb.x, bb.y);
        acc0[j] = p; acc1[j] = p;
    }
    #pragma unroll
    for (int c = 0; c < NFEAT; c++) {
        float sc = S.ss0[c], sh = S.st0[c];
        ull g0 = dup2(xr0[c] * sc + sh);
        ull g1 = dup2(xr1[c] * sc + sh);
        #pragma unroll
        for (int g8 = 0; g8 < 8; g8++) {
            F4U w; w.f = *(const float4*)&S.sW[c][g8 * 4];
            fma2(acc0[g8 * 2],     g0, w.u[0]); fma2(acc0[g8 * 2 + 1], g0, w.u[1]);
            fma2(acc1[g8 * 2],     g1, w.u[0]); fma2(acc1[g8 * 2 + 1], g1, w.u[1]);
        }
    }
    float* ob = g_h + (size_t)b * 384 * NV + v0;
    ull facc0[12], facc1[12];
    stream_epi_fw2<false>(acc0, acc1, nullptr, nullptr, S.sWfw, S.sbfw, ob, facc0, facc1);
    fw_finish2(facc0, facc1, S.sbuf, tid, g_w + ((size_t)b * NA) * NV + v0);
    __syncthreads();
    reduce96_2(S.sbuf, b, half, warp, lane, 0);
}

// =====================================================================
// F: fused block: Gp(l) -> out(l) -> h_{l+1} -> fw(l+1) -> partials
// =====================================================================
struct __align__(16) SmemF {
    float sbuf[NC][HALF_V];
    float sWo32[NF][NF];
    float sWfw[NF][NC];
    float sGp[NA][NF];
    float sam[96], sas[96];
    float sbfw[NC];
    float sbo[NF], sscale[NF], sshift[NF];
};

__global__ __launch_bounds__(256, 2)
void F_block(int l,
             const float* __restrict__ W_out,    const float* __restrict__ b_out,
             const float* __restrict__ bn_gamma, const float* __restrict__ bn_beta,
             const float* __restrict__ bn_mean,  const float* __restrict__ bn_var,
             const float* __restrict__ W_flr,    const float* __restrict__ b_flr,
             const float* __restrict__ W_s,      const float* __restrict__ b_s)
{
    extern __shared__ char smraw[];
    SmemF& S = *reinterpret_cast<SmemF*>(smraw);
    const int tid = threadIdx.x;
    const int b = blockIdx.x >> 1, half = blockIdx.x & 1;
    const int v0 = half * HALF_V + tid * 2;
    const int warp = tid >> 5, lane = tid & 31;
    const int pb = l & 1, lf = l + 1;

    pdl_trigger();   // let the next kernel prelaunch + stage its weights

    // ---- independent prologue: stage weights/biases (kernel inputs only) ----
    const float* WoG = W_out + (size_t)l * 228 * NF;
    ((float4*)&S.sWo32[0][0])[tid] = ((const float4*)WoG)[tid];   // 256 float4 = 32x32
    for (int i = tid; i < NF * NC; i += 256) {
        int k = i / NC, c = i % NC;
        S.sWfw[k][c] = (c < NP) ? W_flr[((size_t)lf * NF + k) * NP + c]
                                : W_s[((size_t)lf * NF + k) * NA + (c - NP)];
    }
    if (tid >= 128 && tid < 160) {
        int j = tid - 128;
        S.sbo[j] = b_out[l * NF + j];
        float sc = bn_gamma[l * NF + j] * rsqrtf(bn_var[l * NF + j] + 1e-3f);
        S.sscale[j] = sc;
        S.sshift[j] = bn_beta[l * NF + j] - bn_mean[l * NF + j] * sc;
    }
    if (tid >= 160 && tid < 160 + NC)
        S.sbfw[tid - 160] = (tid - 160 < NP) ? b_flr[lf * NP + tid - 160]
                                             : b_s[lf * NA + tid - 160 - NP];

    // ---- dependent data: wait for predecessor grid ----
    pdl_wait();

    const float* hb = g_h + ((size_t)b * 384 + (size_t)l * NF) * NV + v0;
    float2 wv[NA];
    #pragma unroll
    for (int a = 0; a < NA; a++)
        wv[a] = *(const float2*)(g_w + ((size_t)b * NA + a) * NV + v0);
    if (tid < 96) {
        float2 pm = *(const float2*)&g_pmax[pb][(b * 96 + tid) * 2];
        float2 ps = *(const float2*)&g_psum[pb][(b * 96 + tid) * 2];
        S.sam[tid] = fmaxf(pm.x, pm.y);
        S.sas[tid] = (ps.x + ps.y) * (1.0f / 1024.0f);
    }
    __syncthreads();

    if (tid < 128) {
        const int aa = warp, j = lane;
        float g = WoG[(224 + aa) * NF + j];
        #pragma unroll
        for (int c = 0; c < NC; c++)
            g += S.sam[aa * NC + c] * WoG[(32 + aa * 48 + c) * NF + j];
        #pragma unroll
        for (int c = 0; c < NC; c++)
            g += S.sas[aa * NC + c] * WoG[(32 + aa * 48 + NC + c) * NF + j];
        S.sGp[aa][j] = g;
    }
    __syncthreads();

    ull acc0[16], acc1[16];
    #pragma unroll
    for (int j = 0; j < 16; j++) {
        float2 bb = *(const float2*)&S.sbo[2 * j];
        ull p = pk2(bb.x, bb.y);
        acc0[j] = p; acc1[j] = p;
    }
    #pragma unroll
    for (int kc = 0; kc < 4; kc++) {
        float2 h2[8];
        #pragma unroll
        for (int k = 0; k < 8; k++)
            h2[k] = *(const float2*)(hb + (size_t)(kc * 8 + k) * NV);
        #pragma unroll
        for (int k = 0; k < 8; k++) {
            ull hk0 = dup2(h2[k].x), hk1 = dup2(h2[k].y);
            #pragma unroll
            for (int g8 = 0; g8 < 8; g8++) {
                F4U w; w.f = *(const float4*)&S.sWo32[kc * 8 + k][g8 * 4];
                fma2(acc0[g8 * 2],     hk0, w.u[0]); fma2(acc0[g8 * 2 + 1], hk0, w.u[1]);
                fma2(acc1[g8 * 2],     hk1, w.u[0]); fma2(acc1[g8 * 2 + 1], hk1, w.u[1]);
            }
        }
    }
    #pragma unroll
    for (int a = 0; a < NA; a++) {
        ull wa0 = dup2(wv[a].x), wa1 = dup2(wv[a].y);
        #pragma unroll
        for (int g8 = 0; g8 < 8; g8++) {
            F4U gg; gg.f = *(const float4*)&S.sGp[a][g8 * 4];
            fma2(acc0[g8 * 2],     wa0, gg.u[0]); fma2(acc0[g8 * 2 + 1], wa0, gg.u[1]);
            fma2(acc1[g8 * 2],     wa1, gg.u[0]); fma2(acc1[g8 * 2 + 1], wa1, gg.u[1]);
        }
    }

    float* ob = g_h + ((size_t)b * 384 + (size_t)lf * NF) * NV + v0;
    ull facc0[12], facc1[12];
    stream_epi_fw2<true>(acc0, acc1, S.sscale, S.sshift, S.sWfw, S.sbfw, ob, facc0, facc1);
    fw_finish2(facc0, facc1, S.sbuf, tid, g_w + ((size_t)b * NA) * NV + v0);
    __syncthreads();
    reduce96_2(S.sbuf, b, half, warp, lane, pb ^ 1);
}

// =====================================================================
// G: final block (l=10): out only. writes slot 11
// =====================================================================
__global__ __launch_bounds__(256, 2)
void G_block(const float* __restrict__ W_out,    const float* __restrict__ b_out,
             const float* __restrict__ bn_gamma, const float* __restrict__ bn_beta,
             const float* __restrict__ bn_mean,  const float* __restrict__ bn_var)
{
    __shared__ float sWo32[NF][NF];
    __shared__ float sGp[NA][NF];
    __shared__ float sam[96], sas[96];
    __shared__ float sbo[NF], sscale[NF], sshift[NF];
    const int tid = threadIdx.x;
    const int b = blockIdx.x >> 1, half = blockIdx.x & 1;
    const int v0 = half * HALF_V + tid * 2;
    const int warp = tid >> 5, lane = tid & 31;
    const int l = 10, pb = 0;

    pdl_trigger();   // let k2_tc prelaunch + stage its 136KB B-frags

    const float* WoG = W_out + (size_t)l * 228 * NF;
    ((float4*)&sWo32[0][0])[tid] = ((const float4*)WoG)[tid];
    if (tid >= 128 && tid < 160) {
        int j = tid - 128;
        sbo[j] = b_out[l * NF + j];
        float sc = bn_gamma[l * NF + j] * rsqrtf(bn_var[l * NF + j] + 1e-3f);
        sscale[j] = sc;
        sshift[j] = bn_beta[l * NF + j] - bn_mean[l * NF + j] * sc;
    }

    pdl_wait();

    const float* hb = g_h + ((size_t)b * 384 + (size_t)l * NF) * NV + v0;
    float2 wv[NA];
    #pragma unroll
    for (int a = 0; a < NA; a++)
        wv[a] = *(const float2*)(g_w + ((size_t)b * NA + a) * NV + v0);
    if (tid < 96) {
        float2 pm = *(const float2*)&g_pmax[pb][(b * 96 + tid) * 2];
        float2 ps = *(const float2*)&g_psum[pb][(b * 96 + tid) * 2];
        sam[tid] = fmaxf(pm.x, pm.y);
        sas[tid] = (ps.x + ps.y) * (1.0f / 1024.0f);
    }
    __syncthreads();
    if (tid < 128) {
        const int aa = warp, j = lane;
        float g = WoG[(224 + aa) * NF + j];
        #pragma unroll
        for (int c = 0; c < NC; c++)
            g += sam[aa * NC + c] * WoG[(32 + aa * 48 + c) * NF + j];
        #pragma unroll
        for (int c = 0; c < NC; c++)
            g += sas[aa * NC + c] * WoG[(32 + aa * 48 + NC + c) * NF + j];
        sGp[aa][j] = g;
    }
    __syncthreads();

    ull acc0[16], acc1[16];
    #pragma unroll
    for (int j = 0; j < 16; j++) {
        float2 bb = *(const float2*)&sbo[2 * j];
        ull p = pk2(bb.x, bb.y);
        acc0[j] = p; acc1[j] = p;
    }
    #pragma unroll
    for (int kc = 0; kc < 4; kc++) {
        float2 h2[8];
        #pragma unroll
        for (int k = 0; k < 8; k++)
            h2[k] = *(const float2*)(hb + (size_t)(kc * 8 + k) * NV);
        #pragma unroll
        for (int k = 0; k < 8; k++) {
            ull hk0 = dup2(h2[k].x), hk1 = dup2(h2[k].y);
            #pragma unroll
            for (int g8 = 0; g8 < 8; g8++) {
                F4U w; w.f = *(const float4*)&sWo32[kc * 8 + k][g8 * 4];
                fma2(acc0[g8 * 2],     hk0, w.u[0]); fma2(acc0[g8 * 2 + 1], hk0, w.u[1]);
                fma2(acc1[g8 * 2],     hk1, w.u[0]); fma2(acc1[g8 * 2 + 1], hk1, w.u[1]);
            }
        }
    }
    #pragma unroll
    for (int a = 0; a < NA; a++) {
        ull wa0 = dup2(wv[a].x), wa1 = dup2(wv[a].y);
        #pragma unroll
        for (int g8 = 0; g8 < 8; g8++) {
            F4U gg; gg.f = *(const float4*)&sGp[a][g8 * 4];
            fma2(acc0[g8 * 2],     wa0, gg.u[0]); fma2(acc0[g8 * 2 + 1], wa0, gg.u[1]);
            fma2(acc1[g8 * 2],     wa1, gg.u[0]); fma2(acc1[g8 * 2 + 1], wa1, gg.u[1]);
        }
    }
    float* ob = g_h + ((size_t)b * 384 + (size_t)11 * NF) * NV + v0;
    #pragma unroll
    for (int j2 = 0; j2 < 16; j2++) {
        float2 z0 = up2(acc0[j2]), z1 = up2(acc1[j2]);
        float sc0 = sscale[2 * j2], sh0 = sshift[2 * j2];
        float sc1 = sscale[2 * j2 + 1], sh1 = sshift[2 * j2 + 1];
        *(float2*)(ob + (size_t)(2 * j2) * NV) =
            make_float2(tanh_fast(z0.x) * sc0 + sh0, tanh_fast(z1.x) * sc0 + sh0);
        *(float2*)(ob + (size_t)(2 * j2 + 1) * NV) =
            make_float2(tanh_fast(z0.y) * sc1 + sh1, tanh_fast(z1.y) * sc1 + sh1);
    }
}

// =====================================================================
// k2_tc: out = relu(relu(F @ W_o0 + b0) @ W_o1 + b1) via 3xTF32 mma.sync
// (split-precision: A*B = Ahi*Bhi + Alo*Bhi + Ahi*Blo; tf32-error ~1e-6).
// F = g_h slots 1..11: logical A[v][k], stored [k][v] (v contiguous).
// grid 512 (b=blk>>2, chunk=blk&3): CTA = 256 vertices, 8 warps.
// Each warp: M=32 (two m16 tiles), N=48, K=352. B hi+lo frags in smem.
// =====================================================================
#define NKT 44              // 352 / 8
#define NNT 6               // 48 / 8
#define BPK (NNT * NKT * 32)  // 8448 frag pairs

struct __align__(16) SmemK2T {
    float bph[BPK * 2];     // packed tf32 B hi-frags
    float bpl[BPK * 2];     // packed tf32 B lo-frags
    float sW1[144];
    float sb0[48];
    float sb1[4];
};

__global__ __launch_bounds__(256, 1)
void k2_tc(const float* __restrict__ W_o0, const float* __restrict__ b_o0,
           const float* __restrict__ W_o1, const float* __restrict__ b_o1,
           float* __restrict__ out)
{
    extern __shared__ char smraw[];
    SmemK2T& S = *reinterpret_cast<SmemK2T*>(smraw);
    const int tid = threadIdx.x;
    const int lane = tid & 31, warp = tid >> 5;
    const int gr = lane >> 2, gc = lane & 3;   // frag row/col indices

    pdl_trigger();

    // independent prologue: stage packed B frags (hi + lo residual)
    for (int i = tid; i < BPK; i += 256) {
        int ln = i & 31, rest = i >> 5;
        int kt = rest % NKT, nt = rest / NKT;
        int c = ln & 3, r = ln >> 2;
        int k0 = kt * 8, n0 = nt * 8;
        float w0 = W_o0[(k0 + c) * 48 + n0 + r];
        float w1 = W_o0[(k0 + c + 4) * 48 + n0 + r];
        unsigned h0, l0, h1, l1;
        split_tf32(w0, h0, l0);
        split_tf32(w1, h1, l1);
        *(uint2*)&S.bph[2 * i] = make_uint2(h0, h1);
        *(uint2*)&S.bpl[2 * i] = make_uint2(l0, l1);
    }
    if (tid < 144) S.sW1[tid] = W_o1[tid];
    if (tid >= 160 && tid < 208) S.sb0[tid - 160] = b_o0[tid - 160];
    if (tid >= 208 && tid < 211) S.sb1[tid - 208] = b_o1[tid - 208];
    __syncthreads();

    pdl_wait();   // g_h slot 11 must be complete

    const int b = blockIdx.x >> 2, chunk = blockIdx.x & 3;
    const int vb = chunk * 256 + warp * 32;          // 32 vertices per warp
    const float* fb = g_h + ((size_t)b * 384 + NF) * NV;

    float d[2][NNT][4];
    #pragma unroll
    for (int t = 0; t < 2; t++)
        #pragma unroll
        for (int nt = 0; nt < NNT; nt++)
            #pragma unroll
            for (int q = 0; q < 4; q++) d[t][nt][q] = 0.0f;

    #pragma unroll 2
    for (int kt = 0; kt < NKT; kt++) {
        const int k0 = kt * 8;
        unsigned ah[2][4], al[2][4];
        #pragma unroll
        for (int t = 0; t < 2; t++) {
            const float* base = fb + (size_t)(k0 + gc) * NV + vb + t * 16 + gr;
            float f0 = base[0];
            float f1 = base[8];
            float f2 = base[(size_t)4 * NV];
            float f3 = base[(size_t)4 * NV + 8];
            split_tf32(f0, ah[t][0], al[t][0]);
            split_tf32(f1, ah[t][1], al[t][1]);
            split_tf32(f2, ah[t][2], al[t][2]);
            split_tf32(f3, ah[t][3], al[t][3]);
        }
        #pragma unroll
        for (int nt = 0; nt < NNT; nt++) {
            const int fi = 2 * ((nt * NKT + kt) * 32 + lane);
            uint2 bh = *(const uint2*)&S.bph[fi];
            uint2 bl = *(const uint2*)&S.bpl[fi];
            #pragma unroll
            for (int t = 0; t < 2; t++) {
                mma_tf32(d[t][nt][0], d[t][nt][1], d[t][nt][2], d[t][nt][3],
                         ah[t][0], ah[t][1], ah[t][2], ah[t][3], bh.x, bh.y);
                mma_tf32(d[t][nt][0], d[t][nt][1], d[t][nt][2], d[t][nt][3],
                         al[t][0], al[t][1], al[t][2], al[t][3], bh.x, bh.y);
                mma_tf32(d[t][nt][0], d[t][nt][1], d[t][nt][2], d[t][nt][3],
                         ah[t][0], ah[t][1], ah[t][2], ah[t][3], bl.x, bl.y);
            }
        }
    }

    // epilogue: bias + relu + second layer (48 -> 3) + quad reduce
    #pragma unroll
    for (int t = 0; t < 2; t++) {
        float o0a = 0.0f, o1a = 0.0f, o2a = 0.0f;   // row gr
        float o0b = 0.0f, o1b = 0.0f, o2b = 0.0f;   // row gr+8
        #pragma unroll
        for (int nt = 0; nt < NNT; nt++) {
            const int n = nt * 8 + 2 * gc;
            float2 bb = *(const float2*)&S.sb0[n];
            float h0 = fmaxf(d[t][nt][0] + bb.x, 0.0f);
            float h1 = fmaxf(d[t][nt][1] + bb.y, 0.0f);
            float h2 = fmaxf(d[t][nt][2] + bb.x, 0.0f);
            float h3 = fmaxf(d[t][nt][3] + bb.y, 0.0f);
            const float* w1a = &S.sW1[n * 3];       // W1[n][0..2], W1[n+1][0..2]
            o0a += h0 * w1a[0] + h1 * w1a[3];
            o1a += h0 * w1a[1] + h1 * w1a[4];
            o2a += h0 * w1a[2] + h1 * w1a[5];
            o0b += h2 * w1a[0] + h3 * w1a[3];
            o1b += h2 * w1a[1] + h3 * w1a[4];
            o2b += h2 * w1a[2] + h3 * w1a[5];
        }
        #pragma unroll
        for (int o = 1; o <= 2; o <<= 1) {
            o0a += __shfl_xor_sync(~0u, o0a, o); o1a += __shfl_xor_sync(~0u, o1a, o);
            o2a += __shfl_xor_sync(~0u, o2a, o); o0b += __shfl_xor_sync(~0u, o0b, o);
            o1b += __shfl_xor_sync(~0u, o1b, o); o2b += __shfl_xor_sync(~0u, o2b, o);
        }
        if (gc == 0) {
            const int va = b * NV + vb + t * 16 + gr;
            float* opa = out + (size_t)va * 3;
            opa[0] = fmaxf(o0a + S.sb1[0], 0.0f);
            opa[1] = fmaxf(o1a + S.sb1[1], 0.0f);
            opa[2] = fmaxf(o2a + S.sb1[2], 0.0f);
            float* opb = out + (size_t)(va + 8) * 3;
            opb[0] = fmaxf(o0b + S.sb1[0], 0.0f);
            opb[1] = fmaxf(o1b + S.sb1[1], 0.0f);
            opb[2] = fmaxf(o2b + S.sb1[2], 0.0f);
        }
    }
}

// =====================================================================
// host-side PDL launch helper
// =====================================================================
template <typename... Args>
static void launch_pdl(void (*kern)(Args...), dim3 grid, dim3 block,
                       size_t smem, Args... args)
{
    cudaLaunchConfig_t cfg = {};
    cfg.gridDim = grid;
    cfg.blockDim = block;
    cfg.dynamicSmemBytes = smem;
    cfg.stream = 0;
    cudaLaunchAttribute attr[1];
    attr[0].id = cudaLaunchAttributeProgrammaticStreamSerialization;
    attr[0].val.programmaticStreamSerializationAllowed = 1;
    cfg.attrs = attr;
    cfg.numAttrs = 1;
    cudaLaunchKernelEx(&cfg, kern, args...);
}

extern "C" void kernel_launch(void* const* d_in, const int* in_sizes, int n_in,
                              void* d_out, int out_size)
{
    const float* x         = (const float*)d_in[0];
    const float* bn0_gamma = (const float*)d_in[1];
    const float* bn0_beta  = (const float*)d_in[2];
    const float* bn0_mean  = (const float*)d_in[3];
    const float* bn0_var   = (const float*)d_in[4];
    const float* W_in      = (const float*)d_in[5];
    const float* b_in      = (const float*)d_in[6];
    const float* W_flr     = (const float*)d_in[7];
    const float* b_flr     = (const float*)d_in[8];
    const float* W_s       = (const float*)d_in[9];
    const float* b_s       = (const float*)d_in[10];
    const float* W_out     = (const float*)d_in[11];
    const float* b_out     = (const float*)d_in[12];
    const float* bn_gamma  = (const float*)d_in[13];
    const float* bn_beta   = (const float*)d_in[14];
    const float* bn_mean   = (const float*)d_in[15];
    const float* bn_var    = (const float*)d_in[16];
    const float* W_o0      = (const float*)d_in[17];
    const float* b_o0      = (const float*)d_in[18];
    const float* W_o1      = (const float*)d_in[19];
    const float* b_o1      = (const float*)d_in[20];

    cudaFuncSetAttribute(kB_fw, cudaFuncAttributeMaxDynamicSharedMemorySize,
                         (int)sizeof(SmemB));
    cudaFuncSetAttribute(F_block, cudaFuncAttributeMaxDynamicSharedMemorySize,
                         (int)sizeof(SmemF));
    cudaFuncSetAttribute(k2_tc, cudaFuncAttributeMaxDynamicSharedMemorySize,
                         (int)sizeof(SmemK2T));

    kB_fw<<<NB * 2, 256, sizeof(SmemB)>>>(x, bn0_gamma, bn0_var, bn0_beta, bn0_mean,
                                          W_in, b_in, W_flr, b_flr, W_s, b_s);

    for (int l = 0; l < NBK - 1; l++) {
        launch_pdl(F_block, dim3(NB * 2), dim3(256), sizeof(SmemF),
                   l, W_out, b_out, bn_gamma, bn_beta, bn_mean, bn_var,
                   W_flr, b_flr, W_s, b_s);
    }
    launch_pdl(G_block, dim3(NB * 2), dim3(256), (size_t)0,
               W_out, b_out, bn_gamma, bn_beta, bn_mean, bn_var);

    launch_pdl(k2_tc, dim3(NB * 4), dim3(256), sizeof(SmemK2T),
               W_o0, b_o0, W_o1, b_o1, (float*)d_out);
}

// round 14
// speedup vs baseline: 1.4751x; 1.0794x over previous
#include <cuda_runtime.h>
#include <math_constants.h>
#include <cstdint>
#include <cstddef>

// ---------------- problem constants ----------------
#define NB    128
#define NV    1024
#define NFEAT 10
#define NBK   11
#define NF    32
#define NP    20
#define NA    4
#define NC    24
#define DFE   352   // NBK*NF
#define HALF_V 512

// h ring: slot 0 = h0, slot l+1 = output of block l. layout g_h[b][s*32+k][v]
__device__ float g_h[(size_t)NB * 384 * NV];     // 201 MB
__device__ float g_w[(size_t)NB * NA * NV];      // per-block edge weights
__device__ float g_pmax[2][NB * 96 * 2];         // double-buffered partial max
__device__ float g_psum[2][NB * 96 * 2];         // double-buffered partial sum

// ---------------- PDL helpers ----------------
__device__ __forceinline__ void pdl_trigger() {
#if defined(__CUDA_ARCH__) && __CUDA_ARCH__ >= 900
    cudaTriggerProgrammaticLaunchCompletion();
#endif
}
__device__ __forceinline__ void pdl_wait() {
#if defined(__CUDA_ARCH__) && __CUDA_ARCH__ >= 900
    cudaGridDependencySynchronize();
#endif
}

// ---------------- f32x2 packed-math helpers ----------------
typedef unsigned long long ull;
__device__ __forceinline__ ull pk2(float a, float b) {
    ull r; asm("mov.b64 %0, {%1, %2};" : "=l"(r) : "f"(a), "f"(b)); return r;
}
__device__ __forceinline__ ull dup2(float a) { return pk2(a, a); }
__device__ __forceinline__ void fma2(ull& d, ull a, ull b) {
    asm("fma.rn.f32x2 %0, %1, %2, %0;" : "+l"(d) : "l"(a), "l"(b));
}
__device__ __forceinline__ ull mul2(ull a, ull b) {
    ull r; asm("mul.rn.f32x2 %0, %1, %2;" : "=l"(r) : "l"(a), "l"(b)); return r;
}
__device__ __forceinline__ ull add2(ull a, ull b) {
    ull r; asm("add.rn.f32x2 %0, %1, %2;" : "=l"(r) : "l"(a), "l"(b)); return r;
}
__device__ __forceinline__ float2 up2(ull v) {
    float2 r; asm("mov.b64 {%0, %1}, %2;" : "=f"(r.x), "=f"(r.y) : "l"(v)); return r;
}
union F4U { float4 f; ull u[2]; };

__device__ __forceinline__ float tanh_fast(float x) {
    float r; asm("tanh.approx.f32 %0, %1;" : "=f"(r) : "f"(x)); return r;
}
__device__ __forceinline__ unsigned to_tf32(float x) {
    unsigned r; asm("cvt.rna.tf32.f32 %0, %1;" : "=r"(r) : "f"(x)); return r;
}
__device__ __forceinline__ void split_tf32(float x, unsigned& hi, unsigned& lo) {
    hi = to_tf32(x);
    lo = to_tf32(x - __uint_as_float(hi));
}
__device__ __forceinline__ void mma_tf32(
    float& d0, float& d1, float& d2, float& d3,
    unsigned a0, unsigned a1, unsigned a2, unsigned a3,
    unsigned b0, unsigned b1)
{
    asm("mma.sync.aligned.m16n8k8.row.col.f32.tf32.tf32.f32 "
        "{%0,%1,%2,%3}, {%4,%5,%6,%7}, {%8,%9}, {%0,%1,%2,%3};"
        : "+f"(d0), "+f"(d1), "+f"(d2), "+f"(d3)
        : "r"(a0), "r"(a1), "r"(a2), "r"(a3), "r"(b0), "r"(b1));
}

// ---------------- 2-vertex shared helpers ----------------
template<bool BN>
__device__ __forceinline__ void stream_epi_fw2(
    ull acc0[16], ull acc1[16],
    const float* __restrict__ sscale, const float* __restrict__ sshift,
    const float (*__restrict__ sWfw)[NC], const float* __restrict__ sbfw,
    float* __restrict__ ob, ull facc0[12], ull facc1[12])
{
    #pragma unroll
    for (int j = 0; j < 12; j++) {
        float2 bb = *(const float2*)&sbfw[2 * j];
        ull p = pk2(bb.x, bb.y);
        facc0[j] = p; facc1[j] = p;
    }
    #pragma unroll
    for (int j2 = 0; j2 < 16; j2++) {
        float2 z0 = up2(acc0[j2]), z1 = up2(acc1[j2]);
        float a00 = tanh_fast(z0.x), a01 = tanh_fast(z0.y);
        float a10 = tanh_fast(z1.x), a11 = tanh_fast(z1.y);
        if (BN) {
            float sc0 = sscale[2 * j2], sh0 = sshift[2 * j2];
            float sc1 = sscale[2 * j2 + 1], sh1 = sshift[2 * j2 + 1];
            a00 = a00 * sc0 + sh0; a10 = a10 * sc0 + sh0;
            a01 = a01 * sc1 + sh1; a11 = a11 * sc1 + sh1;
        }
        *(float2*)(ob + (size_t)(2 * j2) * NV)     = make_float2(a00, a10);
        *(float2*)(ob + (size_t)(2 * j2 + 1) * NV) = make_float2(a01, a11);
        ull d00 = dup2(a00), d01 = dup2(a01), d10 = dup2(a10), d11 = dup2(a11);
        #pragma unroll
        for (int g6 = 0; g6 < 6; g6++) {
            F4U w0; w0.f = *(const float4*)&sWfw[2 * j2][g6 * 4];
            F4U w1; w1.f = *(const float4*)&sWfw[2 * j2 + 1][g6 * 4];
            fma2(facc0[2 * g6],     d00, w0.u[0]); fma2(facc0[2 * g6 + 1], d00, w0.u[1]);
            fma2(facc0[2 * g6],     d01, w1.u[0]); fma2(facc0[2 * g6 + 1], d01, w1.u[1]);
            fma2(facc1[2 * g6],     d10, w0.u[0]); fma2(facc1[2 * g6 + 1], d10, w0.u[1]);
            fma2(facc1[2 * g6],     d11, w1.u[0]); fma2(facc1[2 * g6 + 1], d11, w1.u[1]);
        }
    }
}

__device__ __forceinline__ void fw_finish2(
    ull facc0[12], ull facc1[12], float (*__restrict__ sbuf)[HALF_V], int tid,
    float* __restrict__ gw)
{
    #pragma unroll
    for (int j = 0; j < 10; j++) {
        float2 f0 = up2(facc0[j]), f1 = up2(facc1[j]);
        *(float2*)&sbuf[2 * j][2 * tid]     = make_float2(f0.x, f1.x);
        *(float2*)&sbuf[2 * j + 1][2 * tid] = make_float2(f0.y, f1.y);
    }
    float2 p0 = up2(facc0[10]), q0 = up2(facc0[11]);
    float2 p1 = up2(facc1[10]), q1 = up2(facc1[11]);
    float w0a = __expf(-fabsf(p0.x)), w0b = __expf(-fabsf(p0.y));
    float w0c = __expf(-fabsf(q0.x)), w0d = __expf(-fabsf(q0.y));
    float w1a = __expf(-fabsf(p1.x)), w1b = __expf(-fabsf(p1.y));
    float w1c = __expf(-fabsf(q1.x)), w1d = __expf(-fabsf(q1.y));
    *(float2*)&sbuf[20][2 * tid] = make_float2(w0a, w1a);
    *(float2*)&sbuf[21][2 * tid] = make_float2(w0b, w1b);
    *(float2*)&sbuf[22][2 * tid] = make_float2(w0c, w1c);
    *(float2*)&sbuf[23][2 * tid] = make_float2(w0d, w1d);
    *(float2*)(gw)                    = make_float2(w0a, w1a);
    *(float2*)(gw + (size_t)NV)       = make_float2(w0b, w1b);
    *(float2*)(gw + (size_t)2 * NV)   = make_float2(w0c, w1c);
    *(float2*)(gw + (size_t)3 * NV)   = make_float2(w0d, w1d);
}

// 96 max/sum tasks over 512 vertices; warp w -> aa = w>>1, c = (w&1)*12..+12
__device__ __forceinline__ void reduce96_2(
    const float (*__restrict__ sbuf)[HALF_V], int b, int half, int warp, int lane,
    int pb)
{
    const int aa = warp >> 1, cbase = (warp & 1) * 12;
    ull s2[12]; float m0[12], m1[12];
    #pragma unroll
    for (int c = 0; c < 12; c++) { s2[c] = 0ull; m0[c] = -CUDART_INF_F; m1[c] = -CUDART_INF_F; }
    #pragma unroll
    for (int i = 0; i < 8; i++) {
        const int vv = (lane + i * 32) * 2;
        ull w2 = *(const ull*)&sbuf[NP + aa][vv];
        #pragma unroll
        for (int c = 0; c < 12; c++) {
            ull f2 = *(const ull*)&sbuf[cbase + c][vv];
            ull p = mul2(w2, f2);
            s2[c] = add2(s2[c], p);
            float2 pv = up2(p);
            m0[c] = fmaxf(m0[c], pv.x);
            m1[c] = fmaxf(m1[c], pv.y);
        }
    }
    #pragma unroll
    for (int c = 0; c < 12; c++) {
        float m = fmaxf(m0[c], m1[c]);
        float2 sv = up2(s2[c]);
        float s = sv.x + sv.y;
        #pragma unroll
        for (int o = 16; o > 0; o >>= 1) {
            m = fmaxf(m, __shfl_xor_sync(~0u, m, o));
            s += __shfl_xor_sync(~0u, s, o);
        }
        if (lane == 0) {
            const int t = aa * 24 + cbase + c;
            g_pmax[pb][(b * 96 + t) * 2 + half] = m;
            g_psum[pb][(b * 96 + t) * 2 + half] = s;
        }
    }
}

// =====================================================================
// kB_fw: event mean (computed in-CTA) + h0 = tanh(bn0(x)@W_in + cbias)
// -> slot 0, fused fw(block 0). grid 256 (b=blk>>1, half=blk&1), 256 thr
// =====================================================================
struct __align__(16) SmemB {
    float sbuf[NC][HALF_V];
    float sW[NFEAT][NF];
    float sWfw[NF][NC];
    float scb[NF];
    float ss0[20], st0[20];
    float sbfw[NC];
    float sp[8][12];
    float smean[12];
};

__global__ __launch_bounds__(256, 2)
void kB_fw(const float* __restrict__ x,
           const float* __restrict__ bn0_gamma, const float* __restrict__ bn0_var,
           const float* __restrict__ bn0_beta,  const float* __restrict__ bn0_mean,
           const float* __restrict__ W_in,      const float* __restrict__ b_in,
           const float* __restrict__ W_flr, const float* __restrict__ b_flr,
           const float* __restrict__ W_s,   const float* __restrict__ b_s)
{
    extern __shared__ char smraw[];
    SmemB& S = *reinterpret_cast<SmemB*>(smraw);
    const int tid = threadIdx.x;
    const int b = blockIdx.x >> 1, half = blockIdx.x & 1;
    const int v0 = half * HALF_V + tid * 2;
    const int warp = tid >> 5, lane = tid & 31;

    pdl_trigger();   // allow F(0) to prelaunch and stage its weights

    // per-event vertex mean (each CTA computes it for its event; cheap)
    {
        float s[NFEAT];
        #pragma unroll
        for (int c = 0; c < NFEAT; c++) s[c] = 0.0f;
        #pragma unroll
        for (int i = 0; i < 4; i++) {
            const float* xv = x + ((size_t)b * NV + tid + i * 256) * NFEAT;
            #pragma unroll
            for (int c = 0; c < NFEAT; c++) s[c] += xv[c];
        }
        #pragma unroll
        for (int o = 16; o > 0; o >>= 1)
            #pragma unroll
            for (int c = 0; c < NFEAT; c++) s[c] += __shfl_xor_sync(~0u, s[c], o);
        if (lane == 0)
            #pragma unroll
            for (int c = 0; c < NFEAT; c++) S.sp[warp][c] = s[c];
    }

    const float* xv0 = x + ((size_t)b * NV + v0) * NFEAT;
    float xr0[NFEAT], xr1[NFEAT];
    #pragma unroll
    for (int c = 0; c < NFEAT; c++) { xr0[c] = xv0[c]; xr1[c] = xv0[NFEAT + c]; }

    for (int i = tid; i < NFEAT * NF; i += 256) S.sW[i / NF][i % NF] = W_in[i];
    for (int i = tid; i < NF * NC; i += 256) {
        int k = i / NC, c = i % NC;
        S.sWfw[k][c] = (c < NP) ? W_flr[(size_t)k * NP + c] : W_s[(size_t)k * NA + (c - NP)];
    }
    if (tid >= 32 && tid < 52) {
        int c = tid - 32;
        float sc = bn0_gamma[c] * rsqrtf(bn0_var[c] + 1e-3f);
        S.ss0[c] = sc;
        S.st0[c] = bn0_beta[c] - bn0_mean[c] * sc;
    }
    if (tid >= 64 && tid < 64 + NC)
        S.sbfw[tid - 64] = (tid - 64 < NP) ? b_flr[tid - 64] : b_s[tid - 64 - NP];
    __syncthreads();
    if (tid < NFEAT) {
        float a = 0.0f;
        #pragma unroll
        for (int w = 0; w < 8; w++) a += S.sp[w][tid];
        S.smean[tid] = a * (1.0f / 1024.0f);
    }
    __syncthreads();
    if (tid < NF) {   // fold mean-half of gex + b_in into per-event constant bias
        float a = b_in[tid];
        #pragma unroll
        for (int c = 10; c < 20; c++) {
            float g = S.smean[c - 10] * S.ss0[c] + S.st0[c];
            a += g * W_in[c * NF + tid];
        }
        S.scb[tid] = a;
    }
    __syncthreads();

    ull acc0[16], acc1[16];
    #pragma unroll
    for (int j = 0; j < 16; j++) {
        float2 bb = *(const float2*)&S.scb[2 * j];
        ull p = pk2(bb.x, bb.y);
        acc0[j] = p; acc1[j] = p;
    }
    #pragma unroll
    for (int c = 0; c < NFEAT; c++) {
        float sc = S.ss0[c], sh = S.st0[c];
        ull g0 = dup2(xr0[c] * sc + sh);
        ull g1 = dup2(xr1[c] * sc + sh);
        #pragma unroll
        for (int g8 = 0; g8 < 8; g8++) {
            F4U w; w.f = *(const float4*)&S.sW[c][g8 * 4];
            fma2(acc0[g8 * 2],     g0, w.u[0]); fma2(acc0[g8 * 2 + 1], g0, w.u[1]);
            fma2(acc1[g8 * 2],     g1, w.u[0]); fma2(acc1[g8 * 2 + 1], g1, w.u[1]);
        }
    }
    float* ob = g_h + (size_t)b * 384 * NV + v0;
    ull facc0[12], facc1[12];
    stream_epi_fw2<false>(acc0, acc1, nullptr, nullptr, S.sWfw, S.sbfw, ob, facc0, facc1);
    fw_finish2(facc0, facc1, S.sbuf, tid, g_w + ((size_t)b * NA) * NV + v0);
    __syncthreads();
    reduce96_2(S.sbuf, b, half, warp, lane, 0);
}

// =====================================================================
// F: fused block: Gp(l) -> out(l) -> h_{l+1} -> fw(l+1) -> partials
// Full W_out rows 32..227 staged in the PDL-hidden prologue.
// =====================================================================
struct __align__(16) SmemF {
    float sbuf[NC][HALF_V];
    float sWo32[NF][NF];
    float sWoX[196][NF];     // W_out rows 32..227 (PDL-hidden staging)
    float sWfw[NF][NC];
    float sGp[NA][NF];
    float sam[96], sas[96];
    float sbfw[NC];
    float sbo[NF], sscale[NF], sshift[NF];
};

__global__ __launch_bounds__(256, 2)
void F_block(int l,
             const float* __restrict__ W_out,    const float* __restrict__ b_out,
             const float* __restrict__ bn_gamma, const float* __restrict__ bn_beta,
             const float* __restrict__ bn_mean,  const float* __restrict__ bn_var,
             const float* __restrict__ W_flr,    const float* __restrict__ b_flr,
             const float* __restrict__ W_s,      const float* __restrict__ b_s)
{
    extern __shared__ char smraw[];
    SmemF& S = *reinterpret_cast<SmemF*>(smraw);
    const int tid = threadIdx.x;
    const int b = blockIdx.x >> 1, half = blockIdx.x & 1;
    const int v0 = half * HALF_V + tid * 2;
    const int warp = tid >> 5, lane = tid & 31;
    const int pb = l & 1, lf = l + 1;

    pdl_trigger();   // let the next kernel prelaunch + stage its weights

    // ---- independent prologue: stage weights/biases (kernel inputs only) ----
    const float* WoG = W_out + (size_t)l * 228 * NF;
    ((float4*)&S.sWo32[0][0])[tid] = ((const float4*)WoG)[tid];   // rows 0..31
    {
        const float4* src = (const float4*)(WoG + 32 * NF);
        float4* dst = (float4*)&S.sWoX[0][0];
        for (int i = tid; i < 196 * NF / 4; i += 256) dst[i] = src[i];
    }
    for (int i = tid; i < NF * NC; i += 256) {
        int k = i / NC, c = i % NC;
        S.sWfw[k][c] = (c < NP) ? W_flr[((size_t)lf * NF + k) * NP + c]
                                : W_s[((size_t)lf * NF + k) * NA + (c - NP)];
    }
    if (tid >= 128 && tid < 160) {
        int j = tid - 128;
        S.sbo[j] = b_out[l * NF + j];
        float sc = bn_gamma[l * NF + j] * rsqrtf(bn_var[l * NF + j] + 1e-3f);
        S.sscale[j] = sc;
        S.sshift[j] = bn_beta[l * NF + j] - bn_mean[l * NF + j] * sc;
    }
    if (tid >= 160 && tid < 160 + NC)
        S.sbfw[tid - 160] = (tid - 160 < NP) ? b_flr[lf * NP + tid - 160]
                                             : b_s[lf * NA + tid - 160 - NP];

    // ---- dependent data: wait for predecessor grid ----
    pdl_wait();

    const float* hb = g_h + ((size_t)b * 384 + (size_t)l * NF) * NV + v0;
    float2 wv[NA];
    #pragma unroll
    for (int a = 0; a < NA; a++)
        wv[a] = *(const float2*)(g_w + ((size_t)b * NA + a) * NV + v0);
    if (tid < 96) {
        float2 pm = *(const float2*)&g_pmax[pb][(b * 96 + tid) * 2];
        float2 ps = *(const float2*)&g_psum[pb][(b * 96 + tid) * 2];
        S.sam[tid] = fmaxf(pm.x, pm.y);
        S.sas[tid] = (ps.x + ps.y) * (1.0f / 1024.0f);
    }
    __syncthreads();

    if (tid < 128) {   // Gp from smem-staged W_out rows (rowX = row-32)
        const int aa = warp, j = lane;
        float g = S.sWoX[192 + aa][j];                 // row 224+aa
        #pragma unroll
        for (int c = 0; c < NC; c++)
            g += S.sam[aa * NC + c] * S.sWoX[aa * 48 + c][j];
        #pragma unroll
        for (int c = 0; c < NC; c++)
            g += S.sas[aa * NC + c] * S.sWoX[aa * 48 + NC + c][j];
        S.sGp[aa][j] = g;
    }
    __syncthreads();

    ull acc0[16], acc1[16];
    #pragma unroll
    for (int j = 0; j < 16; j++) {
        float2 bb = *(const float2*)&S.sbo[2 * j];
        ull p = pk2(bb.x, bb.y);
        acc0[j] = p; acc1[j] = p;
    }
    #pragma unroll
    for (int kc = 0; kc < 4; kc++) {
        float2 h2[8];
        #pragma unroll
        for (int k = 0; k < 8; k++)
            h2[k] = *(const float2*)(hb + (size_t)(kc * 8 + k) * NV);
        #pragma unroll
        for (int k = 0; k < 8; k++) {
            ull hk0 = dup2(h2[k].x), hk1 = dup2(h2[k].y);
            #pragma unroll
            for (int g8 = 0; g8 < 8; g8++) {
                F4U w; w.f = *(const float4*)&S.sWo32[kc * 8 + k][g8 * 4];
                fma2(acc0[g8 * 2],     hk0, w.u[0]); fma2(acc0[g8 * 2 + 1], hk0, w.u[1]);
                fma2(acc1[g8 * 2],     hk1, w.u[0]); fma2(acc1[g8 * 2 + 1], hk1, w.u[1]);
            }
        }
    }
    #pragma unroll
    for (int a = 0; a < NA; a++) {
        ull wa0 = dup2(wv[a].x), wa1 = dup2(wv[a].y);
        #pragma unroll
        for (int g8 = 0; g8 < 8; g8++) {
            F4U gg; gg.f = *(const float4*)&S.sGp[a][g8 * 4];
            fma2(acc0[g8 * 2],     wa0, gg.u[0]); fma2(acc0[g8 * 2 + 1], wa0, gg.u[1]);
            fma2(acc1[g8 * 2],     wa1, gg.u[0]); fma2(acc1[g8 * 2 + 1], wa1, gg.u[1]);
        }
    }

    float* ob = g_h + ((size_t)b * 384 + (size_t)lf * NF) * NV + v0;
    ull facc0[12], facc1[12];
    stream_epi_fw2<true>(acc0, acc1, S.sscale, S.sshift, S.sWfw, S.sbfw, ob, facc0, facc1);
    fw_finish2(facc0, facc1, S.sbuf, tid, g_w + ((size_t)b * NA) * NV + v0);
    __syncthreads();
    reduce96_2(S.sbuf, b, half, warp, lane, pb ^ 1);
}

// =====================================================================
// G: final block (l=10): out only. writes slot 11
// =====================================================================
__global__ __launch_bounds__(256, 2)
void G_block(const float* __restrict__ W_out,    const float* __restrict__ b_out,
             const float* __restrict__ bn_gamma, const float* __restrict__ bn_beta,
             const float* __restrict__ bn_mean,  const float* __restrict__ bn_var)
{
    __shared__ float sWo32[NF][NF];
    __shared__ float sWoX[196][NF];
    __shared__ float sGp[NA][NF];
    __shared__ float sam[96], sas[96];
    __shared__ float sbo[NF], sscale[NF], sshift[NF];
    const int tid = threadIdx.x;
    const int b = blockIdx.x >> 1, half = blockIdx.x & 1;
    const int v0 = half * HALF_V + tid * 2;
    const int warp = tid >> 5, lane = tid & 31;
    const int l = 10, pb = 0;

    pdl_trigger();   // let k2_tc prelaunch + stage its 136KB B-frags

    const float* WoG = W_out + (size_t)l * 228 * NF;
    ((float4*)&sWo32[0][0])[tid] = ((const float4*)WoG)[tid];
    {
        const float4* src = (const float4*)(WoG + 32 * NF);
        float4* dst = (float4*)&sWoX[0][0];
        for (int i = tid; i < 196 * NF / 4; i += 256) dst[i] = src[i];
    }
    if (tid >= 128 && tid < 160) {
        int j = tid - 128;
        sbo[j] = b_out[l * NF + j];
        float sc = bn_gamma[l * NF + j] * rsqrtf(bn_var[l * NF + j] + 1e-3f);
        sscale[j] = sc;
        sshift[j] = bn_beta[l * NF + j] - bn_mean[l * NF + j] * sc;
    }

    pdl_wait();

    const float* hb = g_h + ((size_t)b * 384 + (size_t)l * NF) * NV + v0;
    float2 wv[NA];
    #pragma unroll
    for (int a = 0; a < NA; a++)
        wv[a] = *(const float2*)(g_w + ((size_t)b * NA + a) * NV + v0);
    if (tid < 96) {
        float2 pm = *(const float2*)&g_pmax[pb][(b * 96 + tid) * 2];
        float2 ps = *(const float2*)&g_psum[pb][(b * 96 + tid) * 2];
        sam[tid] = fmaxf(pm.x, pm.y);
        sas[tid] = (ps.x + ps.y) * (1.0f / 1024.0f);
    }
    __syncthreads();
    if (tid < 128) {
        const int aa = warp, j = lane;
        float g = sWoX[192 + aa][j];
        #pragma unroll
        for (int c = 0; c < NC; c++)
            g += sam[aa * NC + c] * sWoX[aa * 48 + c][j];
        #pragma unroll
        for (int c = 0; c < NC; c++)
            g += sas[aa * NC + c] * sWoX[aa * 48 + NC + c][j];
        sGp[aa][j] = g;
    }
    __syncthreads();

    ull acc0[16], acc1[16];
    #pragma unroll
    for (int j = 0; j < 16; j++) {
        float2 bb = *(const float2*)&sbo[2 * j];
        ull p = pk2(bb.x, bb.y);
        acc0[j] = p; acc1[j] = p;
    }
    #pragma unroll
    for (int kc = 0; kc < 4; kc++) {
        float2 h2[8];
        #pragma unroll
        for (int k = 0; k < 8; k++)
            h2[k] = *(const float2*)(hb + (size_t)(kc * 8 + k) * NV);
        #pragma unroll
        for (int k = 0; k < 8; k++) {
            ull hk0 = dup2(h2[k].x), hk1 = dup2(h2[k].y);
            #pragma unroll
            for (int g8 = 0; g8 < 8; g8++) {
                F4U w; w.f = *(const float4*)&sWo32[kc * 8 + k][g8 * 4];
                fma2(acc0[g8 * 2],     hk0, w.u[0]); fma2(acc0[g8 * 2 + 1], hk0, w.u[1]);
                fma2(acc1[g8 * 2],     hk1, w.u[0]); fma2(acc1[g8 * 2 + 1], hk1, w.u[1]);
            }
        }
    }
    #pragma unroll
    for (int a = 0; a < NA; a++) {
        ull wa0 = dup2(wv[a].x), wa1 = dup2(wv[a].y);
        #pragma unroll
        for (int g8 = 0; g8 < 8; g8++) {
            F4U gg; gg.f = *(const float4*)&sGp[a][g8 * 4];
            fma2(acc0[g8 * 2],     wa0, gg.u[0]); fma2(acc0[g8 * 2 + 1], wa0, gg.u[1]);
            fma2(acc1[g8 * 2],     wa1, gg.u[0]); fma2(acc1[g8 * 2 + 1], wa1, gg.u[1]);
        }
    }
    float* ob = g_h + ((size_t)b * 384 + (size_t)11 * NF) * NV + v0;
    #pragma unroll
    for (int j2 = 0; j2 < 16; j2++) {
        float2 z0 = up2(acc0[j2]), z1 = up2(acc1[j2]);
        float sc0 = sscale[2 * j2], sh0 = sshift[2 * j2];
        float sc1 = sscale[2 * j2 + 1], sh1 = sshift[2 * j2 + 1];
        *(float2*)(ob + (size_t)(2 * j2) * NV) =
            make_float2(tanh_fast(z0.x) * sc0 + sh0, tanh_fast(z1.x) * sc0 + sh0);
        *(float2*)(ob + (size_t)(2 * j2 + 1) * NV) =
            make_float2(tanh_fast(z0.y) * sc1 + sh1, tanh_fast(z1.y) * sc1 + sh1);
    }
}

// =====================================================================
// k2_tc: out = relu(relu(F @ W_o0 + b0) @ W_o1 + b1) via 3xTF32 mma.sync.
// grid 256 (b=blk>>1, chunk=blk&1): CTA = 512 vertices processed as two
// 256-vertex halves reusing the staged B frags (staging amortized 2x).
// =====================================================================
#define NKT 44              // 352 / 8
#define NNT 6               // 48 / 8
#define BPK (NNT * NKT * 32)  // 8448 frag pairs

struct __align__(16) SmemK2T {
    float bph[BPK * 2];     // packed tf32 B hi-frags
    float bpl[BPK * 2];     // packed tf32 B lo-frags
    float sW1[144];
    float sb0[48];
    float sb1[4];
};

__global__ __launch_bounds__(256, 1)
void k2_tc(const float* __restrict__ W_o0, const float* __restrict__ b_o0,
           const float* __restrict__ W_o1, const float* __restrict__ b_o1,
           float* __restrict__ out)
{
    extern __shared__ char smraw[];
    SmemK2T& S = *reinterpret_cast<SmemK2T*>(smraw);
    const int tid = threadIdx.x;
    const int lane = tid & 31, warp = tid >> 5;
    const int gr = lane >> 2, gc = lane & 3;   // frag row/col indices

    pdl_trigger();

    // independent prologue: stage packed B frags (hi + lo residual)
    for (int i = tid; i < BPK; i += 256) {
        int ln = i & 31, rest = i >> 5;
        int kt = rest % NKT, nt = rest / NKT;
        int c = ln & 3, r = ln >> 2;
        int k0 = kt * 8, n0 = nt * 8;
        float w0 = W_o0[(k0 + c) * 48 + n0 + r];
        float w1 = W_o0[(k0 + c + 4) * 48 + n0 + r];
        unsigned h0, l0, h1, l1;
        split_tf32(w0, h0, l0);
        split_tf32(w1, h1, l1);
        *(uint2*)&S.bph[2 * i] = make_uint2(h0, h1);
        *(uint2*)&S.bpl[2 * i] = make_uint2(l0, l1);
    }
    if (tid < 144) S.sW1[tid] = W_o1[tid];
    if (tid >= 160 && tid < 208) S.sb0[tid - 160] = b_o0[tid - 160];
    if (tid >= 208 && tid < 211) S.sb1[tid - 208] = b_o1[tid - 208];
    __syncthreads();

    pdl_wait();   // g_h slot 11 must be complete

    const int b = blockIdx.x >> 1, chunk = blockIdx.x & 1;
    const float* fb = g_h + ((size_t)b * 384 + NF) * NV;

    #pragma unroll 1
    for (int vhalf = 0; vhalf < 2; vhalf++) {
        const int vb = chunk * 512 + vhalf * 256 + warp * 32;   // 32 verts/warp

        float d[2][NNT][4];
        #pragma unroll
        for (int t = 0; t < 2; t++)
            #pragma unroll
            for (int nt = 0; nt < NNT; nt++)
                #pragma unroll
                for (int q = 0; q < 4; q++) d[t][nt][q] = 0.0f;

        #pragma unroll 2
        for (int kt = 0; kt < NKT; kt++) {
            const int k0 = kt * 8;
            unsigned ah[2][4], al[2][4];
            #pragma unroll
            for (int t = 0; t < 2; t++) {
                const float* base = fb + (size_t)(k0 + gc) * NV + vb + t * 16 + gr;
                float f0 = base[0];
                float f1 = base[8];
                float f2 = base[(size_t)4 * NV];
                float f3 = base[(size_t)4 * NV + 8];
                split_tf32(f0, ah[t][0], al[t][0]);
                split_tf32(f1, ah[t][1], al[t][1]);
                split_tf32(f2, ah[t][2], al[t][2]);
                split_tf32(f3, ah[t][3], al[t][3]);
            }
            #pragma unroll
            for (int nt = 0; nt < NNT; nt++) {
                const int fi = 2 * ((nt * NKT + kt) * 32 + lane);
                uint2 bh = *(const uint2*)&S.bph[fi];
                uint2 bl = *(const uint2*)&S.bpl[fi];
                #pragma unroll
                for (int t = 0; t < 2; t++) {
                    mma_tf32(d[t][nt][0], d[t][nt][1], d[t][nt][2], d[t][nt][3],
                             ah[t][0], ah[t][1], ah[t][2], ah[t][3], bh.x, bh.y);
                    mma_tf32(d[t][nt][0], d[t][nt][1], d[t][nt][2], d[t][nt][3],
                             al[t][0], al[t][1], al[t][2], al[t][3], bh.x, bh.y);
                    mma_tf32(d[t][nt][0], d[t][nt][1], d[t][nt][2], d[t][nt][3],
                             ah[t][0], ah[t][1], ah[t][2], ah[t][3], bl.x, bl.y);
                }
            }
        }

        // epilogue: bias + relu + second layer (48 -> 3) + quad reduce
        #pragma unroll
        for (int t = 0; t < 2; t++) {
            float o0a = 0.0f, o1a = 0.0f, o2a = 0.0f;   // row gr
            float o0b = 0.0f, o1b = 0.0f, o2b = 0.0f;   // row gr+8
            #pragma unroll
            for (int nt = 0; nt < NNT; nt++) {
                const int n = nt * 8 + 2 * gc;
                float2 bb = *(const float2*)&S.sb0[n];
                float h0 = fmaxf(d[t][nt][0] + bb.x, 0.0f);
                float h1 = fmaxf(d[t][nt][1] + bb.y, 0.0f);
                float h2 = fmaxf(d[t][nt][2] + bb.x, 0.0f);
                float h3 = fmaxf(d[t][nt][3] + bb.y, 0.0f);
                const float* w1a = &S.sW1[n * 3];
                o0a += h0 * w1a[0] + h1 * w1a[3];
                o1a += h0 * w1a[1] + h1 * w1a[4];
                o2a += h0 * w1a[2] + h1 * w1a[5];
                o0b += h2 * w1a[0] + h3 * w1a[3];
                o1b += h2 * w1a[1] + h3 * w1a[4];
                o2b += h2 * w1a[2] + h3 * w1a[5];
            }
            #pragma unroll
            for (int o = 1; o <= 2; o <<= 1) {
                o0a += __shfl_xor_sync(~0u, o0a, o); o1a += __shfl_xor_sync(~0u, o1a, o);
                o2a += __shfl_xor_sync(~0u, o2a, o); o0b += __shfl_xor_sync(~0u, o0b, o);
                o1b += __shfl_xor_sync(~0u, o1b, o); o2b += __shfl_xor_sync(~0u, o2b, o);
            }
            if (gc == 0) {
                const int va = b * NV + vb + t * 16 + gr;
                float* opa = out + (size_t)va * 3;
                opa[0] = fmaxf(o0a + S.sb1[0], 0.0f);
                opa[1] = fmaxf(o1a + S.sb1[1], 0.0f);
                opa[2] = fmaxf(o2a + S.sb1[2], 0.0f);
                float* opb = out + (size_t)(va + 8) * 3;
                opb[0] = fmaxf(o0b + S.sb1[0], 0.0f);
                opb[1] = fmaxf(o1b + S.sb1[1], 0.0f);
                opb[2] = fmaxf(o2b + S.sb1[2], 0.0f);
            }
        }
    }
}

// =====================================================================
// host-side PDL launch helper
// =====================================================================
template <typename... Args>
static void launch_pdl(void (*kern)(Args...), dim3 grid, dim3 block,
                       size_t smem, Args... args)
{
    cudaLaunchConfig_t cfg = {};
    cfg.gridDim = grid;
    cfg.blockDim = block;
    cfg.dynamicSmemBytes = smem;
    cfg.stream = 0;
    cudaLaunchAttribute attr[1];
    attr[0].id = cudaLaunchAttributeProgrammaticStreamSerialization;
    attr[0].val.programmaticStreamSerializationAllowed = 1;
    cfg.attrs = attr;
    cfg.numAttrs = 1;
    cudaLaunchKernelEx(&cfg, kern, args...);
}

extern "C" void kernel_launch(void* const* d_in, const int* in_sizes, int n_in,
                              void* d_out, int out_size)
{
    const float* x         = (const float*)d_in[0];
    const float* bn0_gamma = (const float*)d_in[1];
    const float* bn0_beta  = (const float*)d_in[2];
    const float* bn0_mean  = (const float*)d_in[3];
    const float* bn0_var   = (const float*)d_in[4];
    const float* W_in      = (const float*)d_in[5];
    const float* b_in      = (const float*)d_in[6];
    const float* W_flr     = (const float*)d_in[7];
    const float* b_flr     = (const float*)d_in[8];
    const float* W_s       = (const float*)d_in[9];
    const float* b_s       = (const float*)d_in[10];
    const float* W_out     = (const float*)d_in[11];
    const float* b_out     = (const float*)d_in[12];
    const float* bn_gamma  = (const float*)d_in[13];
    const float* bn_beta   = (const float*)d_in[14];
    const float* bn_mean   = (const float*)d_in[15];
    const float* bn_var    = (const float*)d_in[16];
    const float* W_o0      = (const float*)d_in[17];
    const float* b_o0      = (const float*)d_in[18];
    const float* W_o1      = (const float*)d_in[19];
    const float* b_o1      = (const float*)d_in[20];

    cudaFuncSetAttribute(kB_fw, cudaFuncAttributeMaxDynamicSharedMemorySize,
                         (int)sizeof(SmemB));
    cudaFuncSetAttribute(F_block, cudaFuncAttributeMaxDynamicSharedMemorySize,
                         (int)sizeof(SmemF));
    cudaFuncSetAttribute(k2_tc, cudaFuncAttributeMaxDynamicSharedMemorySize,
                         (int)sizeof(SmemK2T));

    kB_fw<<<NB * 2, 256, sizeof(SmemB)>>>(x, bn0_gamma, bn0_var, bn0_beta, bn0_mean,
                                          W_in, b_in, W_flr, b_flr, W_s, b_s);

    for (int l = 0; l < NBK - 1; l++) {
        launch_pdl(F_block, dim3(NB * 2), dim3(256), sizeof(SmemF),
                   l, W_out, b_out, bn_gamma, bn_beta, bn_mean, bn_var,
                   W_flr, b_flr, W_s, b_s);
    }
    launch_pdl(G_block, dim3(NB * 2), dim3(256), (size_t)0,
               W_out, b_out, bn_gamma, bn_beta, bn_mean, bn_var);

    launch_pdl(k2_tc, dim3(NB * 2), dim3(256), sizeof(SmemK2T),
               W_o0, b_o0, W_o1, b_o1, (float*)d_out);
}

// round 15
// speedup vs baseline: 1.5525x; 1.0525x over previous
#include <cuda_runtime.h>
#include <math_constants.h>
#include <cstdint>
#include <cstddef>

// ---------------- problem constants ----------------
#define NB    128
#define NV    1024
#define NFEAT 10
#define NBK   11
#define NF    32
#define NP    20
#define NA    4
#define NC    24
#define DFE   352   // NBK*NF
#define HALF_V 512

// h ring: slot 0 = h0, slot l+1 = output of block l. layout g_h[b][s*32+k][v]
__device__ float g_h[(size_t)NB * 384 * NV];     // 201 MB
__device__ float g_w[(size_t)NB * NA * NV];      // per-block edge weights
__device__ float g_pmax[2][NB * 96 * 2];         // double-buffered partial max
__device__ float g_psum[2][NB * 96 * 2];         // double-buffered partial sum

// ---------------- PDL helpers ----------------
__device__ __forceinline__ void pdl_trigger() {
#if defined(__CUDA_ARCH__) && __CUDA_ARCH__ >= 900
    cudaTriggerProgrammaticLaunchCompletion();
#endif
}
__device__ __forceinline__ void pdl_wait() {
#if defined(__CUDA_ARCH__) && __CUDA_ARCH__ >= 900
    cudaGridDependencySynchronize();
#endif
}

// ---------------- f32x2 packed-math helpers ----------------
typedef unsigned long long ull;
__device__ __forceinline__ ull pk2(float a, float b) {
    ull r; asm("mov.b64 %0, {%1, %2};" : "=l"(r) : "f"(a), "f"(b)); return r;
}
__device__ __forceinline__ ull dup2(float a) { return pk2(a, a); }
__device__ __forceinline__ void fma2(ull& d, ull a, ull b) {
    asm("fma.rn.f32x2 %0, %1, %2, %0;" : "+l"(d) : "l"(a), "l"(b));
}
__device__ __forceinline__ ull mul2(ull a, ull b) {
    ull r; asm("mul.rn.f32x2 %0, %1, %2;" : "=l"(r) : "l"(a), "l"(b)); return r;
}
__device__ __forceinline__ ull add2(ull a, ull b) {
    ull r; asm("add.rn.f32x2 %0, %1, %2;" : "=l"(r) : "l"(a), "l"(b)); return r;
}
__device__ __forceinline__ float2 up2(ull v) {
    float2 r; asm("mov.b64 {%0, %1}, %2;" : "=f"(r.x), "=f"(r.y) : "l"(v)); return r;
}
union F4U { float4 f; ull u[2]; };

__device__ __forceinline__ float tanh_fast(float x) {
    float r; asm("tanh.approx.f32 %0, %1;" : "=f"(r) : "f"(x)); return r;
}
__device__ __forceinline__ unsigned to_tf32(float x) {
    unsigned r; asm("cvt.rna.tf32.f32 %0, %1;" : "=r"(r) : "f"(x)); return r;
}
__device__ __forceinline__ void split_tf32(float x, unsigned& hi, unsigned& lo) {
    hi = to_tf32(x);
    lo = to_tf32(x - __uint_as_float(hi));
}
__device__ __forceinline__ void mma_tf32(
    float& d0, float& d1, float& d2, float& d3,
    unsigned a0, unsigned a1, unsigned a2, unsigned a3,
    unsigned b0, unsigned b1)
{
    asm("mma.sync.aligned.m16n8k8.row.col.f32.tf32.tf32.f32 "
        "{%0,%1,%2,%3}, {%4,%5,%6,%7}, {%8,%9}, {%0,%1,%2,%3};"
        : "+f"(d0), "+f"(d1), "+f"(d2), "+f"(d3)
        : "r"(a0), "r"(a1), "r"(a2), "r"(a3), "r"(b0), "r"(b1));
}

// ---------------- 2-vertex shared helpers ----------------
template<bool BN>
__device__ __forceinline__ void stream_epi_fw2(
    ull acc0[16], ull acc1[16],
    const float* __restrict__ sscale, const float* __restrict__ sshift,
    const float (*__restrict__ sWfw)[NC], const float* __restrict__ sbfw,
    float* __restrict__ ob, ull facc0[12], ull facc1[12])
{
    #pragma unroll
    for (int j = 0; j < 12; j++) {
        float2 bb = *(const float2*)&sbfw[2 * j];
        ull p = pk2(bb.x, bb.y);
        facc0[j] = p; facc1[j] = p;
    }
    #pragma unroll
    for (int j2 = 0; j2 < 16; j2++) {
        float2 z0 = up2(acc0[j2]), z1 = up2(acc1[j2]);
        float a00 = tanh_fast(z0.x), a01 = tanh_fast(z0.y);
        float a10 = tanh_fast(z1.x), a11 = tanh_fast(z1.y);
        if (BN) {
            float sc0 = sscale[2 * j2], sh0 = sshift[2 * j2];
            float sc1 = sscale[2 * j2 + 1], sh1 = sshift[2 * j2 + 1];
            a00 = a00 * sc0 + sh0; a10 = a10 * sc0 + sh0;
            a01 = a01 * sc1 + sh1; a11 = a11 * sc1 + sh1;
        }
        *(float2*)(ob + (size_t)(2 * j2) * NV)     = make_float2(a00, a10);
        *(float2*)(ob + (size_t)(2 * j2 + 1) * NV) = make_float2(a01, a11);
        ull d00 = dup2(a00), d01 = dup2(a01), d10 = dup2(a10), d11 = dup2(a11);
        #pragma unroll
        for (int g6 = 0; g6 < 6; g6++) {
            F4U w0; w0.f = *(const float4*)&sWfw[2 * j2][g6 * 4];
            F4U w1; w1.f = *(const float4*)&sWfw[2 * j2 + 1][g6 * 4];
            fma2(facc0[2 * g6],     d00, w0.u[0]); fma2(facc0[2 * g6 + 1], d00, w0.u[1]);
            fma2(facc0[2 * g6],     d01, w1.u[0]); fma2(facc0[2 * g6 + 1], d01, w1.u[1]);
            fma2(facc1[2 * g6],     d10, w0.u[0]); fma2(facc1[2 * g6 + 1], d10, w0.u[1]);
            fma2(facc1[2 * g6],     d11, w1.u[0]); fma2(facc1[2 * g6 + 1], d11, w1.u[1]);
        }
    }
}

__device__ __forceinline__ void fw_finish2(
    ull facc0[12], ull facc1[12], float (*__restrict__ sbuf)[HALF_V], int tid,
    float* __restrict__ gw)
{
    #pragma unroll
    for (int j = 0; j < 10; j++) {
        float2 f0 = up2(facc0[j]), f1 = up2(facc1[j]);
        *(float2*)&sbuf[2 * j][2 * tid]     = make_float2(f0.x, f1.x);
        *(float2*)&sbuf[2 * j + 1][2 * tid] = make_float2(f0.y, f1.y);
    }
    float2 p0 = up2(facc0[10]), q0 = up2(facc0[11]);
    float2 p1 = up2(facc1[10]), q1 = up2(facc1[11]);
    float w0a = __expf(-fabsf(p0.x)), w0b = __expf(-fabsf(p0.y));
    float w0c = __expf(-fabsf(q0.x)), w0d = __expf(-fabsf(q0.y));
    float w1a = __expf(-fabsf(p1.x)), w1b = __expf(-fabsf(p1.y));
    float w1c = __expf(-fabsf(q1.x)), w1d = __expf(-fabsf(q1.y));
    *(float2*)&sbuf[20][2 * tid] = make_float2(w0a, w1a);
    *(float2*)&sbuf[21][2 * tid] = make_float2(w0b, w1b);
    *(float2*)&sbuf[22][2 * tid] = make_float2(w0c, w1c);
    *(float2*)&sbuf[23][2 * tid] = make_float2(w0d, w1d);
    *(float2*)(gw)                    = make_float2(w0a, w1a);
    *(float2*)(gw + (size_t)NV)       = make_float2(w0b, w1b);
    *(float2*)(gw + (size_t)2 * NV)   = make_float2(w0c, w1c);
    *(float2*)(gw + (size_t)3 * NV)   = make_float2(w0d, w1d);
}

// 96 max/sum tasks over 512 vertices; warp w -> aa = w>>1, c = (w&1)*12..+12
__device__ __forceinline__ void reduce96_2(
    const float (*__restrict__ sbuf)[HALF_V], int b, int half, int warp, int lane,
    int pb)
{
    const int aa = warp >> 1, cbase = (warp & 1) * 12;
    ull s2[12]; float m0[12], m1[12];
    #pragma unroll
    for (int c = 0; c < 12; c++) { s2[c] = 0ull; m0[c] = -CUDART_INF_F; m1[c] = -CUDART_INF_F; }
    #pragma unroll
    for (int i = 0; i < 8; i++) {
        const int vv = (lane + i * 32) * 2;
        ull w2 = *(const ull*)&sbuf[NP + aa][vv];
        #pragma unroll
        for (int c = 0; c < 12; c++) {
            ull f2 = *(const ull*)&sbuf[cbase + c][vv];
            ull p = mul2(w2, f2);
            s2[c] = add2(s2[c], p);
            float2 pv = up2(p);
            m0[c] = fmaxf(m0[c], pv.x);
            m1[c] = fmaxf(m1[c], pv.y);
        }
    }
    #pragma unroll
    for (int c = 0; c < 12; c++) {
        float m = fmaxf(m0[c], m1[c]);
        float2 sv = up2(s2[c]);
        float s = sv.x + sv.y;
        #pragma unroll
        for (int o = 16; o > 0; o >>= 1) {
            m = fmaxf(m, __shfl_xor_sync(~0u, m, o));
            s += __shfl_xor_sync(~0u, s, o);
        }
        if (lane == 0) {
            const int t = aa * 24 + cbase + c;
            g_pmax[pb][(b * 96 + t) * 2 + half] = m;
            g_psum[pb][(b * 96 + t) * 2 + half] = s;
        }
    }
}

// =====================================================================
// kB_fw: event mean (computed in-CTA) + h0 = tanh(bn0(x)@W_in + cbias)
// -> slot 0, fused fw(block 0). grid 256 (b=blk>>1, half=blk&1), 256 thr
// =====================================================================
struct __align__(16) SmemB {
    float sbuf[NC][HALF_V];
    float sW[NFEAT][NF];
    float sWfw[NF][NC];
    float scb[NF];
    float ss0[20], st0[20];
    float sbfw[NC];
    float sp[8][12];
    float smean[12];
};

__global__ __launch_bounds__(256, 2)
void kB_fw(const float* __restrict__ x,
           const float* __restrict__ bn0_gamma, const float* __restrict__ bn0_var,
           const float* __restrict__ bn0_beta,  const float* __restrict__ bn0_mean,
           const float* __restrict__ W_in,      const float* __restrict__ b_in,
           const float* __restrict__ W_flr, const float* __restrict__ b_flr,
           const float* __restrict__ W_s,   const float* __restrict__ b_s)
{
    extern __shared__ char smraw[];
    SmemB& S = *reinterpret_cast<SmemB*>(smraw);
    const int tid = threadIdx.x;
    const int b = blockIdx.x >> 1, half = blockIdx.x & 1;
    const int v0 = half * HALF_V + tid * 2;
    const int warp = tid >> 5, lane = tid & 31;

    pdl_trigger();   // allow F(0) to prelaunch and stage its weights

    // per-event vertex mean (each CTA computes it for its event; cheap)
    {
        float s[NFEAT];
        #pragma unroll
        for (int c = 0; c < NFEAT; c++) s[c] = 0.0f;
        #pragma unroll
        for (int i = 0; i < 4; i++) {
            const float* xv = x + ((size_t)b * NV + tid + i * 256) * NFEAT;
            #pragma unroll
            for (int c = 0; c < NFEAT; c++) s[c] += xv[c];
        }
        #pragma unroll
        for (int o = 16; o > 0; o >>= 1)
            #pragma unroll
            for (int c = 0; c < NFEAT; c++) s[c] += __shfl_xor_sync(~0u, s[c], o);
        if (lane == 0)
            #pragma unroll
            for (int c = 0; c < NFEAT; c++) S.sp[warp][c] = s[c];
    }

    const float* xv0 = x + ((size_t)b * NV + v0) * NFEAT;
    float xr0[NFEAT], xr1[NFEAT];
    #pragma unroll
    for (int c = 0; c < NFEAT; c++) { xr0[c] = xv0[c]; xr1[c] = xv0[NFEAT + c]; }

    for (int i = tid; i < NFEAT * NF; i += 256) S.sW[i / NF][i % NF] = W_in[i];
    for (int i = tid; i < NF * NC; i += 256) {
        int k = i / NC, c = i % NC;
        S.sWfw[k][c] = (c < NP) ? W_flr[(size_t)k * NP + c] : W_s[(size_t)k * NA + (c - NP)];
    }
    if (tid >= 32 && tid < 52) {
        int c = tid - 32;
        float sc = bn0_gamma[c] * rsqrtf(bn0_var[c] + 1e-3f);
        S.ss0[c] = sc;
        S.st0[c] = bn0_beta[c] - bn0_mean[c] * sc;
    }
    if (tid >= 64 && tid < 64 + NC)
        S.sbfw[tid - 64] = (tid - 64 < NP) ? b_flr[tid - 64] : b_s[tid - 64 - NP];
    __syncthreads();
    if (tid < NFEAT) {
        float a = 0.0f;
        #pragma unroll
        for (int w = 0; w < 8; w++) a += S.sp[w][tid];
        S.smean[tid] = a * (1.0f / 1024.0f);
    }
    __syncthreads();
    if (tid < NF) {   // fold mean-half of gex + b_in into per-event constant bias
        float a = b_in[tid];
        #pragma unroll
        for (int c = 10; c < 20; c++) {
            float g = S.smean[c - 10] * S.ss0[c] + S.st0[c];
            a += g * W_in[c * NF + tid];
        }
        S.scb[tid] = a;
    }
    __syncthreads();

    ull acc0[16], acc1[16];
    #pragma unroll
    for (int j = 0; j < 16; j++) {
        float2 bb = *(const float2*)&S.scb[2 * j];
        ull p = pk2(bb.x, bb.y);
        acc0[j] = p; acc1[j] = p;
    }
    #pragma unroll
    for (int c = 0; c < NFEAT; c++) {
        float sc = S.ss0[c], sh = S.st0[c];
        ull g0 = dup2(xr0[c] * sc + sh);
        ull g1 = dup2(xr1[c] * sc + sh);
        #pragma unroll
        for (int g8 = 0; g8 < 8; g8++) {
            F4U w; w.f = *(const float4*)&S.sW[c][g8 * 4];
            fma2(acc0[g8 * 2],     g0, w.u[0]); fma2(acc0[g8 * 2 + 1], g0, w.u[1]);
            fma2(acc1[g8 * 2],     g1, w.u[0]); fma2(acc1[g8 * 2 + 1], g1, w.u[1]);
        }
    }
    float* ob = g_h + (size_t)b * 384 * NV + v0;
    ull facc0[12], facc1[12];
    stream_epi_fw2<false>(acc0, acc1, nullptr, nullptr, S.sWfw, S.sbfw, ob, facc0, facc1);
    fw_finish2(facc0, facc1, S.sbuf, tid, g_w + ((size_t)b * NA) * NV + v0);
    __syncthreads();
    reduce96_2(S.sbuf, b, half, warp, lane, 0);
}

// =====================================================================
// F: fused block: Gp(l) -> out(l) -> h_{l+1} -> fw(l+1) -> partials
// Full W_out rows 32..227 staged in the PDL-hidden prologue.
// =====================================================================
struct __align__(16) SmemF {
    float sbuf[NC][HALF_V];
    float sWo32[NF][NF];
    float sWoX[196][NF];     // W_out rows 32..227 (PDL-hidden staging)
    float sWfw[NF][NC];
    float sGp[NA][NF];
    float sam[96], sas[96];
    float sbfw[NC];
    float sbo[NF], sscale[NF], sshift[NF];
};

__global__ __launch_bounds__(256, 2)
void F_block(int l,
             const float* __restrict__ W_out,    const float* __restrict__ b_out,
             const float* __restrict__ bn_gamma, const float* __restrict__ bn_beta,
             const float* __restrict__ bn_mean,  const float* __restrict__ bn_var,
             const float* __restrict__ W_flr,    const float* __restrict__ b_flr,
             const float* __restrict__ W_s,      const float* __restrict__ b_s)
{
    extern __shared__ char smraw[];
    SmemF& S = *reinterpret_cast<SmemF*>(smraw);
    const int tid = threadIdx.x;
    const int b = blockIdx.x >> 1, half = blockIdx.x & 1;
    const int v0 = half * HALF_V + tid * 2;
    const int warp = tid >> 5, lane = tid & 31;
    const int pb = l & 1, lf = l + 1;

    pdl_trigger();   // let the next kernel prelaunch + stage its weights

    // ---- independent prologue: stage weights/biases (kernel inputs only) ----
    const float* WoG = W_out + (size_t)l * 228 * NF;
    ((float4*)&S.sWo32[0][0])[tid] = ((const float4*)WoG)[tid];   // rows 0..31
    {
        const float4* src = (const float4*)(WoG + 32 * NF);
        float4* dst = (float4*)&S.sWoX[0][0];
        for (int i = tid; i < 196 * NF / 4; i += 256) dst[i] = src[i];
    }
    for (int i = tid; i < NF * NC; i += 256) {
        int k = i / NC, c = i % NC;
        S.sWfw[k][c] = (c < NP) ? W_flr[((size_t)lf * NF + k) * NP + c]
                                : W_s[((size_t)lf * NF + k) * NA + (c - NP)];
    }
    if (tid >= 128 && tid < 160) {
        int j = tid - 128;
        S.sbo[j] = b_out[l * NF + j];
        float sc = bn_gamma[l * NF + j] * rsqrtf(bn_var[l * NF + j] + 1e-3f);
        S.sscale[j] = sc;
        S.sshift[j] = bn_beta[l * NF + j] - bn_mean[l * NF + j] * sc;
    }
    if (tid >= 160 && tid < 160 + NC)
        S.sbfw[tid - 160] = (tid - 160 < NP) ? b_flr[lf * NP + tid - 160]
                                             : b_s[lf * NA + tid - 160 - NP];

    // ---- dependent data: wait for predecessor grid ----
    pdl_wait();

    const float* hb = g_h + ((size_t)b * 384 + (size_t)l * NF) * NV + v0;
    float2 wv[NA];
    #pragma unroll
    for (int a = 0; a < NA; a++)
        wv[a] = *(const float2*)(g_w + ((size_t)b * NA + a) * NV + v0);
    if (tid < 96) {
        float2 pm = *(const float2*)&g_pmax[pb][(b * 96 + tid) * 2];
        float2 ps = *(const float2*)&g_psum[pb][(b * 96 + tid) * 2];
        S.sam[tid] = fmaxf(pm.x, pm.y);
        S.sas[tid] = (ps.x + ps.y) * (1.0f / 1024.0f);
    }
    __syncthreads();

    if (tid < 128) {   // Gp from smem-staged W_out rows (rowX = row-32)
        const int aa = warp, j = lane;
        float g = S.sWoX[192 + aa][j];                 // row 224+aa
        #pragma unroll
        for (int c = 0; c < NC; c++)
            g += S.sam[aa * NC + c] * S.sWoX[aa * 48 + c][j];
        #pragma unroll
        for (int c = 0; c < NC; c++)
            g += S.sas[aa * NC + c] * S.sWoX[aa * 48 + NC + c][j];
        S.sGp[aa][j] = g;
    }
    __syncthreads();

    ull acc0[16], acc1[16];
    #pragma unroll
    for (int j = 0; j < 16; j++) {
        float2 bb = *(const float2*)&S.sbo[2 * j];
        ull p = pk2(bb.x, bb.y);
        acc0[j] = p; acc1[j] = p;
    }
    #pragma unroll
    for (int kc = 0; kc < 4; kc++) {
        float2 h2[8];
        #pragma unroll
        for (int k = 0; k < 8; k++)
            h2[k] = *(const float2*)(hb + (size_t)(kc * 8 + k) * NV);
        #pragma unroll
        for (int k = 0; k < 8; k++) {
            ull hk0 = dup2(h2[k].x), hk1 = dup2(h2[k].y);
            #pragma unroll
            for (int g8 = 0; g8 < 8; g8++) {
                F4U w; w.f = *(const float4*)&S.sWo32[kc * 8 + k][g8 * 4];
                fma2(acc0[g8 * 2],     hk0, w.u[0]); fma2(acc0[g8 * 2 + 1], hk0, w.u[1]);
                fma2(acc1[g8 * 2],     hk1, w.u[0]); fma2(acc1[g8 * 2 + 1], hk1, w.u[1]);
            }
        }
    }
    #pragma unroll
    for (int a = 0; a < NA; a++) {
        ull wa0 = dup2(wv[a].x), wa1 = dup2(wv[a].y);
        #pragma unroll
        for (int g8 = 0; g8 < 8; g8++) {
            F4U gg; gg.f = *(const float4*)&S.sGp[a][g8 * 4];
            fma2(acc0[g8 * 2],     wa0, gg.u[0]); fma2(acc0[g8 * 2 + 1], wa0, gg.u[1]);
            fma2(acc1[g8 * 2],     wa1, gg.u[0]); fma2(acc1[g8 * 2 + 1], wa1, gg.u[1]);
        }
    }

    float* ob = g_h + ((size_t)b * 384 + (size_t)lf * NF) * NV + v0;
    ull facc0[12], facc1[12];
    stream_epi_fw2<true>(acc0, acc1, S.sscale, S.sshift, S.sWfw, S.sbfw, ob, facc0, facc1);
    fw_finish2(facc0, facc1, S.sbuf, tid, g_w + ((size_t)b * NA) * NV + v0);
    __syncthreads();
    reduce96_2(S.sbuf, b, half, warp, lane, pb ^ 1);
}

// =====================================================================
// G: final block (l=10): out only. writes slot 11
// =====================================================================
__global__ __launch_bounds__(256, 2)
void G_block(const float* __restrict__ W_out,    const float* __restrict__ b_out,
             const float* __restrict__ bn_gamma, const float* __restrict__ bn_beta,
             const float* __restrict__ bn_mean,  const float* __restrict__ bn_var)
{
    __shared__ float sWo32[NF][NF];
    __shared__ float sWoX[196][NF];
    __shared__ float sGp[NA][NF];
    __shared__ float sam[96], sas[96];
    __shared__ float sbo[NF], sscale[NF], sshift[NF];
    const int tid = threadIdx.x;
    const int b = blockIdx.x >> 1, half = blockIdx.x & 1;
    const int v0 = half * HALF_V + tid * 2;
    const int warp = tid >> 5, lane = tid & 31;
    const int l = 10, pb = 0;

    pdl_trigger();   // let k2_tc prelaunch + stage its 136KB B-frags

    const float* WoG = W_out + (size_t)l * 228 * NF;
    ((float4*)&sWo32[0][0])[tid] = ((const float4*)WoG)[tid];
    {
        const float4* src = (const float4*)(WoG + 32 * NF);
        float4* dst = (float4*)&sWoX[0][0];
        for (int i = tid; i < 196 * NF / 4; i += 256) dst[i] = src[i];
    }
    if (tid >= 128 && tid < 160) {
        int j = tid - 128;
        sbo[j] = b_out[l * NF + j];
        float sc = bn_gamma[l * NF + j] * rsqrtf(bn_var[l * NF + j] + 1e-3f);
        sscale[j] = sc;
        sshift[j] = bn_beta[l * NF + j] - bn_mean[l * NF + j] * sc;
    }

    pdl_wait();

    const float* hb = g_h + ((size_t)b * 384 + (size_t)l * NF) * NV + v0;
    float2 wv[NA];
    #pragma unroll
    for (int a = 0; a < NA; a++)
        wv[a] = *(const float2*)(g_w + ((size_t)b * NA + a) * NV + v0);
    if (tid < 96) {
        float2 pm = *(const float2*)&g_pmax[pb][(b * 96 + tid) * 2];
        float2 ps = *(const float2*)&g_psum[pb][(b * 96 + tid) * 2];
        sam[tid] = fmaxf(pm.x, pm.y);
        sas[tid] = (ps.x + ps.y) * (1.0f / 1024.0f);
    }
    __syncthreads();
    if (tid < 128) {
        const int aa = warp, j = lane;
        float g = sWoX[192 + aa][j];
        #pragma unroll
        for (int c = 0; c < NC; c++)
            g += sam[aa * NC + c] * sWoX[aa * 48 + c][j];
        #pragma unroll
        for (int c = 0; c < NC; c++)
            g += sas[aa * NC + c] * sWoX[aa * 48 + NC + c][j];
        sGp[aa][j] = g;
    }
    __syncthreads();

    ull acc0[16], acc1[16];
    #pragma unroll
    for (int j = 0; j < 16; j++) {
        float2 bb = *(const float2*)&sbo[2 * j];
        ull p = pk2(bb.x, bb.y);
        acc0[j] = p; acc1[j] = p;
    }
    #pragma unroll
    for (int kc = 0; kc < 4; kc++) {
        float2 h2[8];
        #pragma unroll
        for (int k = 0; k < 8; k++)
            h2[k] = *(const float2*)(hb + (size_t)(kc * 8 + k) * NV);
        #pragma unroll
        for (int k = 0; k < 8; k++) {
            ull hk0 = dup2(h2[k].x), hk1 = dup2(h2[k].y);
            #pragma unroll
            for (int g8 = 0; g8 < 8; g8++) {
                F4U w; w.f = *(const float4*)&sWo32[kc * 8 + k][g8 * 4];
                fma2(acc0[g8 * 2],     hk0, w.u[0]); fma2(acc0[g8 * 2 + 1], hk0, w.u[1]);
                fma2(acc1[g8 * 2],     hk1, w.u[0]); fma2(acc1[g8 * 2 + 1], hk1, w.u[1]);
            }
        }
    }
    #pragma unroll
    for (int a = 0; a < NA; a++) {
        ull wa0 = dup2(wv[a].x), wa1 = dup2(wv[a].y);
        #pragma unroll
        for (int g8 = 0; g8 < 8; g8++) {
            F4U gg; gg.f = *(const float4*)&sGp[a][g8 * 4];
            fma2(acc0[g8 * 2],     wa0, gg.u[0]); fma2(acc0[g8 * 2 + 1], wa0, gg.u[1]);
            fma2(acc1[g8 * 2],     wa1, gg.u[0]); fma2(acc1[g8 * 2 + 1], wa1, gg.u[1]);
        }
    }
    float* ob = g_h + ((size_t)b * 384 + (size_t)11 * NF) * NV + v0;
    #pragma unroll
    for (int j2 = 0; j2 < 16; j2++) {
        float2 z0 = up2(acc0[j2]), z1 = up2(acc1[j2]);
        float sc0 = sscale[2 * j2], sh0 = sshift[2 * j2];
        float sc1 = sscale[2 * j2 + 1], sh1 = sshift[2 * j2 + 1];
        *(float2*)(ob + (size_t)(2 * j2) * NV) =
            make_float2(tanh_fast(z0.x) * sc0 + sh0, tanh_fast(z1.x) * sc0 + sh0);
        *(float2*)(ob + (size_t)(2 * j2 + 1) * NV) =
            make_float2(tanh_fast(z0.y) * sc1 + sh1, tanh_fast(z1.y) * sc1 + sh1);
    }
}

// =====================================================================
// k2_tc: out = relu(relu(F @ W_o0 + b0) @ W_o1 + b1) via 3xTF32 mma.sync.
// grid 128 (1 CTA = 1 event), 512 threads = 16 warps (4/SMSP latency
// hiding), B-frag staging paid once per SM; two 512-vertex halves.
// =====================================================================
#define NKT 44              // 352 / 8
#define NNT 6               // 48 / 8
#define BPK (NNT * NKT * 32)  // 8448 frag pairs

struct __align__(16) SmemK2T {
    float bph[BPK * 2];     // packed tf32 B hi-frags
    float bpl[BPK * 2];     // packed tf32 B lo-frags
    float sW1[144];
    float sb0[48];
    float sb1[4];
};

__global__ __launch_bounds__(512, 1)
void k2_tc(const float* __restrict__ W_o0, const float* __restrict__ b_o0,
           const float* __restrict__ W_o1, const float* __restrict__ b_o1,
           float* __restrict__ out)
{
    extern __shared__ char smraw[];
    SmemK2T& S = *reinterpret_cast<SmemK2T*>(smraw);
    const int tid = threadIdx.x;
    const int lane = tid & 31, warp = tid >> 5;   // warp 0..15
    const int gr = lane >> 2, gc = lane & 3;      // frag row/col indices

    pdl_trigger();

    // independent prologue: stage packed B frags (hi + lo residual)
    for (int i = tid; i < BPK; i += 512) {
        int ln = i & 31, rest = i >> 5;
        int kt = rest % NKT, nt = rest / NKT;
        int c = ln & 3, r = ln >> 2;
        int k0 = kt * 8, n0 = nt * 8;
        float w0 = W_o0[(k0 + c) * 48 + n0 + r];
        float w1 = W_o0[(k0 + c + 4) * 48 + n0 + r];
        unsigned h0, l0, h1, l1;
        split_tf32(w0, h0, l0);
        split_tf32(w1, h1, l1);
        *(uint2*)&S.bph[2 * i] = make_uint2(h0, h1);
        *(uint2*)&S.bpl[2 * i] = make_uint2(l0, l1);
    }
    if (tid < 144) S.sW1[tid] = W_o1[tid];
    if (tid >= 160 && tid < 208) S.sb0[tid - 160] = b_o0[tid - 160];
    if (tid >= 208 && tid < 211) S.sb1[tid - 208] = b_o1[tid - 208];
    __syncthreads();

    pdl_wait();   // g_h slot 11 must be complete

    const int b = blockIdx.x;
    const float* fb = g_h + ((size_t)b * 384 + NF) * NV;

    #pragma unroll 1
    for (int vhalf = 0; vhalf < 2; vhalf++) {
        const int vb = vhalf * 512 + warp * 32;   // 32 vertices per warp

        float d[2][NNT][4];
        #pragma unroll
        for (int t = 0; t < 2; t++)
            #pragma unroll
            for (int nt = 0; nt < NNT; nt++)
                #pragma unroll
                for (int q = 0; q < 4; q++) d[t][nt][q] = 0.0f;

        #pragma unroll 2
        for (int kt = 0; kt < NKT; kt++) {
            const int k0 = kt * 8;
            unsigned ah[2][4], al[2][4];
            #pragma unroll
            for (int t = 0; t < 2; t++) {
                const float* base = fb + (size_t)(k0 + gc) * NV + vb + t * 16 + gr;
                float f0 = base[0];
                float f1 = base[8];
                float f2 = base[(size_t)4 * NV];
                float f3 = base[(size_t)4 * NV + 8];
                split_tf32(f0, ah[t][0], al[t][0]);
                split_tf32(f1, ah[t][1], al[t][1]);
                split_tf32(f2, ah[t][2], al[t][2]);
                split_tf32(f3, ah[t][3], al[t][3]);
            }
            #pragma unroll
            for (int nt = 0; nt < NNT; nt++) {
                const int fi = 2 * ((nt * NKT + kt) * 32 + lane);
                uint2 bh = *(const uint2*)&S.bph[fi];
                uint2 bl = *(const uint2*)&S.bpl[fi];
                #pragma unroll
                for (int t = 0; t < 2; t++) {
                    mma_tf32(d[t][nt][0], d[t][nt][1], d[t][nt][2], d[t][nt][3],
                             ah[t][0], ah[t][1], ah[t][2], ah[t][3], bh.x, bh.y);
                    mma_tf32(d[t][nt][0], d[t][nt][1], d[t][nt][2], d[t][nt][3],
                             al[t][0], al[t][1], al[t][2], al[t][3], bh.x, bh.y);
                    mma_tf32(d[t][nt][0], d[t][nt][1], d[t][nt][2], d[t][nt][3],
                             ah[t][0], ah[t][1], ah[t][2], ah[t][3], bl.x, bl.y);
                }
            }
        }

        // epilogue: bias + relu + second layer (48 -> 3) + quad reduce
        #pragma unroll
        for (int t = 0; t < 2; t++) {
            float o0a = 0.0f, o1a = 0.0f, o2a = 0.0f;   // row gr
            float o0b = 0.0f, o1b = 0.0f, o2b = 0.0f;   // row gr+8
            #pragma unroll
            for (int nt = 0; nt < NNT; nt++) {
                const int n = nt * 8 + 2 * gc;
                float2 bb = *(const float2*)&S.sb0[n];
                float h0 = fmaxf(d[t][nt][0] + bb.x, 0.0f);
                float h1 = fmaxf(d[t][nt][1] + bb.y, 0.0f);
                float h2 = fmaxf(d[t][nt][2] + bb.x, 0.0f);
                float h3 = fmaxf(d[t][nt][3] + bb.y, 0.0f);
                const float* w1a = &S.sW1[n * 3];
                o0a += h0 * w1a[0] + h1 * w1a[3];
                o1a += h0 * w1a[1] + h1 * w1a[4];
                o2a += h0 * w1a[2] + h1 * w1a[5];
                o0b += h2 * w1a[0] + h3 * w1a[3];
                o1b += h2 * w1a[1] + h3 * w1a[4];
                o2b += h2 * w1a[2] + h3 * w1a[5];
            }
            #pragma unroll
            for (int o = 1; o <= 2; o <<= 1) {
                o0a += __shfl_xor_sync(~0u, o0a, o); o1a += __shfl_xor_sync(~0u, o1a, o);
                o2a += __shfl_xor_sync(~0u, o2a, o); o0b += __shfl_xor_sync(~0u, o0b, o);
                o1b += __shfl_xor_sync(~0u, o1b, o); o2b += __shfl_xor_sync(~0u, o2b, o);
            }
            if (gc == 0) {
                const int va = b * NV + vb + t * 16 + gr;
                float* opa = out + (size_t)va * 3;
                opa[0] = fmaxf(o0a + S.sb1[0], 0.0f);
                opa[1] = fmaxf(o1a + S.sb1[1], 0.0f);
                opa[2] = fmaxf(o2a + S.sb1[2], 0.0f);
                float* opb = out + (size_t)(va + 8) * 3;
                opb[0] = fmaxf(o0b + S.sb1[0], 0.0f);
                opb[1] = fmaxf(o1b + S.sb1[1], 0.0f);
                opb[2] = fmaxf(o2b + S.sb1[2], 0.0f);
            }
        }
    }
}

// =====================================================================
// host-side PDL launch helper
// =====================================================================
template <typename... Args>
static void launch_pdl(void (*kern)(Args...), dim3 grid, dim3 block,
                       size_t smem, Args... args)
{
    cudaLaunchConfig_t cfg = {};
    cfg.gridDim = grid;
    cfg.blockDim = block;
    cfg.dynamicSmemBytes = smem;
    cfg.stream = 0;
    cudaLaunchAttribute attr[1];
    attr[0].id = cudaLaunchAttributeProgrammaticStreamSerialization;
    attr[0].val.programmaticStreamSerializationAllowed = 1;
    cfg.attrs = attr;
    cfg.numAttrs = 1;
    cudaLaunchKernelEx(&cfg, kern, args...);
}

extern "C" void kernel_launch(void* const* d_in, const int* in_sizes, int n_in,
                              void* d_out, int out_size)
{
    const float* x         = (const float*)d_in[0];
    const float* bn0_gamma = (const float*)d_in[1];
    const float* bn0_beta  = (const float*)d_in[2];
    const float* bn0_mean  = (const float*)d_in[3];
    const float* bn0_var   = (const float*)d_in[4];
    const float* W_in      = (const float*)d_in[5];
    const float* b_in      = (const float*)d_in[6];
    const float* W_flr     = (const float*)d_in[7];
    const float* b_flr     = (const float*)d_in[8];
    const float* W_s       = (const float*)d_in[9];
    const float* b_s       = (const float*)d_in[10];
    const float* W_out     = (const float*)d_in[11];
    const float* b_out     = (const float*)d_in[12];
    const float* bn_gamma  = (const float*)d_in[13];
    const float* bn_beta   = (const float*)d_in[14];
    const float* bn_mean   = (const float*)d_in[15];
    const float* bn_var    = (const float*)d_in[16];
    const float* W_o0      = (const float*)d_in[17];
    const float* b_o0      = (const float*)d_in[18];
    const float* W_o1      = (const float*)d_in[19];
    const float* b_o1      = (const float*)d_in[20];

    cudaFuncSetAttribute(kB_fw, cudaFuncAttributeMaxDynamicSharedMemorySize,
                         (int)sizeof(SmemB));
    cudaFuncSetAttribute(F_block, cudaFuncAttributeMaxDynamicSharedMemorySize,
                         (int)sizeof(SmemF));
    cudaFuncSetAttribute(k2_tc, cudaFuncAttributeMaxDynamicSharedMemorySize,
                         (int)sizeof(SmemK2T));

    kB_fw<<<NB * 2, 256, sizeof(SmemB)>>>(x, bn0_gamma, bn0_var, bn0_beta, bn0_mean,
                                          W_in, b_in, W_flr, b_flr, W_s, b_s);

    for (int l = 0; l < NBK - 1; l++) {
        launch_pdl(F_block, dim3(NB * 2), dim3(256), sizeof(SmemF),
                   l, W_out, b_out, bn_gamma, bn_beta, bn_mean, bn_var,
                   W_flr, b_flr, W_s, b_s);
    }
    launch_pdl(G_block, dim3(NB * 2), dim3(256), (size_t)0,
               W_out, b_out, bn_gamma, bn_beta, bn_mean, bn_var);

    launch_pdl(k2_tc, dim3(NB), dim3(512), sizeof(SmemK2T),
               W_o0, b_o0, W_o1, b_o1, (float*)d_out);
}

// round 16
// speedup vs baseline: 1.5612x; 1.0056x over previous
#include <cuda_runtime.h>
#include <math_constants.h>
#include <cstdint>
#include <cstddef>

// ---------------- problem constants ----------------
#define NB    128
#define NV    1024
#define NFEAT 10
#define NBK   11
#define NF    32
#define NP    20
#define NA    4
#define NC    24
#define DFE   352   // NBK*NF
#define HALF_V 512

// h ring: slot 0 = h0, slot l+1 = output of block l. layout g_h[b][s*32+k][v]
__device__ float g_h[(size_t)NB * 384 * NV];     // 201 MB
__device__ float g_w[(size_t)NB * NA * NV];      // per-block edge weights
__device__ float g_pmax[2][NB * 96 * 2];         // double-buffered partial max
__device__ float g_psum[2][NB * 96 * 2];         // double-buffered partial sum

// ---------------- PDL helpers ----------------
__device__ __forceinline__ void pdl_trigger() {
#if defined(__CUDA_ARCH__) && __CUDA_ARCH__ >= 900
    cudaTriggerProgrammaticLaunchCompletion();
#endif
}
__device__ __forceinline__ void pdl_wait() {
#if defined(__CUDA_ARCH__) && __CUDA_ARCH__ >= 900
    cudaGridDependencySynchronize();
#endif
}

// ---------------- f32x2 packed-math helpers ----------------
typedef unsigned long long ull;
__device__ __forceinline__ ull pk2(float a, float b) {
    ull r; asm("mov.b64 %0, {%1, %2};" : "=l"(r) : "f"(a), "f"(b)); return r;
}
__device__ __forceinline__ ull dup2(float a) { return pk2(a, a); }
__device__ __forceinline__ void fma2(ull& d, ull a, ull b) {
    asm("fma.rn.f32x2 %0, %1, %2, %0;" : "+l"(d) : "l"(a), "l"(b));
}
__device__ __forceinline__ ull mul2(ull a, ull b) {
    ull r; asm("mul.rn.f32x2 %0, %1, %2;" : "=l"(r) : "l"(a), "l"(b)); return r;
}
__device__ __forceinline__ ull add2(ull a, ull b) {
    ull r; asm("add.rn.f32x2 %0, %1, %2;" : "=l"(r) : "l"(a), "l"(b)); return r;
}
__device__ __forceinline__ float2 up2(ull v) {
    float2 r; asm("mov.b64 {%0, %1}, %2;" : "=f"(r.x), "=f"(r.y) : "l"(v)); return r;
}
union F4U { float4 f; ull u[2]; };

__device__ __forceinline__ float tanh_fast(float x) {
    float r; asm("tanh.approx.f32 %0, %1;" : "=f"(r) : "f"(x)); return r;
}
__device__ __forceinline__ unsigned to_tf32(float x) {
    unsigned r; asm("cvt.rna.tf32.f32 %0, %1;" : "=r"(r) : "f"(x)); return r;
}
__device__ __forceinline__ void split_tf32(float x, unsigned& hi, unsigned& lo) {
    hi = to_tf32(x);
    lo = to_tf32(x - __uint_as_float(hi));
}
__device__ __forceinline__ void mma_tf32(
    float& d0, float& d1, float& d2, float& d3,
    unsigned a0, unsigned a1, unsigned a2, unsigned a3,
    unsigned b0, unsigned b1)
{
    asm("mma.sync.aligned.m16n8k8.row.col.f32.tf32.tf32.f32 "
        "{%0,%1,%2,%3}, {%4,%5,%6,%7}, {%8,%9}, {%0,%1,%2,%3};"
        : "+f"(d0), "+f"(d1), "+f"(d2), "+f"(d3)
        : "r"(a0), "r"(a1), "r"(a2), "r"(a3), "r"(b0), "r"(b1));
}

// ---------------- 2-vertex shared helpers ----------------
template<bool BN>
__device__ __forceinline__ void stream_epi_fw2(
    ull acc0[16], ull acc1[16],
    const float* __restrict__ sscale, const float* __restrict__ sshift,
    const float (*__restrict__ sWfw)[NC], const float* __restrict__ sbfw,
    float* __restrict__ ob, ull facc0[12], ull facc1[12])
{
    #pragma unroll
    for (int j = 0; j < 12; j++) {
        float2 bb = *(const float2*)&sbfw[2 * j];
        ull p = pk2(bb.x, bb.y);
        facc0[j] = p; facc1[j] = p;
    }
    #pragma unroll
    for (int j2 = 0; j2 < 16; j2++) {
        float2 z0 = up2(acc0[j2]), z1 = up2(acc1[j2]);
        float a00 = tanh_fast(z0.x), a01 = tanh_fast(z0.y);
        float a10 = tanh_fast(z1.x), a11 = tanh_fast(z1.y);
        if (BN) {
            float sc0 = sscale[2 * j2], sh0 = sshift[2 * j2];
            float sc1 = sscale[2 * j2 + 1], sh1 = sshift[2 * j2 + 1];
            a00 = a00 * sc0 + sh0; a10 = a10 * sc0 + sh0;
            a01 = a01 * sc1 + sh1; a11 = a11 * sc1 + sh1;
        }
        *(float2*)(ob + (size_t)(2 * j2) * NV)     = make_float2(a00, a10);
        *(float2*)(ob + (size_t)(2 * j2 + 1) * NV) = make_float2(a01, a11);
        ull d00 = dup2(a00), d01 = dup2(a01), d10 = dup2(a10), d11 = dup2(a11);
        #pragma unroll
        for (int g6 = 0; g6 < 6; g6++) {
            F4U w0; w0.f = *(const float4*)&sWfw[2 * j2][g6 * 4];
            F4U w1; w1.f = *(const float4*)&sWfw[2 * j2 + 1][g6 * 4];
            fma2(facc0[2 * g6],     d00, w0.u[0]); fma2(facc0[2 * g6 + 1], d00, w0.u[1]);
            fma2(facc0[2 * g6],     d01, w1.u[0]); fma2(facc0[2 * g6 + 1], d01, w1.u[1]);
            fma2(facc1[2 * g6],     d10, w0.u[0]); fma2(facc1[2 * g6 + 1], d10, w0.u[1]);
            fma2(facc1[2 * g6],     d11, w1.u[0]); fma2(facc1[2 * g6 + 1], d11, w1.u[1]);
        }
    }
}

__device__ __forceinline__ void fw_finish2(
    ull facc0[12], ull facc1[12], float (*__restrict__ sbuf)[HALF_V], int tid,
    float* __restrict__ gw)
{
    #pragma unroll
    for (int j = 0; j < 10; j++) {
        float2 f0 = up2(facc0[j]), f1 = up2(facc1[j]);
        *(float2*)&sbuf[2 * j][2 * tid]     = make_float2(f0.x, f1.x);
        *(float2*)&sbuf[2 * j + 1][2 * tid] = make_float2(f0.y, f1.y);
    }
    float2 p0 = up2(facc0[10]), q0 = up2(facc0[11]);
    float2 p1 = up2(facc1[10]), q1 = up2(facc1[11]);
    float w0a = __expf(-fabsf(p0.x)), w0b = __expf(-fabsf(p0.y));
    float w0c = __expf(-fabsf(q0.x)), w0d = __expf(-fabsf(q0.y));
    float w1a = __expf(-fabsf(p1.x)), w1b = __expf(-fabsf(p1.y));
    float w1c = __expf(-fabsf(q1.x)), w1d = __expf(-fabsf(q1.y));
    *(float2*)&sbuf[20][2 * tid] = make_float2(w0a, w1a);
    *(float2*)&sbuf[21][2 * tid] = make_float2(w0b, w1b);
    *(float2*)&sbuf[22][2 * tid] = make_float2(w0c, w1c);
    *(float2*)&sbuf[23][2 * tid] = make_float2(w0d, w1d);
    *(float2*)(gw)                    = make_float2(w0a, w1a);
    *(float2*)(gw + (size_t)NV)       = make_float2(w0b, w1b);
    *(float2*)(gw + (size_t)2 * NV)   = make_float2(w0c, w1c);
    *(float2*)(gw + (size_t)3 * NV)   = make_float2(w0d, w1d);
}

// 96 max/sum tasks over 512 vertices; warp w -> aa = w>>1, c = (w&1)*12..+12
__device__ __forceinline__ void reduce96_2(
    const float (*__restrict__ sbuf)[HALF_V], int b, int half, int warp, int lane,
    int pb)
{
    const int aa = warp >> 1, cbase = (warp & 1) * 12;
    ull s2[12]; float m0[12], m1[12];
    #pragma unroll
    for (int c = 0; c < 12; c++) { s2[c] = 0ull; m0[c] = -CUDART_INF_F; m1[c] = -CUDART_INF_F; }
    #pragma unroll
    for (int i = 0; i < 8; i++) {
        const int vv = (lane + i * 32) * 2;
        ull w2 = *(const ull*)&sbuf[NP + aa][vv];
        #pragma unroll
        for (int c = 0; c < 12; c++) {
            ull f2 = *(const ull*)&sbuf[cbase + c][vv];
            ull p = mul2(w2, f2);
            s2[c] = add2(s2[c], p);
            float2 pv = up2(p);
            m0[c] = fmaxf(m0[c], pv.x);
            m1[c] = fmaxf(m1[c], pv.y);
        }
    }
    #pragma unroll
    for (int c = 0; c < 12; c++) {
        float m = fmaxf(m0[c], m1[c]);
        float2 sv = up2(s2[c]);
        float s = sv.x + sv.y;
        #pragma unroll
        for (int o = 16; o > 0; o >>= 1) {
            m = fmaxf(m, __shfl_xor_sync(~0u, m, o));
            s += __shfl_xor_sync(~0u, s, o);
        }
        if (lane == 0) {
            const int t = aa * 24 + cbase + c;
            g_pmax[pb][(b * 96 + t) * 2 + half] = m;
            g_psum[pb][(b * 96 + t) * 2 + half] = s;
        }
    }
}

// =====================================================================
// kB_fw: event mean (computed in-CTA) + h0 = tanh(bn0(x)@W_in + cbias)
// -> slot 0, fused fw(block 0). grid 256 (b=blk>>1, half=blk&1), 256 thr
// =====================================================================
struct __align__(16) SmemB {
    float sbuf[NC][HALF_V];
    float sW[NFEAT][NF];
    float sWfw[NF][NC];
    float scb[NF];
    float ss0[20], st0[20];
    float sbfw[NC];
    float sp[8][12];
    float smean[12];
};

__global__ __launch_bounds__(256, 2)
void kB_fw(const float* __restrict__ x,
           const float* __restrict__ bn0_gamma, const float* __restrict__ bn0_var,
           const float* __restrict__ bn0_beta,  const float* __restrict__ bn0_mean,
           const float* __restrict__ W_in,      const float* __restrict__ b_in,
           const float* __restrict__ W_flr, const float* __restrict__ b_flr,
           const float* __restrict__ W_s,   const float* __restrict__ b_s)
{
    extern __shared__ char smraw[];
    SmemB& S = *reinterpret_cast<SmemB*>(smraw);
    const int tid = threadIdx.x;
    const int b = blockIdx.x >> 1, half = blockIdx.x & 1;
    const int v0 = half * HALF_V + tid * 2;
    const int warp = tid >> 5, lane = tid & 31;

    pdl_trigger();   // allow F(0) to prelaunch and stage its weights

    // per-event vertex mean (each CTA computes it for its event; cheap)
    {
        float s[NFEAT];
        #pragma unroll
        for (int c = 0; c < NFEAT; c++) s[c] = 0.0f;
        #pragma unroll
        for (int i = 0; i < 4; i++) {
            const float* xv = x + ((size_t)b * NV + tid + i * 256) * NFEAT;
            #pragma unroll
            for (int c = 0; c < NFEAT; c++) s[c] += xv[c];
        }
        #pragma unroll
        for (int o = 16; o > 0; o >>= 1)
            #pragma unroll
            for (int c = 0; c < NFEAT; c++) s[c] += __shfl_xor_sync(~0u, s[c], o);
        if (lane == 0)
            #pragma unroll
            for (int c = 0; c < NFEAT; c++) S.sp[warp][c] = s[c];
    }

    const float* xv0 = x + ((size_t)b * NV + v0) * NFEAT;
    float xr0[NFEAT], xr1[NFEAT];
    #pragma unroll
    for (int c = 0; c < NFEAT; c++) { xr0[c] = xv0[c]; xr1[c] = xv0[NFEAT + c]; }

    for (int i = tid; i < NFEAT * NF; i += 256) S.sW[i / NF][i % NF] = W_in[i];
    for (int i = tid; i < NF * NC; i += 256) {
        int k = i / NC, c = i % NC;
        S.sWfw[k][c] = (c < NP) ? W_flr[(size_t)k * NP + c] : W_s[(size_t)k * NA + (c - NP)];
    }
    if (tid >= 32 && tid < 52) {
        int c = tid - 32;
        float sc = bn0_gamma[c] * rsqrtf(bn0_var[c] + 1e-3f);
        S.ss0[c] = sc;
        S.st0[c] = bn0_beta[c] - bn0_mean[c] * sc;
    }
    if (tid >= 64 && tid < 64 + NC)
        S.sbfw[tid - 64] = (tid - 64 < NP) ? b_flr[tid - 64] : b_s[tid - 64 - NP];
    __syncthreads();
    if (tid < NFEAT) {
        float a = 0.0f;
        #pragma unroll
        for (int w = 0; w < 8; w++) a += S.sp[w][tid];
        S.smean[tid] = a * (1.0f / 1024.0f);
    }
    __syncthreads();
    if (tid < NF) {   // fold mean-half of gex + b_in into per-event constant bias
        float a = b_in[tid];
        #pragma unroll
        for (int c = 10; c < 20; c++) {
            float g = S.smean[c - 10] * S.ss0[c] + S.st0[c];
            a += g * W_in[c * NF + tid];
        }
        S.scb[tid] = a;
    }
    __syncthreads();

    ull acc0[16], acc1[16];
    #pragma unroll
    for (int j = 0; j < 16; j++) {
        float2 bb = *(const float2*)&S.scb[2 * j];
        ull p = pk2(bb.x, bb.y);
        acc0[j] = p; acc1[j] = p;
    }
    #pragma unroll
    for (int c = 0; c < NFEAT; c++) {
        float sc = S.ss0[c], sh = S.st0[c];
        ull g0 = dup2(xr0[c] * sc + sh);
        ull g1 = dup2(xr1[c] * sc + sh);
        #pragma unroll
        for (int g8 = 0; g8 < 8; g8++) {
            F4U w; w.f = *(const float4*)&S.sW[c][g8 * 4];
            fma2(acc0[g8 * 2],     g0, w.u[0]); fma2(acc0[g8 * 2 + 1], g0, w.u[1]);
            fma2(acc1[g8 * 2],     g1, w.u[0]); fma2(acc1[g8 * 2 + 1], g1, w.u[1]);
        }
    }
    float* ob = g_h + (size_t)b * 384 * NV + v0;
    ull facc0[12], facc1[12];
    stream_epi_fw2<false>(acc0, acc1, nullptr, nullptr, S.sWfw, S.sbfw, ob, facc0, facc1);
    fw_finish2(facc0, facc1, S.sbuf, tid, g_w + ((size_t)b * NA) * NV + v0);
    __syncthreads();
    reduce96_2(S.sbuf, b, half, warp, lane, 0);
}

// =====================================================================
// F: fused block: Gp(l) -> out(l) -> h_{l+1} -> fw(l+1) -> partials
// Full W_out rows 32..227 staged in the PDL-hidden prologue.
// =====================================================================
struct __align__(16) SmemF {
    float sbuf[NC][HALF_V];
    float sWo32[NF][NF];
    float sWoX[196][NF];     // W_out rows 32..227 (PDL-hidden staging)
    float sWfw[NF][NC];
    float sGp[NA][NF];
    float sam[96], sas[96];
    float sbfw[NC];
    float sbo[NF], sscale[NF], sshift[NF];
};

__global__ __launch_bounds__(256, 2)
void F_block(int l,
             const float* __restrict__ W_out,    const float* __restrict__ b_out,
             const float* __restrict__ bn_gamma, const float* __restrict__ bn_beta,
             const float* __restrict__ bn_mean,  const float* __restrict__ bn_var,
             const float* __restrict__ W_flr,    const float* __restrict__ b_flr,
             const float* __restrict__ W_s,      const float* __restrict__ b_s)
{
    extern __shared__ char smraw[];
    SmemF& S = *reinterpret_cast<SmemF*>(smraw);
    const int tid = threadIdx.x;
    const int b = blockIdx.x >> 1, half = blockIdx.x & 1;
    const int v0 = half * HALF_V + tid * 2;
    const int warp = tid >> 5, lane = tid & 31;
    const int pb = l & 1, lf = l + 1;

    pdl_trigger();   // let the next kernel prelaunch + stage its weights

    // ---- independent prologue: stage weights/biases (kernel inputs only) ----
    const float* WoG = W_out + (size_t)l * 228 * NF;
    ((float4*)&S.sWo32[0][0])[tid] = ((const float4*)WoG)[tid];   // rows 0..31
    {
        const float4* src = (const float4*)(WoG + 32 * NF);
        float4* dst = (float4*)&S.sWoX[0][0];
        for (int i = tid; i < 196 * NF / 4; i += 256) dst[i] = src[i];
    }
    for (int i = tid; i < NF * NC; i += 256) {
        int k = i / NC, c = i % NC;
        S.sWfw[k][c] = (c < NP) ? W_flr[((size_t)lf * NF + k) * NP + c]
                                : W_s[((size_t)lf * NF + k) * NA + (c - NP)];
    }
    if (tid >= 128 && tid < 160) {
        int j = tid - 128;
        S.sbo[j] = b_out[l * NF + j];
        float sc = bn_gamma[l * NF + j] * rsqrtf(bn_var[l * NF + j] + 1e-3f);
        S.sscale[j] = sc;
        S.sshift[j] = bn_beta[l * NF + j] - bn_mean[l * NF + j] * sc;
    }
    if (tid >= 160 && tid < 160 + NC)
        S.sbfw[tid - 160] = (tid - 160 < NP) ? b_flr[lf * NP + tid - 160]
                                             : b_s[lf * NA + tid - 160 - NP];

    // ---- dependent data: wait for predecessor grid ----
    pdl_wait();

    const float* hb = g_h + ((size_t)b * 384 + (size_t)l * NF) * NV + v0;
    float2 wv[NA];
    #pragma unroll
    for (int a = 0; a < NA; a++)
        wv[a] = *(const float2*)(g_w + ((size_t)b * NA + a) * NV + v0);
    if (tid < 96) {
        float2 pm = *(const float2*)&g_pmax[pb][(b * 96 + tid) * 2];
        float2 ps = *(const float2*)&g_psum[pb][(b * 96 + tid) * 2];
        S.sam[tid] = fmaxf(pm.x, pm.y);
        S.sas[tid] = (ps.x + ps.y) * (1.0f / 1024.0f);
    }
    __syncthreads();

    if (tid < 128) {   // Gp from smem-staged W_out rows (rowX = row-32)
        const int aa = warp, j = lane;
        float g = S.sWoX[192 + aa][j];                 // row 224+aa
        #pragma unroll
        for (int c = 0; c < NC; c++)
            g += S.sam[aa * NC + c] * S.sWoX[aa * 48 + c][j];
        #pragma unroll
        for (int c = 0; c < NC; c++)
            g += S.sas[aa * NC + c] * S.sWoX[aa * 48 + NC + c][j];
        S.sGp[aa][j] = g;
    }
    __syncthreads();

    ull acc0[16], acc1[16];
    #pragma unroll
    for (int j = 0; j < 16; j++) {
        float2 bb = *(const float2*)&S.sbo[2 * j];
        ull p = pk2(bb.x, bb.y);
        acc0[j] = p; acc1[j] = p;
    }
    #pragma unroll
    for (int kc = 0; kc < 4; kc++) {
        float2 h2[8];
        #pragma unroll
        for (int k = 0; k < 8; k++)
            h2[k] = *(const float2*)(hb + (size_t)(kc * 8 + k) * NV);
        #pragma unroll
        for (int k = 0; k < 8; k++) {
            ull hk0 = dup2(h2[k].x), hk1 = dup2(h2[k].y);
            #pragma unroll
            for (int g8 = 0; g8 < 8; g8++) {
                F4U w; w.f = *(const float4*)&S.sWo32[kc * 8 + k][g8 * 4];
                fma2(acc0[g8 * 2],     hk0, w.u[0]); fma2(acc0[g8 * 2 + 1], hk0, w.u[1]);
                fma2(acc1[g8 * 2],     hk1, w.u[0]); fma2(acc1[g8 * 2 + 1], hk1, w.u[1]);
            }
        }
    }
    #pragma unroll
    for (int a = 0; a < NA; a++) {
        ull wa0 = dup2(wv[a].x), wa1 = dup2(wv[a].y);
        #pragma unroll
        for (int g8 = 0; g8 < 8; g8++) {
            F4U gg; gg.f = *(const float4*)&S.sGp[a][g8 * 4];
            fma2(acc0[g8 * 2],     wa0, gg.u[0]); fma2(acc0[g8 * 2 + 1], wa0, gg.u[1]);
            fma2(acc1[g8 * 2],     wa1, gg.u[0]); fma2(acc1[g8 * 2 + 1], wa1, gg.u[1]);
        }
    }

    float* ob = g_h + ((size_t)b * 384 + (size_t)lf * NF) * NV + v0;
    ull facc0[12], facc1[12];
    stream_epi_fw2<true>(acc0, acc1, S.sscale, S.sshift, S.sWfw, S.sbfw, ob, facc0, facc1);
    fw_finish2(facc0, facc1, S.sbuf, tid, g_w + ((size_t)b * NA) * NV + v0);
    __syncthreads();
    reduce96_2(S.sbuf, b, half, warp, lane, pb ^ 1);
}

// =====================================================================
// k2_tc: final block (l=10, merged G) + output MLP via 3xTF32 mma.sync.
// grid 128 (1 CTA = 1 event), 512 threads = 16 warps.
// Phase 0 (PDL-hidden): stage B-frags + W_out[10] tiles + biases.
// Phase 1 (after wait on F(9)): G-phase -> slot 11 (2 verts/thread).
// Phase 2: MMA over slots 1..11 + second layer.
// =====================================================================
#define NKT 44              // 352 / 8
#define NNT 6               // 48 / 8
#define BPK (NNT * NKT * 32)  // 8448 frag pairs

struct __align__(16) SmemK2T {
    float bph[BPK * 2];      // packed tf32 B hi-frags  (67.6 KB)
    float bpl[BPK * 2];      // packed tf32 B lo-frags  (67.6 KB)
    float sWo32[NF][NF];     // W_out[10] rows 0..31    (4 KB)
    float sWoX[196][NF];     // W_out[10] rows 32..227  (24.5 KB)
    float sGp[NA][NF];
    float sam[96], sas[96];
    float sbo[NF], sscale[NF], sshift[NF];
    float sW1[144];
    float sb0[48];
    float sb1[4];
};

__global__ __launch_bounds__(512, 1)
void k2_tc(const float* __restrict__ W_out,  const float* __restrict__ b_out,
           const float* __restrict__ bn_gamma, const float* __restrict__ bn_beta,
           const float* __restrict__ bn_mean,  const float* __restrict__ bn_var,
           const float* __restrict__ W_o0, const float* __restrict__ b_o0,
           const float* __restrict__ W_o1, const float* __restrict__ b_o1,
           float* __restrict__ out)
{
    extern __shared__ char smraw[];
    SmemK2T& S = *reinterpret_cast<SmemK2T*>(smraw);
    const int tid = threadIdx.x;
    const int lane = tid & 31, warp = tid >> 5;   // warp 0..15
    const int gr = lane >> 2, gc = lane & 3;      // frag row/col indices
    const int b = blockIdx.x;
    const int l = 10, pb = 0;

    pdl_trigger();

    // ---- Phase 0: independent prologue (kernel inputs only) ----
    for (int i = tid; i < BPK; i += 512) {
        int ln = i & 31, rest = i >> 5;
        int kt = rest % NKT, nt = rest / NKT;
        int c = ln & 3, r = ln >> 2;
        int k0 = kt * 8, n0 = nt * 8;
        float w0 = W_o0[(k0 + c) * 48 + n0 + r];
        float w1 = W_o0[(k0 + c + 4) * 48 + n0 + r];
        unsigned h0, l0, h1, l1;
        split_tf32(w0, h0, l0);
        split_tf32(w1, h1, l1);
        *(uint2*)&S.bph[2 * i] = make_uint2(h0, h1);
        *(uint2*)&S.bpl[2 * i] = make_uint2(l0, l1);
    }
    const float* WoG = W_out + (size_t)l * 228 * NF;
    {
        const float4* src = (const float4*)WoG;
        float4* dst = (float4*)&S.sWo32[0][0];
        for (int i = tid; i < NF * NF / 4; i += 512) dst[i] = src[i];
        const float4* srcX = (const float4*)(WoG + 32 * NF);
        float4* dstX = (float4*)&S.sWoX[0][0];
        for (int i = tid; i < 196 * NF / 4; i += 512) dstX[i] = srcX[i];
    }
    if (tid < NF) {
        int j = tid;
        S.sbo[j] = b_out[l * NF + j];
        float sc = bn_gamma[l * NF + j] * rsqrtf(bn_var[l * NF + j] + 1e-3f);
        S.sscale[j] = sc;
        S.sshift[j] = bn_beta[l * NF + j] - bn_mean[l * NF + j] * sc;
    }
    if (tid >= 64 && tid < 208) S.sW1[tid - 64] = W_o1[tid - 64];
    if (tid >= 224 && tid < 272) S.sb0[tid - 224] = b_o0[tid - 224];
    if (tid >= 288 && tid < 291) S.sb1[tid - 288] = b_o1[tid - 288];
    __syncthreads();

    pdl_wait();   // F(9) complete: slot 10 h, g_w, partials pb=0

    // ---- Phase 1: G (block 10) -> slot 11 h; 2 verts/thread ----
    {
        const int v0 = tid * 2;
        const float* hb = g_h + ((size_t)b * 384 + (size_t)l * NF) * NV + v0;
        float2 wv[NA];
        #pragma unroll
        for (int a = 0; a < NA; a++)
            wv[a] = *(const float2*)(g_w + ((size_t)b * NA + a) * NV + v0);
        if (tid < 96) {
            float2 pm = *(const float2*)&g_pmax[pb][(b * 96 + tid) * 2];
            float2 ps = *(const float2*)&g_psum[pb][(b * 96 + tid) * 2];
            S.sam[tid] = fmaxf(pm.x, pm.y);
            S.sas[tid] = (ps.x + ps.y) * (1.0f / 1024.0f);
        }
        __syncthreads();
        if (tid < 128) {
            const int aa = warp, j = lane;
            float g = S.sWoX[192 + aa][j];
            #pragma unroll
            for (int c = 0; c < NC; c++)
                g += S.sam[aa * NC + c] * S.sWoX[aa * 48 + c][j];
            #pragma unroll
            for (int c = 0; c < NC; c++)
                g += S.sas[aa * NC + c] * S.sWoX[aa * 48 + NC + c][j];
            S.sGp[aa][j] = g;
        }
        __syncthreads();

        ull acc0[16], acc1[16];
        #pragma unroll
        for (int j = 0; j < 16; j++) {
            float2 bb = *(const float2*)&S.sbo[2 * j];
            ull p = pk2(bb.x, bb.y);
            acc0[j] = p; acc1[j] = p;
        }
        #pragma unroll
        for (int kc = 0; kc < 4; kc++) {
            float2 h2[8];
            #pragma unroll
            for (int k = 0; k < 8; k++)
                h2[k] = *(const float2*)(hb + (size_t)(kc * 8 + k) * NV);
            #pragma unroll
            for (int k = 0; k < 8; k++) {
                ull hk0 = dup2(h2[k].x), hk1 = dup2(h2[k].y);
                #pragma unroll
                for (int g8 = 0; g8 < 8; g8++) {
                    F4U w; w.f = *(const float4*)&S.sWo32[kc * 8 + k][g8 * 4];
                    fma2(acc0[g8 * 2],     hk0, w.u[0]); fma2(acc0[g8 * 2 + 1], hk0, w.u[1]);
                    fma2(acc1[g8 * 2],     hk1, w.u[0]); fma2(acc1[g8 * 2 + 1], hk1, w.u[1]);
                }
            }
        }
        #pragma unroll
        for (int a = 0; a < NA; a++) {
            ull wa0 = dup2(wv[a].x), wa1 = dup2(wv[a].y);
            #pragma unroll
            for (int g8 = 0; g8 < 8; g8++) {
                F4U gg; gg.f = *(const float4*)&S.sGp[a][g8 * 4];
                fma2(acc0[g8 * 2],     wa0, gg.u[0]); fma2(acc0[g8 * 2 + 1], wa0, gg.u[1]);
                fma2(acc1[g8 * 2],     wa1, gg.u[0]); fma2(acc1[g8 * 2 + 1], wa1, gg.u[1]);
            }
        }
        float* ob = g_h + ((size_t)b * 384 + (size_t)11 * NF) * NV + v0;
        #pragma unroll
        for (int j2 = 0; j2 < 16; j2++) {
            float2 z0 = up2(acc0[j2]), z1 = up2(acc1[j2]);
            float sc0 = S.sscale[2 * j2], sh0 = S.sshift[2 * j2];
            float sc1 = S.sscale[2 * j2 + 1], sh1 = S.sshift[2 * j2 + 1];
            *(float2*)(ob + (size_t)(2 * j2) * NV) =
                make_float2(tanh_fast(z0.x) * sc0 + sh0, tanh_fast(z1.x) * sc0 + sh0);
            *(float2*)(ob + (size_t)(2 * j2 + 1) * NV) =
                make_float2(tanh_fast(z0.y) * sc1 + sh1, tanh_fast(z1.y) * sc1 + sh1);
        }
    }
    __syncthreads();   // slot-11 writes by this CTA visible to all its threads

    // ---- Phase 2: MMA over slots 1..11 (incl. fresh slot 11) ----
    const float* fb = g_h + ((size_t)b * 384 + NF) * NV;

    #pragma unroll 1
    for (int vhalf = 0; vhalf < 2; vhalf++) {
        const int vb = vhalf * 512 + warp * 32;   // 32 vertices per warp

        float d[2][NNT][4];
        #pragma unroll
        for (int t = 0; t < 2; t++)
            #pragma unroll
            for (int nt = 0; nt < NNT; nt++)
                #pragma unroll
                for (int q = 0; q < 4; q++) d[t][nt][q] = 0.0f;

        #pragma unroll 2
        for (int kt = 0; kt < NKT; kt++) {
            const int k0 = kt * 8;
            unsigned ah[2][4], al[2][4];
            #pragma unroll
            for (int t = 0; t < 2; t++) {
                const float* base = fb + (size_t)(k0 + gc) * NV + vb + t * 16 + gr;
                float f0 = base[0];
                float f1 = base[8];
                float f2 = base[(size_t)4 * NV];
                float f3 = base[(size_t)4 * NV + 8];
                split_tf32(f0, ah[t][0], al[t][0]);
                split_tf32(f1, ah[t][1], al[t][1]);
                split_tf32(f2, ah[t][2], al[t][2]);
                split_tf32(f3, ah[t][3], al[t][3]);
            }
            #pragma unroll
            for (int nt = 0; nt < NNT; nt++) {
                const int fi = 2 * ((nt * NKT + kt) * 32 + lane);
                uint2 bh = *(const uint2*)&S.bph[fi];
                uint2 bl = *(const uint2*)&S.bpl[fi];
                #pragma unroll
                for (int t = 0; t < 2; t++) {
                    mma_tf32(d[t][nt][0], d[t][nt][1], d[t][nt][2], d[t][nt][3],
                             ah[t][0], ah[t][1], ah[t][2], ah[t][3], bh.x, bh.y);
                    mma_tf32(d[t][nt][0], d[t][nt][1], d[t][nt][2], d[t][nt][3],
                             al[t][0], al[t][1], al[t][2], al[t][3], bh.x, bh.y);
                    mma_tf32(d[t][nt][0], d[t][nt][1], d[t][nt][2], d[t][nt][3],
                             ah[t][0], ah[t][1], ah[t][2], ah[t][3], bl.x, bl.y);
                }
            }
        }

        // epilogue: bias + relu + second layer (48 -> 3) + quad reduce
        #pragma unroll
        for (int t = 0; t < 2; t++) {
            float o0a = 0.0f, o1a = 0.0f, o2a = 0.0f;   // row gr
            float o0b = 0.0f, o1b = 0.0f, o2b = 0.0f;   // row gr+8
            #pragma unroll
            for (int nt = 0; nt < NNT; nt++) {
                const int n = nt * 8 + 2 * gc;
                float2 bb = *(const float2*)&S.sb0[n];
                float h0 = fmaxf(d[t][nt][0] + bb.x, 0.0f);
                float h1 = fmaxf(d[t][nt][1] + bb.y, 0.0f);
                float h2 = fmaxf(d[t][nt][2] + bb.x, 0.0f);
                float h3 = fmaxf(d[t][nt][3] + bb.y, 0.0f);
                const float* w1a = &S.sW1[n * 3];
                o0a += h0 * w1a[0] + h1 * w1a[3];
                o1a += h0 * w1a[1] + h1 * w1a[4];
                o2a += h0 * w1a[2] + h1 * w1a[5];
                o0b += h2 * w1a[0] + h3 * w1a[3];
                o1b += h2 * w1a[1] + h3 * w1a[4];
                o2b += h2 * w1a[2] + h3 * w1a[5];
            }
            #pragma unroll
            for (int o = 1; o <= 2; o <<= 1) {
                o0a += __shfl_xor_sync(~0u, o0a, o); o1a += __shfl_xor_sync(~0u, o1a, o);
                o2a += __shfl_xor_sync(~0u, o2a, o); o0b += __shfl_xor_sync(~0u, o0b, o);
                o1b += __shfl_xor_sync(~0u, o1b, o); o2b += __shfl_xor_sync(~0u, o2b, o);
            }
            if (gc == 0) {
                const int va = b * NV + vb + t * 16 + gr;
                float* opa = out + (size_t)va * 3;
                opa[0] = fmaxf(o0a + S.sb1[0], 0.0f);
                opa[1] = fmaxf(o1a + S.sb1[1], 0.0f);
                opa[2] = fmaxf(o2a + S.sb1[2], 0.0f);
                float* opb = out + (size_t)(va + 8) * 3;
                opb[0] = fmaxf(o0b + S.sb1[0], 0.0f);
                opb[1] = fmaxf(o1b + S.sb1[1], 0.0f);
                opb[2] = fmaxf(o2b + S.sb1[2], 0.0f);
            }
        }
    }
}

// =====================================================================
// host-side PDL launch helper
// =====================================================================
template <typename... Args>
static void launch_pdl(void (*kern)(Args...), dim3 grid, dim3 block,
                       size_t smem, Args... args)
{
    cudaLaunchConfig_t cfg = {};
    cfg.gridDim = grid;
    cfg.blockDim = block;
    cfg.dynamicSmemBytes = smem;
    cfg.stream = 0;
    cudaLaunchAttribute attr[1];
    attr[0].id = cudaLaunchAttributeProgrammaticStreamSerialization;
    attr[0].val.programmaticStreamSerializationAllowed = 1;
    cfg.attrs = attr;
    cfg.numAttrs = 1;
    cudaLaunchKernelEx(&cfg, kern, args...);
}

extern "C" void kernel_launch(void* const* d_in, const int* in_sizes, int n_in,
                              void* d_out, int out_size)
{
    const float* x         = (const float*)d_in[0];
    const float* bn0_gamma = (const float*)d_in[1];
    const float* bn0_beta  = (const float*)d_in[2];
    const float* bn0_mean  = (const float*)d_in[3];
    const float* bn0_var   = (const float*)d_in[4];
    const float* W_in      = (const float*)d_in[5];
    const float* b_in      = (const float*)d_in[6];
    const float* W_flr     = (const float*)d_in[7];
    const float* b_flr     = (const float*)d_in[8];
    const float* W_s       = (const float*)d_in[9];
    const float* b_s       = (const float*)d_in[10];
    const float* W_out     = (const float*)d_in[11];
    const float* b_out     = (const float*)d_in[12];
    const float* bn_gamma  = (const float*)d_in[13];
    const float* bn_beta   = (const float*)d_in[14];
    const float* bn_mean   = (const float*)d_in[15];
    const float* bn_var    = (const float*)d_in[16];
    const float* W_o0      = (const float*)d_in[17];
    const float* b_o0      = (const float*)d_in[18];
    const float* W_o1      = (const float*)d_in[19];
    const float* b_o1      = (const float*)d_in[20];

    cudaFuncSetAttribute(kB_fw, cudaFuncAttributeMaxDynamicSharedMemorySize,
                         (int)sizeof(SmemB));
    cudaFuncSetAttribute(F_block, cudaFuncAttributeMaxDynamicSharedMemorySize,
                         (int)sizeof(SmemF));
    cudaFuncSetAttribute(k2_tc, cudaFuncAttributeMaxDynamicSharedMemorySize,
                         (int)sizeof(SmemK2T));

    kB_fw<<<NB * 2, 256, sizeof(SmemB)>>>(x, bn0_gamma, bn0_var, bn0_beta, bn0_mean,
                                          W_in, b_in, W_flr, b_flr, W_s, b_s);

    for (int l = 0; l < NBK - 1; l++) {
        launch_pdl(F_block, dim3(NB * 2), dim3(256), sizeof(SmemF),
                   l, W_out, b_out, bn_gamma, bn_beta, bn_mean, bn_var,
                   W_flr, b_flr, W_s, b_s);
    }

    launch_pdl(k2_tc, dim3(NB), dim3(512), sizeof(SmemK2T),
               W_out, b_out, bn_gamma, bn_beta, bn_mean, bn_var,
               W_o0, b_o0, W_o1, b_o1, (float*)d_out);
}